// round 5
// baseline (speedup 1.0000x reference)
#include <cuda_runtime.h>
#include <cuda_bf16.h>
#include <math.h>
#include <stdint.h>

// Problem constants
#define Bz 8
#define Nn 1024
#define Dd 256
#define Hh 8
#define HC 4
#define DH 64
#define HD 2048                 // Hh*Dd
#define ND (Nn*Dd)              // 262144
#define NNt ((size_t)Nn*Nn)     // 1048576

// ---------------- scratch (device globals) ----------------
__device__ float g_posq[Bz*Dd];
__device__ float g_w[Bz*Dd];
__device__ float g_sel[Bz*Nn];
__device__ float g_fa[Bz*ND];
__device__ uint8_t g_connect[(size_t)Bz*Nn*Nn];            // 8 MB (u8)
__device__ float g_Wh[(size_t)Bz*Hh*ND];
__device__ uint32_t g_WhT[(size_t)Bz*Hh*ND];               // P2 packed
__device__ float g_s1[Bz*Hh*Nn];
__device__ float g_s2[Bz*Hh*Nn];
__device__ float g_logits[(size_t)Bz*HC*Nn*Nn];            // CA logits fp32 (128 MB)
__device__ __nv_bfloat16 g_attn_bf[(size_t)Bz*Hh*Nn*Nn];   // GAT attn / CA attn (bf16)
__device__ __nv_bfloat16 g_attno_bf[(size_t)Bz*Nn*Nn];
__device__ float g_cat[(size_t)Bz*Nn*HD];
__device__ float g_Who[Bz*ND];
__device__ uint32_t g_WhoT[Bz*ND];                         // P2
__device__ float g_so1[Bz*Nn];
__device__ float g_so2[Bz*Nn];
__device__ float g_gout[Bz*ND];
__device__ float g_qx[Bz*ND];
__device__ float g_kv[Bz*ND];
__device__ float g_q[Bz*ND];
__device__ float g_k[Bz*ND];
__device__ float g_v[Bz*ND];
__device__ uint32_t g_vT[Bz*ND];                           // P2
__device__ float g_o[Bz*ND];
// transposed weights (fp32)
__device__ float g_adjWT[Dd*Dd];
__device__ float g_gatWT[Hh*Dd*Dd];
__device__ float g_WoT[HD*Dd];
__device__ float g_caWqT[Dd*Dd];
__device__ float g_caWkT[Dd*Dd];
__device__ float g_caWvT[Dd*Dd];
__device__ float g_caWpT[Dd*Dd];

// ---------------- low-level helpers ----------------
__device__ __forceinline__ uint32_t smem_u32(const void* p) {
    uint32_t a;
    asm("{ .reg .u64 t; cvta.to.shared.u64 t, %1; cvt.u32.u64 %0, t; }" : "=r"(a) : "l"(p));
    return a;
}
__device__ __forceinline__ void ldsm4(uint32_t* r, uint32_t addr) {
    asm volatile("ldmatrix.sync.aligned.m8n8.x4.shared.b16 {%0,%1,%2,%3}, [%4];"
        : "=r"(r[0]), "=r"(r[1]), "=r"(r[2]), "=r"(r[3]) : "r"(addr));
}
__device__ __forceinline__ void mma16816(float* c, const uint32_t* a, const uint32_t* b) {
    asm volatile("mma.sync.aligned.m16n8k16.row.col.f32.bf16.bf16.f32 "
        "{%0,%1,%2,%3}, {%4,%5,%6,%7}, {%8,%9}, {%0,%1,%2,%3};"
        : "+f"(c[0]), "+f"(c[1]), "+f"(c[2]), "+f"(c[3])
        : "r"(a[0]), "r"(a[1]), "r"(a[2]), "r"(a[3]), "r"(b[0]), "r"(b[1]));
}
__device__ __forceinline__ uint32_t packbf(float v0, float v1) {
    uint32_t r;
    asm("cvt.rn.bf16x2.f32 %0, %1, %2;" : "=r"(r) : "f"(v1), "f"(v0));
    return r;
}
__device__ __forceinline__ void split4(float4 v, uint2& h, uint2& l) {
    float h0 = __bfloat162float(__float2bfloat16(v.x));
    float h1 = __bfloat162float(__float2bfloat16(v.y));
    float h2 = __bfloat162float(__float2bfloat16(v.z));
    float h3 = __bfloat162float(__float2bfloat16(v.w));
    h.x = packbf(h0, h1); h.y = packbf(h2, h3);
    l.x = packbf(v.x - h0, v.y - h1);
    l.y = packbf(v.z - h2, v.w - h3);
}
// pack value as (hi bf16 | lo bf16<<16)
__device__ __forceinline__ uint32_t packP2(float v) {
    __nv_bfloat16 h = __float2bfloat16(v);
    float hf = __bfloat162float(h);
    __nv_bfloat16 l = __float2bfloat16(v - hf);
    return (uint32_t)__bfloat16_as_ushort(h) | ((uint32_t)__bfloat16_as_ushort(l) << 16);
}

// ---------------- merged transpose kernel (all 7 weights, fp32) ----------------
__device__ __forceinline__ void tile_transpose(const float* s, float* d, int R, int C,
                                               int bx, int by, int tx, int ty, float (*t)[33])
{
    #pragma unroll
    for (int i = 0; i < 32; i += 8)
        t[ty + i][tx] = s[(size_t)(by + ty + i) * C + bx + tx];
    __syncthreads();
    #pragma unroll
    for (int i = 0; i < 32; i += 8)
        d[(size_t)(bx + ty + i) * R + by + tx] = t[tx][ty + i];
}
__global__ void k_transpose_all(const float* adjW, float* adjWT,
                                const float* caWq, float* caWqT,
                                const float* caWk, float* caWkT,
                                const float* caWv, float* caWvT,
                                const float* caWp, float* caWpT,
                                const float* gatW, float* gatWT,
                                const float* gatWo, float* WoT)
{
    __shared__ float t[32][33];
    int id = blockIdx.x;
    int tx = threadIdx.x, ty = threadIdx.y;
    if (id < 320) {
        const float* srcs[5] = {adjW, caWq, caWk, caWv, caWp};
        float* dsts[5] = {adjWT, caWqT, caWkT, caWvT, caWpT};
        int m = id >> 6, l = id & 63;
        tile_transpose(srcs[m], dsts[m], Dd, Dd, (l & 7) * 32, (l >> 3) * 32, tx, ty, t);
    } else if (id < 832) {
        int l = id - 320;
        int z = l >> 6; l &= 63;
        tile_transpose(gatW + (size_t)z * Dd * Dd, gatWT + (size_t)z * Dd * Dd,
                       Dd, Dd, (l & 7) * 32, (l >> 3) * 32, tx, ty, t);
    } else {
        int l = id - 832;   // gatWo: [HD, Dd] -> [Dd, HD]
        tile_transpose(gatWo, WoT, HD, Dd, (l & 7) * 32, (l >> 3) * 32, tx, ty, t);
    }
}

// ---------------- bf16 mma.sync NT GEMM ----------------
// C[M,N] = A[M,K] @ B[N,K]^T. KTILE=32, double-buffered, 8 warps, warp tile 64x32.
// AMODE: AF32 (fp32, split hi/lo, 3 products) | ABF16 (bf16 probs, hi only, 2 products)
// BMODE: BF32 (fp32, split in loader) | BP2 (packed hi/lo uint32, prmt unpack)
enum { EPI_NONE = 0, EPI_ELU = 1, EPI_CONNECT = 2, EPI_RESID = 3 };
enum { AF32 = 0, ABF16 = 1 };
enum { BF32 = 0, BP2 = 1 };
#define ROWB 80

template <int BM, int BN, int WM, int WN, int EPI, int AMODE, int BMODE, bool DUAL>
__global__ void __launch_bounds__(256, 2)
mma_gemm(const void* __restrict__ Av, const void* __restrict__ Bv, void* __restrict__ Cv,
         int K, int lda, int ldb, int ldc, int zInner,
         long sAb, long sAi, long sBb, long sBi, long sCb, long sCi,
         const float* __restrict__ e1, long sE1b, const float* __restrict__ e2,
         uint32_t* __restrict__ Ct, long sCtb, long sCti, int ldct)
{
    constexpr int ABYTES = BM * ROWB;
    constexpr int BBYTES = BN * ROWB;
    constexpr int APASS = BM / 32;
    constexpr int BPASS = BN / 32;
    constexpr int NAPL = (AMODE == ABF16) ? 1 : 2;   // A planes per stage

    extern __shared__ char smem[];
    const uint32_t sb = smem_u32(smem);

    const int tid = threadIdx.x;
    const int wid = tid >> 5;
    const int lane = tid & 31;

    const int z = blockIdx.z;
    const int zb = z / zInner, zi = z % zInner;
    const size_t aoff = (size_t)zb * sAb + (size_t)zi * sAi;
    const size_t boff = (size_t)zb * sBb + (size_t)zi * sBi;
    const float* Apf = (AMODE == AF32) ? ((const float*)Av + aoff) : nullptr;
    const __nv_bfloat16* Apb = (AMODE == ABF16) ? ((const __nv_bfloat16*)Av + aoff) : nullptr;
    const float* Bpf = (BMODE == BF32) ? ((const float*)Bv + boff) : nullptr;
    const uint32_t* Bpp = (BMODE == BP2) ? ((const uint32_t*)Bv + boff) : nullptr;
    float* Cp = (float*)Cv + (size_t)zb * sCb + (size_t)zi * sCi;
    uint8_t* Cp8 = (uint8_t*)Cv + (size_t)zb * sCb + (size_t)zi * sCi;
    const float* e1p = e1 ? (e1 + (size_t)zb * sE1b) : nullptr;

    const int m0 = blockIdx.y * BM;
    const int n0 = blockIdx.x * BN;

    const int lq = tid & 7;
    const int lr = tid >> 3;

    const int wid_m = wid % WM;
    const int wid_n = wid / WM;
    const int g = lane >> 3, rl = lane & 7;
    const int aRowBase = wid_m * 64 + (g & 1) * 8 + rl;
    const int aKsel = (g >> 1) * 8;
    const int bRowBase = wid_n * 32 + (g >> 1) * 8 + rl;
    const int bKsel = (g & 1) * 8;

    float acc[4][4][4] = {};
    float4 paf[APASS]; uint2 pab[APASS];
    float4 pbf[BPASS]; uint4 pbp[BPASS];

    const int nkt = K >> 5;
    const uint32_t bbase = 2 * NAPL * ABYTES;

    auto loadA = [&](int kk) {
        #pragma unroll
        for (int i = 0; i < APASS; i++) {
            if (AMODE == AF32)
                paf[i] = *reinterpret_cast<const float4*>(Apf + (size_t)(m0 + lr + 32 * i) * lda + kk + lq * 4);
            else
                pab[i] = *reinterpret_cast<const uint2*>(Apb + (size_t)(m0 + lr + 32 * i) * lda + kk + lq * 4);
        }
    };
    auto loadB = [&](int kk) {
        #pragma unroll
        for (int i = 0; i < BPASS; i++) {
            if (BMODE == BF32)
                pbf[i] = *reinterpret_cast<const float4*>(Bpf + (size_t)(n0 + lr + 32 * i) * ldb + kk + lq * 4);
            else
                pbp[i] = *reinterpret_cast<const uint4*>(Bpp + (size_t)(n0 + lr + 32 * i) * ldb + kk + lq * 4);
        }
    };
    auto storeA = [&](int stage) {
        #pragma unroll
        for (int i = 0; i < APASS; i++) {
            int off = stage * NAPL * ABYTES + (lr + 32 * i) * ROWB + lq * 8;
            if (AMODE == AF32) {
                uint2 h, l; split4(paf[i], h, l);
                *reinterpret_cast<uint2*>(smem + off) = h;
                *reinterpret_cast<uint2*>(smem + ABYTES + off) = l;
            } else {
                *reinterpret_cast<uint2*>(smem + off) = pab[i];
            }
        }
    };
    auto storeB = [&](int stage) {
        #pragma unroll
        for (int i = 0; i < BPASS; i++) {
            int off = bbase + stage * 2 * BBYTES + (lr + 32 * i) * ROWB + lq * 8;
            uint2 h, l;
            if (BMODE == BF32) {
                split4(pbf[i], h, l);
            } else {
                h.x = __byte_perm(pbp[i].x, pbp[i].y, 0x5410);
                h.y = __byte_perm(pbp[i].z, pbp[i].w, 0x5410);
                l.x = __byte_perm(pbp[i].x, pbp[i].y, 0x7632);
                l.y = __byte_perm(pbp[i].z, pbp[i].w, 0x7632);
            }
            *reinterpret_cast<uint2*>(smem + off) = h;
            *reinterpret_cast<uint2*>(smem + BBYTES + off) = l;
        }
    };

    // prologue
    loadA(0); loadB(0);
    storeA(0); storeB(0);
    __syncthreads();

    for (int kt = 0; kt < nkt; kt++) {
        const int stage = kt & 1;
        const bool more = (kt + 1 < nkt);
        if (more) { loadA((kt + 1) << 5); loadB((kt + 1) << 5); }

        const uint32_t sAhi = sb + stage * NAPL * ABYTES;
        const uint32_t sAlo = sAhi + ABYTES;
        const uint32_t sBhi = sb + bbase + stage * 2 * BBYTES;
        const uint32_t sBlo = sBhi + BBYTES;

        #pragma unroll
        for (int j = 0; j < 2; j++) {
            const int kb = j * 16;
            uint32_t a[4][4], bh[4][2], bl[4][2];
            #pragma unroll
            for (int im = 0; im < 4; im++)
                ldsm4(a[im], sAhi + (uint32_t)((aRowBase + im * 16) * ROWB + (kb + aKsel) * 2));
            #pragma unroll
            for (int i2 = 0; i2 < 2; i2++) {
                uint32_t t[4];
                ldsm4(t, sBhi + (uint32_t)((bRowBase + i2 * 16) * ROWB + (kb + bKsel) * 2));
                bh[2 * i2][0] = t[0]; bh[2 * i2][1] = t[1];
                bh[2 * i2 + 1][0] = t[2]; bh[2 * i2 + 1][1] = t[3];
            }
            #pragma unroll
            for (int im = 0; im < 4; im++)
                #pragma unroll
                for (int in = 0; in < 4; in++)
                    mma16816(acc[im][in], a[im], bh[in]);           // Ah*Bh
            #pragma unroll
            for (int i2 = 0; i2 < 2; i2++) {
                uint32_t t[4];
                ldsm4(t, sBlo + (uint32_t)((bRowBase + i2 * 16) * ROWB + (kb + bKsel) * 2));
                bl[2 * i2][0] = t[0]; bl[2 * i2][1] = t[1];
                bl[2 * i2 + 1][0] = t[2]; bl[2 * i2 + 1][1] = t[3];
            }
            #pragma unroll
            for (int im = 0; im < 4; im++)
                #pragma unroll
                for (int in = 0; in < 4; in++)
                    mma16816(acc[im][in], a[im], bl[in]);           // Ah*Bl
            if (AMODE == AF32) {
                #pragma unroll
                for (int im = 0; im < 4; im++)
                    ldsm4(a[im], sAlo + (uint32_t)((aRowBase + im * 16) * ROWB + (kb + aKsel) * 2));
                #pragma unroll
                for (int im = 0; im < 4; im++)
                    #pragma unroll
                    for (int in = 0; in < 4; in++)
                        mma16816(acc[im][in], a[im], bh[in]);       // Al*Bh
            }
        }

        if (more) { storeA(stage ^ 1); storeB(stage ^ 1); }
        __syncthreads();
    }

    // epilogue
    const int mw = m0 + wid_m * 64;
    const int nw = n0 + wid_n * 32;
    #pragma unroll
    for (int im = 0; im < 4; im++) {
        const int row = mw + im * 16 + (lane >> 2);
        const float sr0 = (EPI == EPI_CONNECT) ? e1p[row] : 0.f;
        const float sr1 = (EPI == EPI_CONNECT) ? e1p[row + 8] : 0.f;
        #pragma unroll
        for (int in = 0; in < 4; in++) {
            const int col = nw + in * 8 + (lane & 3) * 2;
            float v00 = acc[im][in][0], v01 = acc[im][in][1];
            float v10 = acc[im][in][2], v11 = acc[im][in][3];
            if (EPI == EPI_ELU) {
                v00 = v00 > 0.f ? v00 : expm1f(v00);
                v01 = v01 > 0.f ? v01 : expm1f(v01);
                v10 = v10 > 0.f ? v10 : expm1f(v10);
                v11 = v11 > 0.f ? v11 : expm1f(v11);
            } else if (EPI == EPI_RESID) {
                const float g0 = e2[col], g1 = e2[col + 1];
                const size_t r0 = (size_t)row * ldc + col;
                const size_t r1 = (size_t)(row + 8) * ldc + col;
                v00 = e1p[r0] + g0 * v00; v01 = e1p[r0 + 1] + g1 * v01;
                v10 = e1p[r1] + g0 * v10; v11 = e1p[r1 + 1] + g1 * v11;
            }
            if (EPI == EPI_CONNECT) {
                const float sc0 = e1p[col], sc1 = e1p[col + 1];
                uchar2 c0, c1;
                c0.x = (v00 > 0.f && sr0 > 0.5f && sc0 > 0.5f) ? 1 : 0;
                c0.y = (v01 > 0.f && sr0 > 0.5f && sc1 > 0.5f) ? 1 : 0;
                c1.x = (v10 > 0.f && sr1 > 0.5f && sc0 > 0.5f) ? 1 : 0;
                c1.y = (v11 > 0.f && sr1 > 0.5f && sc1 > 0.5f) ? 1 : 0;
                *reinterpret_cast<uchar2*>(Cp8 + (size_t)row * ldc + col) = c0;
                *reinterpret_cast<uchar2*>(Cp8 + (size_t)(row + 8) * ldc + col) = c1;
            } else {
                *reinterpret_cast<float2*>(Cp + (size_t)row * ldc + col) = make_float2(v00, v01);
                *reinterpret_cast<float2*>(Cp + (size_t)(row + 8) * ldc + col) = make_float2(v10, v11);
            }
            if (DUAL) {
                uint32_t* Ctp = Ct + (size_t)zb * sCtb + (size_t)zi * sCti;
                Ctp[(size_t)col * ldct + row] = packP2(v00);
                Ctp[(size_t)(col + 1) * ldct + row] = packP2(v01);
                Ctp[(size_t)col * ldct + row + 8] = packP2(v10);
                Ctp[(size_t)(col + 1) * ldct + row + 8] = packP2(v11);
            }
        }
    }
}

// ---------------- auxiliary kernels ----------------
__global__ void k_posquery(const float* __restrict__ x, const int* __restrict__ mask,
                           float* __restrict__ pq)
{
    int b = blockIdx.x, d = threadIdx.x;
    float s = 0.f, cnt = 0.f;
    for (int n = 0; n < Nn; n++) {
        int m = mask[b * Nn + n];
        if (m == 1) { s += x[((size_t)b * Nn + n) * Dd + d]; cnt += 1.f; }
    }
    pq[b * Dd + d] = s / fmaxf(cnt, 1.f);
}

__global__ void k_simvec(const float* __restrict__ Wx, const float* __restrict__ Wq,
                         const float* __restrict__ pq, float* __restrict__ w)
{
    __shared__ float spq[Dd];
    __shared__ float qs[Dd];
    int b = blockIdx.x, t = threadIdx.x;
    spq[t] = pq[b * Dd + t];
    __syncthreads();
    float a = 0.f;
    for (int i = 0; i < Dd; i++) a += spq[i] * Wq[i * Dd + t];
    qs[t] = a;
    __syncthreads();
    float a2 = 0.f;
    for (int j = 0; j < Dd; j++) a2 += Wx[t * Dd + j] * qs[j];
    w[b * Dd + t] = a2;
}

__global__ void k_possim(const float* __restrict__ x, const float* __restrict__ w,
                         float* __restrict__ possim_out, float* __restrict__ sel)
{
    int row = blockIdx.x * 8 + (threadIdx.x >> 5);
    int lane = threadIdx.x & 31;
    int b = row / Nn;
    float s = 0.f;
    for (int e = lane; e < Dd; e += 32) s += x[(size_t)row * Dd + e] * w[b * Dd + e];
    #pragma unroll
    for (int o = 16; o; o >>= 1) s += __shfl_xor_sync(0xffffffffu, s, o);
    if (lane == 0) {
        float p = 1.f / (1.f + expf(-s * 0.0625f));
        possim_out[row] = p;
        sel[row] = (p > 0.97f) ? 1.f : 0.f;
    }
}

__global__ void k_dot2(const float* __restrict__ rows, const float* __restrict__ a1,
                       const float* __restrict__ a2, float* __restrict__ s1,
                       float* __restrict__ s2, int nheads)
{
    int row = blockIdx.x * 8 + (threadIdx.x >> 5);
    int lane = threadIdx.x & 31;
    int head = (row / Nn) % nheads;
    const float* rp = rows + (size_t)row * Dd;
    const float* a1p = a1 + head * Dd;
    const float* a2p = a2 + head * Dd;
    float u = 0.f, v = 0.f;
    for (int e = lane; e < Dd; e += 32) {
        float rv = rp[e];
        u += rv * a1p[e];
        v += rv * a2p[e];
    }
    #pragma unroll
    for (int o = 16; o; o >>= 1) {
        u += __shfl_xor_sync(0xffffffffu, u, o);
        v += __shfl_xor_sync(0xffffffffu, v, o);
    }
    if (lane == 0) { s1[row] = u; s2[row] = v; }
}

// GAT masked softmax -> bf16 output
__global__ void k_softmax_gat(const float* __restrict__ s1, const float* __restrict__ s2,
                              const uint8_t* __restrict__ connect, __nv_bfloat16* __restrict__ attn,
                              int nheads)
{
    __shared__ float red[256];
    int i = blockIdx.x;
    int z = blockIdx.y;
    int b = z / nheads;
    const uint8_t* con = connect + (size_t)b * NNt + (size_t)i * Nn;
    const float* s2p = s2 + (size_t)z * Nn;
    float s1v = s1[(size_t)z * Nn + i];
    int t = threadIdx.x;
    float v[4];
    float mx = -INFINITY;
    #pragma unroll
    for (int k = 0; k < 4; k++) {
        int j = t + k * 256;
        float e = s1v + s2p[j];
        e = (e >= 0.f) ? e : 0.2f * e;
        v[k] = con[j] ? e : -9.0e15f;
        mx = fmaxf(mx, v[k]);
    }
    red[t] = mx; __syncthreads();
    for (int s = 128; s > 0; s >>= 1) { if (t < s) red[t] = fmaxf(red[t], red[t + s]); __syncthreads(); }
    mx = red[0]; __syncthreads();
    float sum = 0.f;
    #pragma unroll
    for (int k = 0; k < 4; k++) { v[k] = expf(v[k] - mx); sum += v[k]; }
    red[t] = sum; __syncthreads();
    for (int s = 128; s > 0; s >>= 1) { if (t < s) red[t] += red[t + s]; __syncthreads(); }
    float inv = 1.f / red[0];
    __nv_bfloat16* out = attn + (size_t)z * NNt + (size_t)i * Nn;
    #pragma unroll
    for (int k = 0; k < 4; k++) out[t + k * 256] = __float2bfloat16(v[k] * inv);
}

// CA masked softmax: fp32 logits in, bf16 out, scale 0.125
__global__ void k_softmax_ca(const float* __restrict__ logits, const float* __restrict__ sel,
                             __nv_bfloat16* __restrict__ attn)
{
    __shared__ float red[256];
    int i = blockIdx.x;
    int z = blockIdx.y;
    int b = z / HC;
    const float* row = logits + (size_t)z * NNt + (size_t)i * Nn;
    const float* sp = sel + b * Nn;
    int t = threadIdx.x;
    float v[4];
    float mx = -INFINITY;
    #pragma unroll
    for (int k = 0; k < 4; k++) {
        int j = t + k * 256;
        v[k] = (sp[j] > 0.5f) ? row[j] * 0.125f : -1.0e9f;
        mx = fmaxf(mx, v[k]);
    }
    red[t] = mx; __syncthreads();
    for (int s = 128; s > 0; s >>= 1) { if (t < s) red[t] = fmaxf(red[t], red[t + s]); __syncthreads(); }
    mx = red[0]; __syncthreads();
    float sum = 0.f;
    #pragma unroll
    for (int k = 0; k < 4; k++) { v[k] = expf(v[k] - mx); sum += v[k]; }
    red[t] = sum; __syncthreads();
    for (int s = 128; s > 0; s >>= 1) { if (t < s) red[t] += red[t + s]; __syncthreads(); }
    float inv = 1.f / red[0];
    __nv_bfloat16* out = attn + (size_t)z * NNt + (size_t)i * Nn;
    #pragma unroll
    for (int k = 0; k < 4; k++) out[t + k * 256] = __float2bfloat16(v[k] * inv);
}

__global__ void k_ln(const float* __restrict__ in, const float* __restrict__ g,
                     const float* __restrict__ bb, float* __restrict__ out)
{
    int row = blockIdx.x * 8 + (threadIdx.x >> 5);
    int lane = threadIdx.x & 31;
    size_t base = (size_t)row * Dd;
    float vbuf[8];
    float s = 0.f, sq = 0.f;
    #pragma unroll
    for (int k = 0; k < 8; k++) {
        float x = in[base + lane + k * 32];
        vbuf[k] = x; s += x; sq += x * x;
    }
    #pragma unroll
    for (int o = 16; o; o >>= 1) {
        s += __shfl_xor_sync(0xffffffffu, s, o);
        sq += __shfl_xor_sync(0xffffffffu, sq, o);
    }
    float mean = s * (1.f / Dd);
    float var = sq * (1.f / Dd) - mean * mean;
    float rstd = rsqrtf(var + 1e-5f);
    #pragma unroll
    for (int k = 0; k < 8; k++) {
        int d = lane + k * 32;
        out[base + d] = (vbuf[k] - mean) * rstd * g[d] + bb[d];
    }
}

__global__ void k_qfull_ln(const float* __restrict__ gout, const float* __restrict__ pe,
                           const float* __restrict__ sel, const float* __restrict__ g,
                           const float* __restrict__ bb, float* __restrict__ out)
{
    int row = blockIdx.x * 8 + (threadIdx.x >> 5);
    int lane = threadIdx.x & 31;
    int n = row % Nn;
    size_t base = (size_t)row * Dd;
    float selv = sel[row];
    float vbuf[8];
    float s = 0.f, sq = 0.f;
    #pragma unroll
    for (int k = 0; k < 8; k++) {
        int d = lane + k * 32;
        float x = (selv > 0.5f) ? (gout[base + d] + pe[(size_t)n * Dd + d]) : 0.f;
        vbuf[k] = x; s += x; sq += x * x;
    }
    #pragma unroll
    for (int o = 16; o; o >>= 1) {
        s += __shfl_xor_sync(0xffffffffu, s, o);
        sq += __shfl_xor_sync(0xffffffffu, sq, o);
    }
    float mean = s * (1.f / Dd);
    float var = sq * (1.f / Dd) - mean * mean;
    float rstd = rsqrtf(var + 1e-5f);
    #pragma unroll
    for (int k = 0; k < 8; k++) {
        int d = lane + k * 32;
        out[base + d] = (vbuf[k] - mean) * rstd * g[d] + bb[d];
    }
}

// ---------------- launch ----------------
#define GETSYM(p, T, s) do { void* _t; cudaGetSymbolAddress(&_t, s); p = (T*)_t; } while (0)
#define SMEMSZ(BM, BN, NAPL) (2 * (NAPL) * (BM) * ROWB + 4 * (BN) * ROWB)

extern "C" void kernel_launch(void* const* d_in, const int* in_sizes, int n_in,
                              void* d_out, int out_size)
{
    const float* x      = (const float*)d_in[0];
    const int*   mask   = (const int*)  d_in[1];
    const float* pe     = (const float*)d_in[2];
    const float* simWx  = (const float*)d_in[3];
    const float* simWq  = (const float*)d_in[4];
    const float* adjW   = (const float*)d_in[5];
    const float* gatW   = (const float*)d_in[6];
    const float* gatA1  = (const float*)d_in[7];
    const float* gatA2  = (const float*)d_in[8];
    const float* gatWo  = (const float*)d_in[9];
    const float* gatAo1 = (const float*)d_in[10];
    const float* gatAo2 = (const float*)d_in[11];
    const float* ln3g   = (const float*)d_in[12];
    const float* ln3b   = (const float*)d_in[13];
    const float* ln4g   = (const float*)d_in[14];
    const float* ln4b   = (const float*)d_in[15];
    const float* caWq   = (const float*)d_in[16];
    const float* caWk   = (const float*)d_in[17];
    const float* caWv   = (const float*)d_in[18];
    const float* caWp   = (const float*)d_in[19];
    const float* gamma  = (const float*)d_in[20];
    (void)in_sizes; (void)n_in; (void)out_size;

    float* out = (float*)d_out;
    float* possim_out = out + (size_t)Bz * Nn * Dd;

    float *posq, *w, *sel, *fa, *Wh, *s1, *s2, *logits, *cat, *Who;
    float *so1, *so2, *gout, *qx, *kv, *q, *k, *v, *o;
    uint8_t* connect;
    uint32_t *WhT, *WhoT, *vT;
    __nv_bfloat16 *attn_bf, *attno_bf;
    float *adjWT, *gatWT, *WoT, *caWqT, *caWkT, *caWvT, *caWpT;
    GETSYM(posq, float, g_posq);   GETSYM(w, float, g_w);       GETSYM(sel, float, g_sel);
    GETSYM(fa, float, g_fa);       GETSYM(connect, uint8_t, g_connect);
    GETSYM(Wh, float, g_Wh);       GETSYM(WhT, uint32_t, g_WhT);
    GETSYM(s1, float, g_s1);       GETSYM(s2, float, g_s2);
    GETSYM(logits, float, g_logits);
    GETSYM(attn_bf, __nv_bfloat16, g_attn_bf);
    GETSYM(attno_bf, __nv_bfloat16, g_attno_bf);
    GETSYM(cat, float, g_cat);
    GETSYM(Who, float, g_Who);     GETSYM(WhoT, uint32_t, g_WhoT);
    GETSYM(so1, float, g_so1);     GETSYM(so2, float, g_so2);
    GETSYM(gout, float, g_gout);   GETSYM(qx, float, g_qx);     GETSYM(kv, float, g_kv);
    GETSYM(q, float, g_q);         GETSYM(k, float, g_k);       GETSYM(v, float, g_v);
    GETSYM(vT, uint32_t, g_vT);    GETSYM(o, float, g_o);
    GETSYM(adjWT, float, g_adjWT); GETSYM(gatWT, float, g_gatWT); GETSYM(WoT, float, g_WoT);
    GETSYM(caWqT, float, g_caWqT); GETSYM(caWkT, float, g_caWkT);
    GETSYM(caWvT, float, g_caWvT); GETSYM(caWpT, float, g_caWpT);

    const int SM_FF  = SMEMSZ(128, 128, 2);   // AF32 128x128 (80 KB -> 2 CTAs/SM)
    const int SM_BP  = SMEMSZ(128, 128, 1);   // ABF16 128x128 (60 KB)
    const int SM_BP2 = SMEMSZ(256, 64, 1);    // ABF16 256x64 (60 KB)
    cudaFuncSetAttribute(mma_gemm<128,128,2,4,EPI_NONE,   AF32, BF32,false>, cudaFuncAttributeMaxDynamicSharedMemorySize, SM_FF);
    cudaFuncSetAttribute(mma_gemm<128,128,2,4,EPI_NONE,   AF32, BF32,true >, cudaFuncAttributeMaxDynamicSharedMemorySize, SM_FF);
    cudaFuncSetAttribute(mma_gemm<128,128,2,4,EPI_CONNECT,AF32, BF32,false>, cudaFuncAttributeMaxDynamicSharedMemorySize, SM_FF);
    cudaFuncSetAttribute(mma_gemm<128,128,2,4,EPI_RESID,  AF32, BF32,false>, cudaFuncAttributeMaxDynamicSharedMemorySize, SM_FF);
    cudaFuncSetAttribute(mma_gemm<128,128,2,4,EPI_ELU,    ABF16,BP2, false>, cudaFuncAttributeMaxDynamicSharedMemorySize, SM_BP);
    cudaFuncSetAttribute(mma_gemm<256,64, 4,2,EPI_NONE,   ABF16,BP2, false>, cudaFuncAttributeMaxDynamicSharedMemorySize, SM_BP2);

    const long zero = 0;

    // 0: all weight transposes in one launch
    k_transpose_all<<<1344, dim3(32, 8)>>>(adjW, adjWT, caWq, caWqT, caWk, caWkT,
                                           caWv, caWvT, caWp, caWpT, gatW, gatWT, gatWo, WoT);

    // 1-3: selection path
    k_posquery<<<Bz, 256>>>(x, mask, posq);
    k_simvec<<<Bz, 256>>>(simWx, simWq, posq, w);
    k_possim<<<Bz * Nn / 8, 256>>>(x, w, possim_out, sel);

    // 4: fa = x @ adjW
    mma_gemm<128,128,2,4,EPI_NONE,AF32,BF32,false><<<dim3(2, 64, 1), 256, SM_FF>>>(
        x, adjWT, fa, Dd, Dd, Dd, Dd,
        1, zero, zero, zero, zero, zero, zero,
        nullptr, zero, nullptr, nullptr, zero, zero, 0);

    // 5: connect (u8) = (fa fa^T > 0) & sel_i & sel_j
    mma_gemm<128,128,2,4,EPI_CONNECT,AF32,BF32,false><<<dim3(8, 8, Bz), 256, SM_FF>>>(
        fa, fa, connect, Dd, Dd, Dd, Nn,
        1, (long)ND, zero, (long)ND, zero, (long)NNt, zero,
        sel, (long)Nn, nullptr, nullptr, zero, zero, 0);

    // 6: Wh = x @ gatW[h]; dual-write WhT (P2)
    mma_gemm<128,128,2,4,EPI_NONE,AF32,BF32,true><<<dim3(2, 8, Bz * Hh), 256, SM_FF>>>(
        x, gatWT, Wh, Dd, Dd, Dd, Dd,
        Hh, (long)ND, zero, zero, (long)Dd * Dd, (long)Hh * ND, (long)ND,
        nullptr, zero, nullptr, WhT, (long)Hh * ND, (long)ND, Nn);

    // 7: s1/s2
    k_dot2<<<Bz * Hh * Nn / 8, 256>>>(Wh, gatA1, gatA2, s1, s2, Hh);

    // 8: GAT softmax -> bf16
    k_softmax_gat<<<dim3(Nn, Bz * Hh), 256>>>(s1, s2, connect, attn_bf, Hh);

    // 9: cat = elu( attn @ Wh )   [A bf16, B P2, 2-product]
    mma_gemm<128,128,2,4,EPI_ELU,ABF16,BP2,false><<<dim3(2, 8, Bz * Hh), 256, SM_BP>>>(
        attn_bf, WhT, cat, Nn, Nn, Nn, HD,
        Hh, (long)Hh * NNt, (long)NNt, (long)Hh * ND, (long)ND, (long)Nn * HD, (long)Dd,
        nullptr, zero, nullptr, nullptr, zero, zero, 0);

    // 10: Who = cat @ gatWo; dual-write WhoT (P2)
    mma_gemm<128,128,2,4,EPI_NONE,AF32,BF32,true><<<dim3(2, 8, Bz), 256, SM_FF>>>(
        cat, WoT, Who, HD, HD, HD, Dd,
        1, (long)Nn * HD, zero, zero, zero, (long)ND, zero,
        nullptr, zero, nullptr, WhoT, (long)ND, zero, Nn);

    // 11: so1/so2
    k_dot2<<<Bz * Nn / 8, 256>>>(Who, gatAo1, gatAo2, so1, so2, 1);

    // 12: out-layer softmax -> bf16
    k_softmax_gat<<<dim3(Nn, Bz), 256>>>(so1, so2, connect, attno_bf, 1);

    // 13: gout = elu( attn_o @ Who )   [2-product]
    mma_gemm<128,128,2,4,EPI_ELU,ABF16,BP2,false><<<dim3(2, 8, Bz), 256, SM_BP>>>(
        attno_bf, WhoT, gout, Nn, Nn, Nn, Dd,
        1, (long)NNt, zero, (long)ND, zero, (long)ND, zero,
        nullptr, zero, nullptr, nullptr, zero, zero, 0);

    // 14-15: LayerNorms
    k_ln<<<Bz * Nn / 8, 256>>>(x, ln3g, ln3b, qx);
    k_qfull_ln<<<Bz * Nn / 8, 256>>>(gout, pe, sel, ln4g, ln4b, kv);

    // 16: q/k/v projections; v dual-writes vT (P2)
    mma_gemm<128,128,2,4,EPI_NONE,AF32,BF32,false><<<dim3(2, 64, 1), 256, SM_FF>>>(
        qx, caWqT, q, Dd, Dd, Dd, Dd,
        1, zero, zero, zero, zero, zero, zero,
        nullptr, zero, nullptr, nullptr, zero, zero, 0);
    mma_gemm<128,128,2,4,EPI_NONE,AF32,BF32,false><<<dim3(2, 64, 1), 256, SM_FF>>>(
        kv, caWkT, k, Dd, Dd, Dd, Dd,
        1, zero, zero, zero, zero, zero, zero,
        nullptr, zero, nullptr, nullptr, zero, zero, 0);
    mma_gemm<128,128,2,4,EPI_NONE,AF32,BF32,true><<<dim3(2, 8, Bz), 256, SM_FF>>>(
        kv, caWvT, v, Dd, Dd, Dd, Dd,
        1, (long)ND, zero, zero, zero, (long)ND, zero,
        nullptr, zero, nullptr, vT, (long)ND, zero, Nn);

    // 17: CA logits (fp32)
    mma_gemm<128,128,2,4,EPI_NONE,AF32,BF32,false><<<dim3(8, 8, Bz * HC), 256, SM_FF>>>(
        q, k, logits, DH, Dd, Dd, Nn,
        HC, (long)ND, (long)DH, (long)ND, (long)DH, (long)HC * NNt, (long)NNt,
        nullptr, zero, nullptr, nullptr, zero, zero, 0);

    // 18: CA softmax -> bf16 (reuse attn_bf)
    k_softmax_ca<<<dim3(Nn, Bz * HC), 256>>>(logits, sel, attn_bf);

    // 19: o = a @ v   [2-product, 256x64 tiles]
    mma_gemm<256,64,4,2,EPI_NONE,ABF16,BP2,false><<<dim3(1, 4, Bz * HC), 256, SM_BP2>>>(
        attn_bf, vT, o, Nn, Nn, Nn, Dd,
        HC, (long)HC * NNt, (long)NNt, (long)ND, (long)DH * Nn, (long)ND, (long)DH,
        nullptr, zero, nullptr, nullptr, zero, zero, 0);

    // 20: out = x + gamma * (o @ caWp)
    mma_gemm<128,128,2,4,EPI_RESID,AF32,BF32,false><<<dim3(2, 64, 1), 256, SM_FF>>>(
        o, caWpT, out, Dd, Dd, Dd, Dd,
        1, zero, zero, zero, zero, zero, zero,
        x, zero, gamma, nullptr, zero, zero, 0);
}

// round 6
// speedup vs baseline: 1.0896x; 1.0896x over previous
#include <cuda_runtime.h>
#include <cuda_bf16.h>
#include <math.h>
#include <stdint.h>

// Problem constants
#define Bz 8
#define Nn 1024
#define Dd 256
#define Hh 8
#define HC 4
#define DH 64
#define HD 2048                 // Hh*Dd
#define ND (Nn*Dd)              // 262144
#define NNt ((size_t)Nn*Nn)     // 1048576

// ---------------- scratch (device globals) ----------------
// Plane-pair convention: array of 2*L bf16; hi plane at [0,L), lo plane at [L,2L).
__device__ float g_posq[Bz*Dd];
__device__ float g_w[Bz*Dd];
__device__ float g_sel[Bz*Nn];
__device__ uint8_t g_connect[(size_t)Bz*Nn*Nn];
__device__ float g_s1[Bz*Hh*Nn];
__device__ float g_s2[Bz*Hh*Nn];
__device__ float g_so1[Bz*Nn];
__device__ float g_so2[Bz*Nn];
__device__ float g_logits[(size_t)Bz*HC*Nn*Nn];            // 128 MB
__device__ __nv_bfloat16 g_attn_bf[(size_t)Bz*Hh*Nn*Nn];   // GAT / CA probs
__device__ __nv_bfloat16 g_attno_bf[(size_t)Bz*Nn*Nn];

__device__ __nv_bfloat16 g_x2[2*(size_t)Bz*ND];
__device__ __nv_bfloat16 g_fa2[2*(size_t)Bz*ND];
__device__ __nv_bfloat16 g_Wh2[2*(size_t)Bz*Hh*ND];
__device__ __nv_bfloat16 g_WhT2[2*(size_t)Bz*Hh*ND];
__device__ __nv_bfloat16 g_cat2[2*(size_t)Bz*Nn*HD];
__device__ __nv_bfloat16 g_Who2[2*(size_t)Bz*ND];
__device__ __nv_bfloat16 g_WhoT2[2*(size_t)Bz*ND];
__device__ __nv_bfloat16 g_gout2[2*(size_t)Bz*ND];
__device__ __nv_bfloat16 g_qx2[2*(size_t)Bz*ND];
__device__ __nv_bfloat16 g_kv2[2*(size_t)Bz*ND];
__device__ __nv_bfloat16 g_q2[2*(size_t)Bz*ND];
__device__ __nv_bfloat16 g_k2[2*(size_t)Bz*ND];
__device__ __nv_bfloat16 g_vT2[2*(size_t)Bz*ND];
__device__ __nv_bfloat16 g_o2[2*(size_t)Bz*ND];
// transposed weights (planes)
__device__ __nv_bfloat16 g_adjWT2[2*Dd*Dd];
__device__ __nv_bfloat16 g_gatWT2[2*Hh*Dd*Dd];
__device__ __nv_bfloat16 g_WoT2[2*HD*Dd];
__device__ __nv_bfloat16 g_caWqT2[2*Dd*Dd];
__device__ __nv_bfloat16 g_caWkT2[2*Dd*Dd];
__device__ __nv_bfloat16 g_caWvT2[2*Dd*Dd];
__device__ __nv_bfloat16 g_caWpT2[2*Dd*Dd];

// ---------------- low-level helpers ----------------
__device__ __forceinline__ uint32_t smem_u32(const void* p) {
    uint32_t a;
    asm("{ .reg .u64 t; cvta.to.shared.u64 t, %1; cvt.u32.u64 %0, t; }" : "=r"(a) : "l"(p));
    return a;
}
__device__ __forceinline__ void ldsm4(uint32_t* r, uint32_t addr) {
    asm volatile("ldmatrix.sync.aligned.m8n8.x4.shared.b16 {%0,%1,%2,%3}, [%4];"
        : "=r"(r[0]), "=r"(r[1]), "=r"(r[2]), "=r"(r[3]) : "r"(addr));
}
__device__ __forceinline__ void mma16816(float* c, const uint32_t* a, const uint32_t* b) {
    asm volatile("mma.sync.aligned.m16n8k16.row.col.f32.bf16.bf16.f32 "
        "{%0,%1,%2,%3}, {%4,%5,%6,%7}, {%8,%9}, {%0,%1,%2,%3};"
        : "+f"(c[0]), "+f"(c[1]), "+f"(c[2]), "+f"(c[3])
        : "r"(a[0]), "r"(a[1]), "r"(a[2]), "r"(a[3]), "r"(b[0]), "r"(b[1]));
}
__device__ __forceinline__ void split1(float v, __nv_bfloat16& h, __nv_bfloat16& l) {
    h = __float2bfloat16(v);
    l = __float2bfloat16(v - __bfloat162float(h));
}
__device__ __forceinline__ uint32_t pack2(__nv_bfloat16 a, __nv_bfloat16 b) {
    return (uint32_t)__bfloat16_as_ushort(a) | ((uint32_t)__bfloat16_as_ushort(b) << 16);
}
#define CP16(dst, src) \
    asm volatile("cp.async.cg.shared.global [%0], [%1], 16;" :: "r"(dst), "l"(src))
#define CP_COMMIT() asm volatile("cp.async.commit_group;" ::: "memory")

// ---------------- split x into planes ----------------
__global__ void k_split(const float* __restrict__ in, __nv_bfloat16* __restrict__ outp, long plane)
{
    int i = blockIdx.x * 256 + threadIdx.x;
    float4 v = reinterpret_cast<const float4*>(in)[i];
    __nv_bfloat16 h0, l0, h1, l1, h2, l2, h3, l3;
    split1(v.x, h0, l0); split1(v.y, h1, l1); split1(v.z, h2, l2); split1(v.w, h3, l3);
    uint2 hp = make_uint2(pack2(h0, h1), pack2(h2, h3));
    uint2 lp = make_uint2(pack2(l0, l1), pack2(l2, l3));
    reinterpret_cast<uint2*>(outp)[i] = hp;
    reinterpret_cast<uint2*>(outp + plane)[i] = lp;
}

// ---------------- merged transpose kernel (emit planes) ----------------
__global__ void k_transpose_all(const float* adjW, __nv_bfloat16* adjWT,
                                const float* caWq, __nv_bfloat16* caWqT,
                                const float* caWk, __nv_bfloat16* caWkT,
                                const float* caWv, __nv_bfloat16* caWvT,
                                const float* caWp, __nv_bfloat16* caWpT,
                                const float* gatW, __nv_bfloat16* gatWT,
                                const float* gatWo, __nv_bfloat16* WoT)
{
    __shared__ float t[32][33];
    int id = blockIdx.x;
    int tx = threadIdx.x, ty = threadIdx.y;
    const float* src; __nv_bfloat16* dh; long plane; int R, C, bx, by;
    if (id < 320) {
        const float* srcs[5] = {adjW, caWq, caWk, caWv, caWp};
        __nv_bfloat16* dsts[5] = {adjWT, caWqT, caWkT, caWvT, caWpT};
        int m = id >> 6, l = id & 63;
        src = srcs[m]; dh = dsts[m]; plane = Dd * Dd;
        R = Dd; C = Dd; bx = (l & 7) * 32; by = (l >> 3) * 32;
    } else if (id < 832) {
        int l = id - 320; int z = l >> 6; l &= 63;
        src = gatW + (size_t)z * Dd * Dd; dh = gatWT + (size_t)z * Dd * Dd;
        plane = (long)Hh * Dd * Dd;
        R = Dd; C = Dd; bx = (l & 7) * 32; by = (l >> 3) * 32;
    } else {
        int l = id - 832;
        src = gatWo; dh = WoT; plane = (long)HD * Dd;
        R = HD; C = Dd; bx = (l & 7) * 32; by = (l >> 3) * 32;
    }
    #pragma unroll
    for (int i = 0; i < 32; i += 8)
        t[ty + i][tx] = src[(size_t)(by + ty + i) * C + bx + tx];
    __syncthreads();
    #pragma unroll
    for (int i = 0; i < 32; i += 8) {
        float v = t[tx][ty + i];
        __nv_bfloat16 h, l2;
        split1(v, h, l2);
        size_t o = (size_t)(bx + ty + i) * R + by + tx;
        dh[o] = h; dh[plane + o] = l2;
    }
}

// ---------------- plane-pair bf16 mma.sync NT GEMM ----------------
// C[M,N] = A[M,K] @ B[N,K]^T. Operands are bf16 plane pairs (or single plane probs).
// NA = #A planes (1 or 2); B always 2 planes. Products: Ah*Bh + Ah*Bl (+ Al*Bh if NA==2).
enum { EPI_NONE = 0, EPI_ELU = 1, EPI_CONNECT = 2, EPI_RESID = 3 };
enum { OUT_F32 = 0, OUT_PLANES = 1, OUT_CONNECT = 2, OUT_NONE = 3 };
#define ROWB 80

template <int BM, int BN, int WM, int WN, int EPI, int NA, int OUT, bool DUAL>
__global__ void __launch_bounds__(256, 2)
mma_gemm(const __nv_bfloat16* __restrict__ A, long aPlane,
         const __nv_bfloat16* __restrict__ Bm, long bPlane,
         void* __restrict__ Cv, long cPlane,
         int K, int lda, int ldb, int ldc, int zInner,
         long sAb, long sAi, long sBb, long sBi, long sCb, long sCi,
         const float* __restrict__ e1, long sE1b, const float* __restrict__ e2,
         __nv_bfloat16* __restrict__ Ct, long ctPlane, long sCtb, long sCti, int ldct)
{
    constexpr int ABYTES = BM * ROWB;
    constexpr int BBYTES = BN * ROWB;

    extern __shared__ char smem[];
    const uint32_t sb = smem_u32(smem);

    const int tid = threadIdx.x;
    const int wid = tid >> 5;
    const int lane = tid & 31;

    const int z = blockIdx.z;
    const int zb = z / zInner, zi = z % zInner;
    const __nv_bfloat16* Ap = A + (size_t)zb * sAb + (size_t)zi * sAi;
    const __nv_bfloat16* Bp = Bm + (size_t)zb * sBb + (size_t)zi * sBi;
    float* Cpf = (float*)Cv + (size_t)zb * sCb + (size_t)zi * sCi;
    __nv_bfloat16* Cpb = (__nv_bfloat16*)Cv + (size_t)zb * sCb + (size_t)zi * sCi;
    uint8_t* Cp8 = (uint8_t*)Cv + (size_t)zb * sCb + (size_t)zi * sCi;
    const float* e1p = e1 ? (e1 + (size_t)zb * sE1b) : nullptr;

    const int m0 = blockIdx.y * BM;
    const int n0 = blockIdx.x * BN;

    // cp.async copy indices: 64 rows x 4 chunks of 16B per 256 threads per pass
    const int crow = tid >> 2;
    const int cch = tid & 3;

    const int wid_m = wid % WM;
    const int wid_n = wid / WM;
    const int g = lane >> 3, rl = lane & 7;
    const int aRowBase = wid_m * 64 + (g & 1) * 8 + rl;
    const int aKsel = (g >> 1) * 8;
    const int bRowBase = wid_n * 32 + (g >> 1) * 8 + rl;
    const int bKsel = (g & 1) * 8;

    float acc[4][4][4] = {};
    const int nkt = K >> 5;
    const uint32_t bbase = 2 * NA * ABYTES;

    auto copyTile = [&](int kk, int stage) {
        #pragma unroll
        for (int pl = 0; pl < NA; pl++) {
            const __nv_bfloat16* src = Ap + (size_t)pl * aPlane;
            uint32_t dst0 = sb + (stage * NA + pl) * ABYTES;
            #pragma unroll
            for (int i = 0; i < BM / 64; i++) {
                int row = crow + 64 * i;
                CP16(dst0 + row * ROWB + cch * 16,
                     src + (size_t)(m0 + row) * lda + kk + cch * 8);
            }
        }
        #pragma unroll
        for (int pl = 0; pl < 2; pl++) {
            const __nv_bfloat16* src = Bp + (size_t)pl * bPlane;
            uint32_t dst0 = sb + bbase + (stage * 2 + pl) * BBYTES;
            #pragma unroll
            for (int i = 0; i < BN / 64; i++) {
                int row = crow + 64 * i;
                CP16(dst0 + row * ROWB + cch * 16,
                     src + (size_t)(n0 + row) * ldb + kk + cch * 8);
            }
        }
    };

    copyTile(0, 0); CP_COMMIT();

    for (int kt = 0; kt < nkt; kt++) {
        const int stage = kt & 1;
        const bool more = (kt + 1 < nkt);
        if (more) { copyTile((kt + 1) << 5, stage ^ 1); CP_COMMIT(); }
        if (more) asm volatile("cp.async.wait_group 1;" ::: "memory");
        else      asm volatile("cp.async.wait_group 0;" ::: "memory");
        __syncthreads();

        const uint32_t sAhi = sb + stage * NA * ABYTES;
        const uint32_t sAlo = sAhi + ABYTES;
        const uint32_t sBhi = sb + bbase + stage * 2 * BBYTES;
        const uint32_t sBlo = sBhi + BBYTES;

        #pragma unroll
        for (int j = 0; j < 2; j++) {
            const int kb = j * 16;
            uint32_t a[4][4], bh[4][2], bl[4][2];
            #pragma unroll
            for (int im = 0; im < 4; im++)
                ldsm4(a[im], sAhi + (uint32_t)((aRowBase + im * 16) * ROWB + (kb + aKsel) * 2));
            #pragma unroll
            for (int i2 = 0; i2 < 2; i2++) {
                uint32_t t[4];
                ldsm4(t, sBhi + (uint32_t)((bRowBase + i2 * 16) * ROWB + (kb + bKsel) * 2));
                bh[2 * i2][0] = t[0]; bh[2 * i2][1] = t[1];
                bh[2 * i2 + 1][0] = t[2]; bh[2 * i2 + 1][1] = t[3];
            }
            #pragma unroll
            for (int im = 0; im < 4; im++)
                #pragma unroll
                for (int in = 0; in < 4; in++)
                    mma16816(acc[im][in], a[im], bh[in]);           // Ah*Bh
            #pragma unroll
            for (int i2 = 0; i2 < 2; i2++) {
                uint32_t t[4];
                ldsm4(t, sBlo + (uint32_t)((bRowBase + i2 * 16) * ROWB + (kb + bKsel) * 2));
                bl[2 * i2][0] = t[0]; bl[2 * i2][1] = t[1];
                bl[2 * i2 + 1][0] = t[2]; bl[2 * i2 + 1][1] = t[3];
            }
            #pragma unroll
            for (int im = 0; im < 4; im++)
                #pragma unroll
                for (int in = 0; in < 4; in++)
                    mma16816(acc[im][in], a[im], bl[in]);           // Ah*Bl
            if (NA == 2) {
                #pragma unroll
                for (int im = 0; im < 4; im++)
                    ldsm4(a[im], sAlo + (uint32_t)((aRowBase + im * 16) * ROWB + (kb + aKsel) * 2));
                #pragma unroll
                for (int im = 0; im < 4; im++)
                    #pragma unroll
                    for (int in = 0; in < 4; in++)
                        mma16816(acc[im][in], a[im], bh[in]);       // Al*Bh
            }
        }
        __syncthreads();
    }

    // epilogue
    const int mw = m0 + wid_m * 64;
    const int nw = n0 + wid_n * 32;
    #pragma unroll
    for (int im = 0; im < 4; im++) {
        const int row = mw + im * 16 + (lane >> 2);
        const float sr0 = (EPI == EPI_CONNECT) ? e1p[row] : 0.f;
        const float sr1 = (EPI == EPI_CONNECT) ? e1p[row + 8] : 0.f;
        #pragma unroll
        for (int in = 0; in < 4; in++) {
            const int col = nw + in * 8 + (lane & 3) * 2;
            float v00 = acc[im][in][0], v01 = acc[im][in][1];
            float v10 = acc[im][in][2], v11 = acc[im][in][3];
            if (EPI == EPI_ELU) {
                v00 = v00 > 0.f ? v00 : expm1f(v00);
                v01 = v01 > 0.f ? v01 : expm1f(v01);
                v10 = v10 > 0.f ? v10 : expm1f(v10);
                v11 = v11 > 0.f ? v11 : expm1f(v11);
            } else if (EPI == EPI_RESID) {
                const float g0 = e2[col], g1 = e2[col + 1];
                const size_t r0 = (size_t)row * ldc + col;
                const size_t r1 = (size_t)(row + 8) * ldc + col;
                v00 = e1p[r0] + g0 * v00; v01 = e1p[r0 + 1] + g1 * v01;
                v10 = e1p[r1] + g0 * v10; v11 = e1p[r1 + 1] + g1 * v11;
            }
            const size_t o0 = (size_t)row * ldc + col;
            const size_t o1 = (size_t)(row + 8) * ldc + col;
            if (OUT == OUT_CONNECT) {
                const float sc0 = e1p[col], sc1 = e1p[col + 1];
                uchar2 c0, c1;
                c0.x = (v00 > 0.f && sr0 > 0.5f && sc0 > 0.5f) ? 1 : 0;
                c0.y = (v01 > 0.f && sr0 > 0.5f && sc1 > 0.5f) ? 1 : 0;
                c1.x = (v10 > 0.f && sr1 > 0.5f && sc0 > 0.5f) ? 1 : 0;
                c1.y = (v11 > 0.f && sr1 > 0.5f && sc1 > 0.5f) ? 1 : 0;
                *reinterpret_cast<uchar2*>(Cp8 + o0) = c0;
                *reinterpret_cast<uchar2*>(Cp8 + o1) = c1;
            } else if (OUT == OUT_F32) {
                *reinterpret_cast<float2*>(Cpf + o0) = make_float2(v00, v01);
                *reinterpret_cast<float2*>(Cpf + o1) = make_float2(v10, v11);
            }
            __nv_bfloat16 h00, l00, h01, l01, h10, l10, h11, l11;
            if (OUT == OUT_PLANES || DUAL) {
                split1(v00, h00, l00); split1(v01, h01, l01);
                split1(v10, h10, l10); split1(v11, h11, l11);
            }
            if (OUT == OUT_PLANES) {
                *reinterpret_cast<uint32_t*>(Cpb + o0) = pack2(h00, h01);
                *reinterpret_cast<uint32_t*>(Cpb + o1) = pack2(h10, h11);
                *reinterpret_cast<uint32_t*>(Cpb + cPlane + o0) = pack2(l00, l01);
                *reinterpret_cast<uint32_t*>(Cpb + cPlane + o1) = pack2(l10, l11);
            }
            if (DUAL) {
                __nv_bfloat16* Ctp = Ct + (size_t)zb * sCtb + (size_t)zi * sCti;
                const size_t t0 = (size_t)col * ldct + row;
                const size_t t1 = (size_t)(col + 1) * ldct + row;
                Ctp[t0] = h00; Ctp[t0 + 8] = h10;
                Ctp[t1] = h01; Ctp[t1 + 8] = h11;
                Ctp[ctPlane + t0] = l00; Ctp[ctPlane + t0 + 8] = l10;
                Ctp[ctPlane + t1] = l01; Ctp[ctPlane + t1 + 8] = l11;
            }
        }
    }
}

// ---------------- auxiliary kernels ----------------
__global__ void k_posquery(const float* __restrict__ x, const int* __restrict__ mask,
                           float* __restrict__ pq)
{
    int b = blockIdx.x, d = threadIdx.x;
    float s = 0.f, cnt = 0.f;
    for (int n = 0; n < Nn; n++) {
        int m = mask[b * Nn + n];
        if (m == 1) { s += x[((size_t)b * Nn + n) * Dd + d]; cnt += 1.f; }
    }
    pq[b * Dd + d] = s / fmaxf(cnt, 1.f);
}

__global__ void k_simvec(const float* __restrict__ Wx, const float* __restrict__ Wq,
                         const float* __restrict__ pq, float* __restrict__ w)
{
    __shared__ float spq[Dd];
    __shared__ float qs[Dd];
    int b = blockIdx.x, t = threadIdx.x;
    spq[t] = pq[b * Dd + t];
    __syncthreads();
    float a = 0.f;
    for (int i = 0; i < Dd; i++) a += spq[i] * Wq[i * Dd + t];
    qs[t] = a;
    __syncthreads();
    float a2 = 0.f;
    for (int j = 0; j < Dd; j++) a2 += Wx[t * Dd + j] * qs[j];
    w[b * Dd + t] = a2;
}

__global__ void k_possim(const float* __restrict__ x, const float* __restrict__ w,
                         float* __restrict__ possim_out, float* __restrict__ sel)
{
    int row = blockIdx.x * 8 + (threadIdx.x >> 5);
    int lane = threadIdx.x & 31;
    int b = row / Nn;
    float s = 0.f;
    for (int e = lane; e < Dd; e += 32) s += x[(size_t)row * Dd + e] * w[b * Dd + e];
    #pragma unroll
    for (int o = 16; o; o >>= 1) s += __shfl_xor_sync(0xffffffffu, s, o);
    if (lane == 0) {
        float p = 1.f / (1.f + expf(-s * 0.0625f));
        possim_out[row] = p;
        sel[row] = (p > 0.97f) ? 1.f : 0.f;
    }
}

// dot of plane-pair rows with a1/a2
__global__ void k_dot2p(const __nv_bfloat16* __restrict__ rows, long plane,
                        const float* __restrict__ a1, const float* __restrict__ a2,
                        float* __restrict__ s1, float* __restrict__ s2, int nheads)
{
    int row = blockIdx.x * 8 + (threadIdx.x >> 5);
    int lane = threadIdx.x & 31;
    int head = (row / Nn) % nheads;
    const __nv_bfloat16* rp = rows + (size_t)row * Dd;
    const float* a1p = a1 + head * Dd;
    const float* a2p = a2 + head * Dd;
    float u = 0.f, v = 0.f;
    for (int e = lane; e < Dd; e += 32) {
        float rv = __bfloat162float(rp[e]) + __bfloat162float(rp[plane + e]);
        u += rv * a1p[e];
        v += rv * a2p[e];
    }
    #pragma unroll
    for (int o = 16; o; o >>= 1) {
        u += __shfl_xor_sync(0xffffffffu, u, o);
        v += __shfl_xor_sync(0xffffffffu, v, o);
    }
    if (lane == 0) { s1[row] = u; s2[row] = v; }
}

__global__ void k_softmax_gat(const float* __restrict__ s1, const float* __restrict__ s2,
                              const uint8_t* __restrict__ connect, __nv_bfloat16* __restrict__ attn,
                              int nheads)
{
    __shared__ float red[256];
    int i = blockIdx.x;
    int z = blockIdx.y;
    int b = z / nheads;
    const uint8_t* con = connect + (size_t)b * NNt + (size_t)i * Nn;
    const float* s2p = s2 + (size_t)z * Nn;
    float s1v = s1[(size_t)z * Nn + i];
    int t = threadIdx.x;
    float v[4];
    float mx = -INFINITY;
    #pragma unroll
    for (int k = 0; k < 4; k++) {
        int j = t + k * 256;
        float e = s1v + s2p[j];
        e = (e >= 0.f) ? e : 0.2f * e;
        v[k] = con[j] ? e : -9.0e15f;
        mx = fmaxf(mx, v[k]);
    }
    red[t] = mx; __syncthreads();
    for (int s = 128; s > 0; s >>= 1) { if (t < s) red[t] = fmaxf(red[t], red[t + s]); __syncthreads(); }
    mx = red[0]; __syncthreads();
    float sum = 0.f;
    #pragma unroll
    for (int k = 0; k < 4; k++) { v[k] = expf(v[k] - mx); sum += v[k]; }
    red[t] = sum; __syncthreads();
    for (int s = 128; s > 0; s >>= 1) { if (t < s) red[t] += red[t + s]; __syncthreads(); }
    float inv = 1.f / red[0];
    __nv_bfloat16* out = attn + (size_t)z * NNt + (size_t)i * Nn;
    #pragma unroll
    for (int k = 0; k < 4; k++) out[t + k * 256] = __float2bfloat16(v[k] * inv);
}

__global__ void k_softmax_ca(const float* __restrict__ logits, const float* __restrict__ sel,
                             __nv_bfloat16* __restrict__ attn)
{
    __shared__ float red[256];
    int i = blockIdx.x;
    int z = blockIdx.y;
    int b = z / HC;
    const float* row = logits + (size_t)z * NNt + (size_t)i * Nn;
    const float* sp = sel + b * Nn;
    int t = threadIdx.x;
    float v[4];
    float mx = -INFINITY;
    #pragma unroll
    for (int k = 0; k < 4; k++) {
        int j = t + k * 256;
        v[k] = (sp[j] > 0.5f) ? row[j] * 0.125f : -1.0e9f;
        mx = fmaxf(mx, v[k]);
    }
    red[t] = mx; __syncthreads();
    for (int s = 128; s > 0; s >>= 1) { if (t < s) red[t] = fmaxf(red[t], red[t + s]); __syncthreads(); }
    mx = red[0]; __syncthreads();
    float sum = 0.f;
    #pragma unroll
    for (int k = 0; k < 4; k++) { v[k] = expf(v[k] - mx); sum += v[k]; }
    red[t] = sum; __syncthreads();
    for (int s = 128; s > 0; s >>= 1) { if (t < s) red[t] += red[t + s]; __syncthreads(); }
    float inv = 1.f / red[0];
    __nv_bfloat16* out = attn + (size_t)z * NNt + (size_t)i * Nn;
    #pragma unroll
    for (int k = 0; k < 4; k++) out[t + k * 256] = __float2bfloat16(v[k] * inv);
}

// LayerNorm: fp32 in -> plane-pair out
__global__ void k_ln(const float* __restrict__ in, const float* __restrict__ g,
                     const float* __restrict__ bb, __nv_bfloat16* __restrict__ out, long oplane)
{
    int row = blockIdx.x * 8 + (threadIdx.x >> 5);
    int lane = threadIdx.x & 31;
    size_t base = (size_t)row * Dd;
    float vbuf[8];
    float s = 0.f, sq = 0.f;
    #pragma unroll
    for (int k = 0; k < 8; k++) {
        float x = in[base + lane + k * 32];
        vbuf[k] = x; s += x; sq += x * x;
    }
    #pragma unroll
    for (int o = 16; o; o >>= 1) {
        s += __shfl_xor_sync(0xffffffffu, s, o);
        sq += __shfl_xor_sync(0xffffffffu, sq, o);
    }
    float mean = s * (1.f / Dd);
    float var = sq * (1.f / Dd) - mean * mean;
    float rstd = rsqrtf(var + 1e-5f);
    #pragma unroll
    for (int k = 0; k < 8; k++) {
        int d = lane + k * 32;
        float y = (vbuf[k] - mean) * rstd * g[d] + bb[d];
        __nv_bfloat16 h, l; split1(y, h, l);
        out[base + d] = h; out[oplane + base + d] = l;
    }
}

// kv = LN4( sel ? gout + pos_emb : 0 ); gout is plane-pair
__global__ void k_qfull_ln(const __nv_bfloat16* __restrict__ gout, long gplane,
                           const float* __restrict__ pe,
                           const float* __restrict__ sel, const float* __restrict__ g,
                           const float* __restrict__ bb, __nv_bfloat16* __restrict__ out, long oplane)
{
    int row = blockIdx.x * 8 + (threadIdx.x >> 5);
    int lane = threadIdx.x & 31;
    int n = row % Nn;
    size_t base = (size_t)row * Dd;
    float selv = sel[row];
    float vbuf[8];
    float s = 0.f, sq = 0.f;
    #pragma unroll
    for (int k = 0; k < 8; k++) {
        int d = lane + k * 32;
        float gv = __bfloat162float(gout[base + d]) + __bfloat162float(gout[gplane + base + d]);
        float x = (selv > 0.5f) ? (gv + pe[(size_t)n * Dd + d]) : 0.f;
        vbuf[k] = x; s += x; sq += x * x;
    }
    #pragma unroll
    for (int o = 16; o; o >>= 1) {
        s += __shfl_xor_sync(0xffffffffu, s, o);
        sq += __shfl_xor_sync(0xffffffffu, sq, o);
    }
    float mean = s * (1.f / Dd);
    float var = sq * (1.f / Dd) - mean * mean;
    float rstd = rsqrtf(var + 1e-5f);
    #pragma unroll
    for (int k = 0; k < 8; k++) {
        int d = lane + k * 32;
        float y = (vbuf[k] - mean) * rstd * g[d] + bb[d];
        __nv_bfloat16 h, l; split1(y, h, l);
        out[base + d] = h; out[oplane + base + d] = l;
    }
}

// ---------------- launch ----------------
#define GETSYM(p, T, s) do { void* _t; cudaGetSymbolAddress(&_t, s); p = (T*)_t; } while (0)
#define SMEMSZ(BM, BN, NA) ((2 * (NA) * (BM) + 4 * (BN)) * ROWB)

extern "C" void kernel_launch(void* const* d_in, const int* in_sizes, int n_in,
                              void* d_out, int out_size)
{
    const float* x      = (const float*)d_in[0];
    const int*   mask   = (const int*)  d_in[1];
    const float* pe     = (const float*)d_in[2];
    const float* simWx  = (const float*)d_in[3];
    const float* simWq  = (const float*)d_in[4];
    const float* adjW   = (const float*)d_in[5];
    const float* gatW   = (const float*)d_in[6];
    const float* gatA1  = (const float*)d_in[7];
    const float* gatA2  = (const float*)d_in[8];
    const float* gatWo  = (const float*)d_in[9];
    const float* gatAo1 = (const float*)d_in[10];
    const float* gatAo2 = (const float*)d_in[11];
    const float* ln3g   = (const float*)d_in[12];
    const float* ln3b   = (const float*)d_in[13];
    const float* ln4g   = (const float*)d_in[14];
    const float* ln4b   = (const float*)d_in[15];
    const float* caWq   = (const float*)d_in[16];
    const float* caWk   = (const float*)d_in[17];
    const float* caWv   = (const float*)d_in[18];
    const float* caWp   = (const float*)d_in[19];
    const float* gamma  = (const float*)d_in[20];
    (void)in_sizes; (void)n_in; (void)out_size;

    float* out = (float*)d_out;
    float* possim_out = out + (size_t)Bz * Nn * Dd;

    float *posq, *w, *sel, *s1, *s2, *so1, *so2, *logits;
    uint8_t* connect;
    __nv_bfloat16 *attn_bf, *attno_bf;
    __nv_bfloat16 *x2, *fa2, *Wh2, *WhT2, *cat2, *Who2, *WhoT2, *gout2, *qx2, *kv2;
    __nv_bfloat16 *q2, *k2, *vT2, *o2;
    __nv_bfloat16 *adjWT2, *gatWT2, *WoT2, *caWqT2, *caWkT2, *caWvT2, *caWpT2;
    GETSYM(posq, float, g_posq);   GETSYM(w, float, g_w);       GETSYM(sel, float, g_sel);
    GETSYM(connect, uint8_t, g_connect);
    GETSYM(s1, float, g_s1);       GETSYM(s2, float, g_s2);
    GETSYM(so1, float, g_so1);     GETSYM(so2, float, g_so2);
    GETSYM(logits, float, g_logits);
    GETSYM(attn_bf, __nv_bfloat16, g_attn_bf);
    GETSYM(attno_bf, __nv_bfloat16, g_attno_bf);
    GETSYM(x2, __nv_bfloat16, g_x2);     GETSYM(fa2, __nv_bfloat16, g_fa2);
    GETSYM(Wh2, __nv_bfloat16, g_Wh2);   GETSYM(WhT2, __nv_bfloat16, g_WhT2);
    GETSYM(cat2, __nv_bfloat16, g_cat2);
    GETSYM(Who2, __nv_bfloat16, g_Who2); GETSYM(WhoT2, __nv_bfloat16, g_WhoT2);
    GETSYM(gout2, __nv_bfloat16, g_gout2);
    GETSYM(qx2, __nv_bfloat16, g_qx2);   GETSYM(kv2, __nv_bfloat16, g_kv2);
    GETSYM(q2, __nv_bfloat16, g_q2);     GETSYM(k2, __nv_bfloat16, g_k2);
    GETSYM(vT2, __nv_bfloat16, g_vT2);   GETSYM(o2, __nv_bfloat16, g_o2);
    GETSYM(adjWT2, __nv_bfloat16, g_adjWT2); GETSYM(gatWT2, __nv_bfloat16, g_gatWT2);
    GETSYM(WoT2, __nv_bfloat16, g_WoT2);
    GETSYM(caWqT2, __nv_bfloat16, g_caWqT2); GETSYM(caWkT2, __nv_bfloat16, g_caWkT2);
    GETSYM(caWvT2, __nv_bfloat16, g_caWvT2); GETSYM(caWpT2, __nv_bfloat16, g_caWpT2);

    // plane offsets (elements)
    const long PL_BND  = (long)Bz * ND;
    const long PL_BHND = (long)Bz * Hh * ND;
    const long PL_CAT  = (long)Bz * Nn * HD;
    const long PL_DD   = (long)Dd * Dd;
    const long PL_GATW = (long)Hh * Dd * Dd;
    const long PL_WO   = (long)HD * Dd;

    const int SM_22 = SMEMSZ(128, 128, 2);   // 80 KB
    const int SM_12 = SMEMSZ(128, 128, 1);   // 60 KB
    const int SM_AV = SMEMSZ(256, 64, 1);    // 60 KB
    cudaFuncSetAttribute(mma_gemm<128,128,2,4,EPI_NONE,   2,OUT_PLANES, false>, cudaFuncAttributeMaxDynamicSharedMemorySize, SM_22);
    cudaFuncSetAttribute(mma_gemm<128,128,2,4,EPI_NONE,   2,OUT_PLANES, true >, cudaFuncAttributeMaxDynamicSharedMemorySize, SM_22);
    cudaFuncSetAttribute(mma_gemm<128,128,2,4,EPI_CONNECT,2,OUT_CONNECT,false>, cudaFuncAttributeMaxDynamicSharedMemorySize, SM_22);
    cudaFuncSetAttribute(mma_gemm<128,128,2,4,EPI_NONE,   2,OUT_NONE,   true >, cudaFuncAttributeMaxDynamicSharedMemorySize, SM_22);
    cudaFuncSetAttribute(mma_gemm<128,128,2,4,EPI_NONE,   2,OUT_F32,    false>, cudaFuncAttributeMaxDynamicSharedMemorySize, SM_22);
    cudaFuncSetAttribute(mma_gemm<128,128,2,4,EPI_RESID,  2,OUT_F32,    false>, cudaFuncAttributeMaxDynamicSharedMemorySize, SM_22);
    cudaFuncSetAttribute(mma_gemm<128,128,2,4,EPI_ELU,    1,OUT_PLANES, false>, cudaFuncAttributeMaxDynamicSharedMemorySize, SM_12);
    cudaFuncSetAttribute(mma_gemm<256,64, 4,2,EPI_NONE,   1,OUT_PLANES, false>, cudaFuncAttributeMaxDynamicSharedMemorySize, SM_AV);

    const long zero = 0;

    // prep: weight transposes (planes) + x split
    k_transpose_all<<<1344, dim3(32, 8)>>>(adjW, adjWT2, caWq, caWqT2, caWk, caWkT2,
                                           caWv, caWvT2, caWp, caWpT2, gatW, gatWT2, gatWo, WoT2);
    k_split<<<Bz * ND / 1024, 256>>>(x, x2, PL_BND);

    // selection path
    k_posquery<<<Bz, 256>>>(x, mask, posq);
    k_simvec<<<Bz, 256>>>(simWx, simWq, posq, w);
    k_possim<<<Bz * Nn / 8, 256>>>(x, w, possim_out, sel);

    // fa = x @ adjW  -> planes
    mma_gemm<128,128,2,4,EPI_NONE,2,OUT_PLANES,false><<<dim3(2, 64, 1), 256, SM_22>>>(
        x2, PL_BND, adjWT2, PL_DD, fa2, PL_BND,
        Dd, Dd, Dd, Dd, 1, zero, zero, zero, zero, zero, zero,
        nullptr, zero, nullptr, nullptr, zero, zero, zero, 0);

    // connect (u8) = (fa fa^T > 0) & sel_i & sel_j
    mma_gemm<128,128,2,4,EPI_CONNECT,2,OUT_CONNECT,false><<<dim3(8, 8, Bz), 256, SM_22>>>(
        fa2, PL_BND, fa2, PL_BND, connect, zero,
        Dd, Dd, Dd, Nn, 1, (long)ND, zero, (long)ND, zero, (long)NNt, zero,
        sel, (long)Nn, nullptr, nullptr, zero, zero, zero, 0);

    // Wh = x @ gatW[h] -> planes + transposed planes
    mma_gemm<128,128,2,4,EPI_NONE,2,OUT_PLANES,true><<<dim3(2, 8, Bz * Hh), 256, SM_22>>>(
        x2, PL_BND, gatWT2, PL_GATW, Wh2, PL_BHND,
        Dd, Dd, Dd, Dd, Hh, (long)ND, zero, zero, (long)Dd * Dd,
        (long)Hh * ND, (long)ND,
        nullptr, zero, nullptr, WhT2, PL_BHND, (long)Hh * ND, (long)ND, Nn);

    // s1/s2
    k_dot2p<<<Bz * Hh * Nn / 8, 256>>>(Wh2, PL_BHND, gatA1, gatA2, s1, s2, Hh);

    // GAT softmax -> bf16
    k_softmax_gat<<<dim3(Nn, Bz * Hh), 256>>>(s1, s2, connect, attn_bf, Hh);

    // cat = elu( attn @ Wh )  [A 1-plane probs, B WhT planes]
    mma_gemm<128,128,2,4,EPI_ELU,1,OUT_PLANES,false><<<dim3(2, 8, Bz * Hh), 256, SM_12>>>(
        attn_bf, zero, WhT2, PL_BHND, cat2, PL_CAT,
        Nn, Nn, Nn, HD, Hh, (long)Hh * NNt, (long)NNt, (long)Hh * ND, (long)ND,
        (long)Nn * HD, (long)Dd,
        nullptr, zero, nullptr, nullptr, zero, zero, zero, 0);

    // Who = cat @ gatWo -> planes + transposed planes
    mma_gemm<128,128,2,4,EPI_NONE,2,OUT_PLANES,true><<<dim3(2, 8, Bz), 256, SM_22>>>(
        cat2, PL_CAT, WoT2, PL_WO, Who2, PL_BND,
        HD, HD, HD, Dd, 1, (long)Nn * HD, zero, zero, zero, (long)ND, zero,
        nullptr, zero, nullptr, WhoT2, PL_BND, (long)ND, zero, Nn);

    // so1/so2
    k_dot2p<<<Bz * Nn / 8, 256>>>(Who2, PL_BND, gatAo1, gatAo2, so1, so2, 1);

    // out-layer softmax -> bf16
    k_softmax_gat<<<dim3(Nn, Bz), 256>>>(so1, so2, connect, attno_bf, 1);

    // gout = elu( attn_o @ Who ) -> planes
    mma_gemm<128,128,2,4,EPI_ELU,1,OUT_PLANES,false><<<dim3(2, 8, Bz), 256, SM_12>>>(
        attno_bf, zero, WhoT2, PL_BND, gout2, PL_BND,
        Nn, Nn, Nn, Dd, 1, (long)NNt, zero, (long)ND, zero, (long)ND, zero,
        nullptr, zero, nullptr, nullptr, zero, zero, zero, 0);

    // LayerNorms -> planes
    k_ln<<<Bz * Nn / 8, 256>>>(x, ln3g, ln3b, qx2, PL_BND);
    k_qfull_ln<<<Bz * Nn / 8, 256>>>(gout2, PL_BND, pe, sel, ln4g, ln4b, kv2, PL_BND);

    // q/k projections -> planes; v -> transposed planes only
    mma_gemm<128,128,2,4,EPI_NONE,2,OUT_PLANES,false><<<dim3(2, 64, 1), 256, SM_22>>>(
        qx2, PL_BND, caWqT2, PL_DD, q2, PL_BND,
        Dd, Dd, Dd, Dd, 1, zero, zero, zero, zero, zero, zero,
        nullptr, zero, nullptr, nullptr, zero, zero, zero, 0);
    mma_gemm<128,128,2,4,EPI_NONE,2,OUT_PLANES,false><<<dim3(2, 64, 1), 256, SM_22>>>(
        kv2, PL_BND, caWkT2, PL_DD, k2, PL_BND,
        Dd, Dd, Dd, Dd, 1, zero, zero, zero, zero, zero, zero,
        nullptr, zero, nullptr, nullptr, zero, zero, zero, 0);
    mma_gemm<128,128,2,4,EPI_NONE,2,OUT_NONE,true><<<dim3(2, 8, Bz), 256, SM_22>>>(
        kv2, PL_BND, caWvT2, PL_DD, nullptr, zero,
        Dd, Dd, Dd, Dd, 1, (long)ND, zero, zero, zero, (long)ND, zero,
        nullptr, zero, nullptr, vT2, PL_BND, (long)ND, zero, Nn);

    // CA logits (fp32)
    mma_gemm<128,128,2,4,EPI_NONE,2,OUT_F32,false><<<dim3(8, 8, Bz * HC), 256, SM_22>>>(
        q2, PL_BND, k2, PL_BND, logits, zero,
        DH, Dd, Dd, Nn, HC, (long)ND, (long)DH, (long)ND, (long)DH,
        (long)HC * NNt, (long)NNt,
        nullptr, zero, nullptr, nullptr, zero, zero, zero, 0);

    // CA softmax -> bf16
    k_softmax_ca<<<dim3(Nn, Bz * HC), 256>>>(logits, sel, attn_bf);

    // o = a @ v -> planes  [256x64 tiles]
    mma_gemm<256,64,4,2,EPI_NONE,1,OUT_PLANES,false><<<dim3(1, 4, Bz * HC), 256, SM_AV>>>(
        attn_bf, zero, vT2, PL_BND, o2, PL_BND,
        Nn, Nn, Nn, Dd, HC, (long)HC * NNt, (long)NNt, (long)ND, (long)DH * Nn,
        (long)ND, (long)DH,
        nullptr, zero, nullptr, nullptr, zero, zero, zero, 0);

    // out = x + gamma * (o @ caWp)
    mma_gemm<128,128,2,4,EPI_RESID,2,OUT_F32,false><<<dim3(2, 64, 1), 256, SM_22>>>(
        o2, PL_BND, caWpT2, PL_DD, out, zero,
        Dd, Dd, Dd, Dd, 1, zero, zero, zero, zero, zero, zero,
        x, zero, gamma, nullptr, zero, zero, zero, 0);
}

// round 7
// speedup vs baseline: 1.3253x; 1.2164x over previous
#include <cuda_runtime.h>
#include <cuda_bf16.h>
#include <math.h>
#include <stdint.h>

// Problem constants
#define Bz 8
#define Nn 1024
#define Dd 256
#define Hh 8
#define HC 4
#define DH 64
#define HD 2048                 // Hh*Dd
#define ND (Nn*Dd)              // 262144
#define NNt ((size_t)Nn*Nn)     // 1048576

// ---------------- scratch (device globals) ----------------
__device__ float g_posq[Bz*Dd];
__device__ float g_pqpart[Bz*16*Dd];
__device__ float g_pqcnt[Bz*16];
__device__ float g_qs[Bz*Dd];
__device__ float g_w[Bz*Dd];
__device__ float g_sel[Bz*Nn];
__device__ uint8_t g_connect[(size_t)Bz*Nn*Nn];
__device__ float g_s1[Bz*Hh*Nn];
__device__ float g_s2[Bz*Hh*Nn];
__device__ float g_so1[Bz*Nn];
__device__ float g_so2[Bz*Nn];
__device__ float g_logits[(size_t)Bz*HC*Nn*Nn];            // 128 MB
__device__ __nv_bfloat16 g_attn_bf[(size_t)Bz*Hh*Nn*Nn];   // GAT / CA probs
__device__ __nv_bfloat16 g_attno_bf[(size_t)Bz*Nn*Nn];

__device__ __nv_bfloat16 g_x2[2*(size_t)Bz*ND];
__device__ __nv_bfloat16 g_fa2[2*(size_t)Bz*ND];
__device__ __nv_bfloat16 g_Wh2[2*(size_t)Bz*Hh*ND];
__device__ __nv_bfloat16 g_WhT2[2*(size_t)Bz*Hh*ND];
__device__ __nv_bfloat16 g_cat2[2*(size_t)Bz*Nn*HD];
__device__ __nv_bfloat16 g_Who2[2*(size_t)Bz*ND];
__device__ __nv_bfloat16 g_WhoT2[2*(size_t)Bz*ND];
__device__ __nv_bfloat16 g_gout2[2*(size_t)Bz*ND];
__device__ __nv_bfloat16 g_qx2[2*(size_t)Bz*ND];
__device__ __nv_bfloat16 g_kv2[2*(size_t)Bz*ND];
__device__ __nv_bfloat16 g_q2[2*(size_t)Bz*ND];
__device__ __nv_bfloat16 g_k2[2*(size_t)Bz*ND];
__device__ __nv_bfloat16 g_vT2[2*(size_t)Bz*ND];
__device__ __nv_bfloat16 g_o2[2*(size_t)Bz*ND];
// transposed weights (planes)
__device__ __nv_bfloat16 g_adjWT2[2*Dd*Dd];
__device__ __nv_bfloat16 g_gatWT2[2*Hh*Dd*Dd];
__device__ __nv_bfloat16 g_WoT2[2*HD*Dd];
__device__ __nv_bfloat16 g_caWqT2[2*Dd*Dd];
__device__ __nv_bfloat16 g_caWkT2[2*Dd*Dd];
__device__ __nv_bfloat16 g_caWvT2[2*Dd*Dd];
__device__ __nv_bfloat16 g_caWpT2[2*Dd*Dd];

// ---------------- low-level helpers ----------------
__device__ __forceinline__ uint32_t smem_u32(const void* p) {
    uint32_t a;
    asm("{ .reg .u64 t; cvta.to.shared.u64 t, %1; cvt.u32.u64 %0, t; }" : "=r"(a) : "l"(p));
    return a;
}
__device__ __forceinline__ void ldsm4(uint32_t* r, uint32_t addr) {
    asm volatile("ldmatrix.sync.aligned.m8n8.x4.shared.b16 {%0,%1,%2,%3}, [%4];"
        : "=r"(r[0]), "=r"(r[1]), "=r"(r[2]), "=r"(r[3]) : "r"(addr));
}
__device__ __forceinline__ void mma16816(float* c, const uint32_t* a, const uint32_t* b) {
    asm volatile("mma.sync.aligned.m16n8k16.row.col.f32.bf16.bf16.f32 "
        "{%0,%1,%2,%3}, {%4,%5,%6,%7}, {%8,%9}, {%0,%1,%2,%3};"
        : "+f"(c[0]), "+f"(c[1]), "+f"(c[2]), "+f"(c[3])
        : "r"(a[0]), "r"(a[1]), "r"(a[2]), "r"(a[3]), "r"(b[0]), "r"(b[1]));
}
__device__ __forceinline__ void split1(float v, __nv_bfloat16& h, __nv_bfloat16& l) {
    h = __float2bfloat16(v);
    l = __float2bfloat16(v - __bfloat162float(h));
}
__device__ __forceinline__ uint32_t pack2(__nv_bfloat16 a, __nv_bfloat16 b) {
    return (uint32_t)__bfloat16_as_ushort(a) | ((uint32_t)__bfloat16_as_ushort(b) << 16);
}
#define CP16(dst, src) \
    asm volatile("cp.async.cg.shared.global [%0], [%1], 16;" :: "r"(dst), "l"(src))
#define CP_COMMIT() asm volatile("cp.async.commit_group;" ::: "memory")

// block reduce (8 warps) via shfl + tiny smem; 2 syncs
template <bool MAX>
__device__ __forceinline__ float bred(float v, float* r8, int wid, int lane) {
    #pragma unroll
    for (int o = 16; o; o >>= 1) {
        float u = __shfl_xor_sync(0xffffffffu, v, o);
        v = MAX ? fmaxf(v, u) : (v + u);
    }
    if (lane == 0) r8[wid] = v;
    __syncthreads();
    if (wid == 0) {
        float u = r8[lane & 7];
        #pragma unroll
        for (int o = 4; o; o >>= 1) {
            float t = __shfl_xor_sync(0xffffffffu, u, o);
            u = MAX ? fmaxf(u, t) : (u + t);
        }
        if (lane == 0) r8[0] = u;
    }
    __syncthreads();
    return r8[0];
}

// ---------------- split x into planes ----------------
__global__ void k_split(const float* __restrict__ in, __nv_bfloat16* __restrict__ outp, long plane)
{
    int i = blockIdx.x * 256 + threadIdx.x;
    float4 v = reinterpret_cast<const float4*>(in)[i];
    __nv_bfloat16 h0, l0, h1, l1, h2, l2, h3, l3;
    split1(v.x, h0, l0); split1(v.y, h1, l1); split1(v.z, h2, l2); split1(v.w, h3, l3);
    reinterpret_cast<uint2*>(outp)[i] = make_uint2(pack2(h0, h1), pack2(h2, h3));
    reinterpret_cast<uint2*>(outp + plane)[i] = make_uint2(pack2(l0, l1), pack2(l2, l3));
}

// ---------------- merged transpose kernel (emit planes) ----------------
__global__ void k_transpose_all(const float* adjW, __nv_bfloat16* adjWT,
                                const float* caWq, __nv_bfloat16* caWqT,
                                const float* caWk, __nv_bfloat16* caWkT,
                                const float* caWv, __nv_bfloat16* caWvT,
                                const float* caWp, __nv_bfloat16* caWpT,
                                const float* gatW, __nv_bfloat16* gatWT,
                                const float* gatWo, __nv_bfloat16* WoT)
{
    __shared__ float t[32][33];
    int id = blockIdx.x;
    int tx = threadIdx.x, ty = threadIdx.y;
    const float* src; __nv_bfloat16* dh; long plane; int R, C, bx, by;
    if (id < 320) {
        const float* srcs[5] = {adjW, caWq, caWk, caWv, caWp};
        __nv_bfloat16* dsts[5] = {adjWT, caWqT, caWkT, caWvT, caWpT};
        int m = id >> 6, l = id & 63;
        src = srcs[m]; dh = dsts[m]; plane = Dd * Dd;
        R = Dd; C = Dd; bx = (l & 7) * 32; by = (l >> 3) * 32;
    } else if (id < 832) {
        int l = id - 320; int z = l >> 6; l &= 63;
        src = gatW + (size_t)z * Dd * Dd; dh = gatWT + (size_t)z * Dd * Dd;
        plane = (long)Hh * Dd * Dd;
        R = Dd; C = Dd; bx = (l & 7) * 32; by = (l >> 3) * 32;
    } else {
        int l = id - 832;
        src = gatWo; dh = WoT; plane = (long)HD * Dd;
        R = HD; C = Dd; bx = (l & 7) * 32; by = (l >> 3) * 32;
    }
    #pragma unroll
    for (int i = 0; i < 32; i += 8)
        t[ty + i][tx] = src[(size_t)(by + ty + i) * C + bx + tx];
    __syncthreads();
    #pragma unroll
    for (int i = 0; i < 32; i += 8) {
        float v = t[tx][ty + i];
        __nv_bfloat16 h, l2;
        split1(v, h, l2);
        size_t o = (size_t)(bx + ty + i) * R + by + tx;
        dh[o] = h; dh[plane + o] = l2;
    }
}

// ---------------- plane-pair bf16 mma.sync NT GEMM ----------------
enum { EPI_NONE = 0, EPI_ELU = 1, EPI_CONNECT = 2, EPI_RESID = 3 };
enum { OUT_F32 = 0, OUT_PLANES = 1, OUT_CONNECT = 2, OUT_NONE = 3 };
#define ROWB 80

template <int BM, int BN, int WM, int WN, int EPI, int NA, int OUT, bool DUAL>
__global__ void __launch_bounds__(256, 2)
mma_gemm(const __nv_bfloat16* __restrict__ A, long aPlane,
         const __nv_bfloat16* __restrict__ Bm, long bPlane,
         void* __restrict__ Cv, long cPlane,
         int K, int lda, int ldb, int ldc, int zInner,
         long sAb, long sAi, long sBb, long sBi, long sCb, long sCi,
         const float* __restrict__ e1, long sE1b, const float* __restrict__ e2,
         __nv_bfloat16* __restrict__ Ct, long ctPlane, long sCtb, long sCti, int ldct)
{
    constexpr int ABYTES = BM * ROWB;
    constexpr int BBYTES = BN * ROWB;

    extern __shared__ char smem[];
    const uint32_t sb = smem_u32(smem);

    const int tid = threadIdx.x;
    const int wid = tid >> 5;
    const int lane = tid & 31;

    const int z = blockIdx.z;
    const int zb = z / zInner, zi = z % zInner;
    const __nv_bfloat16* Ap = A + (size_t)zb * sAb + (size_t)zi * sAi;
    const __nv_bfloat16* Bp = Bm + (size_t)zb * sBb + (size_t)zi * sBi;
    float* Cpf = (float*)Cv + (size_t)zb * sCb + (size_t)zi * sCi;
    __nv_bfloat16* Cpb = (__nv_bfloat16*)Cv + (size_t)zb * sCb + (size_t)zi * sCi;
    uint8_t* Cp8 = (uint8_t*)Cv + (size_t)zb * sCb + (size_t)zi * sCi;
    const float* e1p = e1 ? (e1 + (size_t)zb * sE1b) : nullptr;

    const int m0 = blockIdx.y * BM;
    const int n0 = blockIdx.x * BN;

    const int crow = tid >> 2;
    const int cch = tid & 3;

    const int wid_m = wid % WM;
    const int wid_n = wid / WM;
    const int g = lane >> 3, rl = lane & 7;
    const int aRowBase = wid_m * 64 + (g & 1) * 8 + rl;
    const int aKsel = (g >> 1) * 8;
    const int bRowBase = wid_n * 32 + (g >> 1) * 8 + rl;
    const int bKsel = (g & 1) * 8;

    float acc[4][4][4] = {};
    const int nkt = K >> 5;
    const uint32_t bbase = 2 * NA * ABYTES;

    auto copyTile = [&](int kk, int stage) {
        #pragma unroll
        for (int pl = 0; pl < NA; pl++) {
            const __nv_bfloat16* src = Ap + (size_t)pl * aPlane;
            uint32_t dst0 = sb + (stage * NA + pl) * ABYTES;
            #pragma unroll
            for (int i = 0; i < BM / 64; i++) {
                int row = crow + 64 * i;
                CP16(dst0 + row * ROWB + cch * 16,
                     src + (size_t)(m0 + row) * lda + kk + cch * 8);
            }
        }
        #pragma unroll
        for (int pl = 0; pl < 2; pl++) {
            const __nv_bfloat16* src = Bp + (size_t)pl * bPlane;
            uint32_t dst0 = sb + bbase + (stage * 2 + pl) * BBYTES;
            #pragma unroll
            for (int i = 0; i < BN / 64; i++) {
                int row = crow + 64 * i;
                CP16(dst0 + row * ROWB + cch * 16,
                     src + (size_t)(n0 + row) * ldb + kk + cch * 8);
            }
        }
    };

    copyTile(0, 0); CP_COMMIT();

    for (int kt = 0; kt < nkt; kt++) {
        const int stage = kt & 1;
        const bool more = (kt + 1 < nkt);
        if (more) { copyTile((kt + 1) << 5, stage ^ 1); CP_COMMIT(); }
        if (more) asm volatile("cp.async.wait_group 1;" ::: "memory");
        else      asm volatile("cp.async.wait_group 0;" ::: "memory");
        __syncthreads();

        const uint32_t sAhi = sb + stage * NA * ABYTES;
        const uint32_t sAlo = sAhi + ABYTES;
        const uint32_t sBhi = sb + bbase + stage * 2 * BBYTES;
        const uint32_t sBlo = sBhi + BBYTES;

        #pragma unroll
        for (int j = 0; j < 2; j++) {
            const int kb = j * 16;
            uint32_t a[4][4], bh[4][2], bl[4][2];
            #pragma unroll
            for (int im = 0; im < 4; im++)
                ldsm4(a[im], sAhi + (uint32_t)((aRowBase + im * 16) * ROWB + (kb + aKsel) * 2));
            #pragma unroll
            for (int i2 = 0; i2 < 2; i2++) {
                uint32_t t[4];
                ldsm4(t, sBhi + (uint32_t)((bRowBase + i2 * 16) * ROWB + (kb + bKsel) * 2));
                bh[2 * i2][0] = t[0]; bh[2 * i2][1] = t[1];
                bh[2 * i2 + 1][0] = t[2]; bh[2 * i2 + 1][1] = t[3];
            }
            #pragma unroll
            for (int im = 0; im < 4; im++)
                #pragma unroll
                for (int in = 0; in < 4; in++)
                    mma16816(acc[im][in], a[im], bh[in]);           // Ah*Bh
            #pragma unroll
            for (int i2 = 0; i2 < 2; i2++) {
                uint32_t t[4];
                ldsm4(t, sBlo + (uint32_t)((bRowBase + i2 * 16) * ROWB + (kb + bKsel) * 2));
                bl[2 * i2][0] = t[0]; bl[2 * i2][1] = t[1];
                bl[2 * i2 + 1][0] = t[2]; bl[2 * i2 + 1][1] = t[3];
            }
            #pragma unroll
            for (int im = 0; im < 4; im++)
                #pragma unroll
                for (int in = 0; in < 4; in++)
                    mma16816(acc[im][in], a[im], bl[in]);           // Ah*Bl
            if (NA == 2) {
                #pragma unroll
                for (int im = 0; im < 4; im++)
                    ldsm4(a[im], sAlo + (uint32_t)((aRowBase + im * 16) * ROWB + (kb + aKsel) * 2));
                #pragma unroll
                for (int im = 0; im < 4; im++)
                    #pragma unroll
                    for (int in = 0; in < 4; in++)
                        mma16816(acc[im][in], a[im], bh[in]);       // Al*Bh
            }
        }
        __syncthreads();
    }

    // epilogue
    const int mw = m0 + wid_m * 64;
    const int nw = n0 + wid_n * 32;
    #pragma unroll
    for (int im = 0; im < 4; im++) {
        const int row = mw + im * 16 + (lane >> 2);
        const float sr0 = (EPI == EPI_CONNECT) ? e1p[row] : 0.f;
        const float sr1 = (EPI == EPI_CONNECT) ? e1p[row + 8] : 0.f;
        #pragma unroll
        for (int in = 0; in < 4; in++) {
            const int col = nw + in * 8 + (lane & 3) * 2;
            float v00 = acc[im][in][0], v01 = acc[im][in][1];
            float v10 = acc[im][in][2], v11 = acc[im][in][3];
            if (EPI == EPI_ELU) {
                v00 = v00 > 0.f ? v00 : expm1f(v00);
                v01 = v01 > 0.f ? v01 : expm1f(v01);
                v10 = v10 > 0.f ? v10 : expm1f(v10);
                v11 = v11 > 0.f ? v11 : expm1f(v11);
            } else if (EPI == EPI_RESID) {
                const float g0 = e2[col], g1 = e2[col + 1];
                const size_t r0 = (size_t)row * ldc + col;
                const size_t r1 = (size_t)(row + 8) * ldc + col;
                v00 = e1p[r0] + g0 * v00; v01 = e1p[r0 + 1] + g1 * v01;
                v10 = e1p[r1] + g0 * v10; v11 = e1p[r1 + 1] + g1 * v11;
            }
            const size_t o0 = (size_t)row * ldc + col;
            const size_t o1 = (size_t)(row + 8) * ldc + col;
            if (OUT == OUT_CONNECT) {
                const float sc0 = e1p[col], sc1 = e1p[col + 1];
                uchar2 c0, c1;
                c0.x = (v00 > 0.f && sr0 > 0.5f && sc0 > 0.5f) ? 1 : 0;
                c0.y = (v01 > 0.f && sr0 > 0.5f && sc1 > 0.5f) ? 1 : 0;
                c1.x = (v10 > 0.f && sr1 > 0.5f && sc0 > 0.5f) ? 1 : 0;
                c1.y = (v11 > 0.f && sr1 > 0.5f && sc1 > 0.5f) ? 1 : 0;
                *reinterpret_cast<uchar2*>(Cp8 + o0) = c0;
                *reinterpret_cast<uchar2*>(Cp8 + o1) = c1;
            } else if (OUT == OUT_F32) {
                *reinterpret_cast<float2*>(Cpf + o0) = make_float2(v00, v01);
                *reinterpret_cast<float2*>(Cpf + o1) = make_float2(v10, v11);
            }
            __nv_bfloat16 h00, l00, h01, l01, h10, l10, h11, l11;
            if (OUT == OUT_PLANES || DUAL) {
                split1(v00, h00, l00); split1(v01, h01, l01);
                split1(v10, h10, l10); split1(v11, h11, l11);
            }
            if (OUT == OUT_PLANES) {
                *reinterpret_cast<uint32_t*>(Cpb + o0) = pack2(h00, h01);
                *reinterpret_cast<uint32_t*>(Cpb + o1) = pack2(h10, h11);
                *reinterpret_cast<uint32_t*>(Cpb + cPlane + o0) = pack2(l00, l01);
                *reinterpret_cast<uint32_t*>(Cpb + cPlane + o1) = pack2(l10, l11);
            }
            if (DUAL) {
                __nv_bfloat16* Ctp = Ct + (size_t)zb * sCtb + (size_t)zi * sCti;
                const size_t t0 = (size_t)col * ldct + row;
                const size_t t1 = (size_t)(col + 1) * ldct + row;
                Ctp[t0] = h00; Ctp[t0 + 8] = h10;
                Ctp[t1] = h01; Ctp[t1 + 8] = h11;
                Ctp[ctPlane + t0] = l00; Ctp[ctPlane + t0 + 8] = l10;
                Ctp[ctPlane + t1] = l01; Ctp[ctPlane + t1 + 8] = l11;
            }
        }
    }
}

// ---------------- auxiliary kernels ----------------
// posquery stage 1: partial masked sums over 64-row segments
__global__ void k_posquery1(const float* __restrict__ x, const int* __restrict__ mask,
                            float* __restrict__ part, float* __restrict__ cntp)
{
    int seg = blockIdx.x, b = blockIdx.y, d = threadIdx.x;
    int n0 = seg * 64;
    float s = 0.f, cnt = 0.f;
    for (int n = n0; n < n0 + 64; n++) {
        if (mask[b * Nn + n] == 1) { s += x[((size_t)b * Nn + n) * Dd + d]; cnt += 1.f; }
    }
    part[((size_t)b * 16 + seg) * Dd + d] = s;
    if (d == 0) cntp[b * 16 + seg] = cnt;
}
// posquery stage 2: reduce 16 segments
__global__ void k_posquery2(const float* __restrict__ part, const float* __restrict__ cntp,
                            float* __restrict__ pq)
{
    int b = blockIdx.x, d = threadIdx.x;
    float s = 0.f, cnt = 0.f;
    #pragma unroll
    for (int seg = 0; seg < 16; seg++) {
        s += part[((size_t)b * 16 + seg) * Dd + d];
        cnt += cntp[b * 16 + seg];
    }
    pq[b * Dd + d] = s / fmaxf(cnt, 1.f);
}

// qs = Wq^T @ pq  (block per 32 outputs; 8 k-segments reduced in smem)
__global__ void k_mv1(const float* __restrict__ Wq, const float* __restrict__ pq,
                      float* __restrict__ qs)
{
    __shared__ float spq[Dd];
    __shared__ float red[8][32];
    int b = blockIdx.y, t0 = blockIdx.x * 32;
    int tid = threadIdx.x;
    spq[tid] = pq[b * Dd + tid];
    __syncthreads();
    int tseg = tid >> 5, tl = tid & 31;
    float s = 0.f;
    #pragma unroll
    for (int i = 0; i < 32; i++)
        s += spq[tseg * 32 + i] * Wq[(tseg * 32 + i) * Dd + t0 + tl];
    red[tseg][tl] = s;
    __syncthreads();
    if (tseg == 0) {
        float a = 0.f;
        #pragma unroll
        for (int k = 0; k < 8; k++) a += red[k][tl];
        qs[b * Dd + t0 + tl] = a;
    }
}
// w = Wx @ qs  (warp per output row, coalesced)
__global__ void k_mv2(const float* __restrict__ Wx, const float* __restrict__ qs,
                      float* __restrict__ w)
{
    int b = blockIdx.y;
    int wid = threadIdx.x >> 5, lane = threadIdx.x & 31;
    int t = blockIdx.x * 8 + wid;
    float s = 0.f;
    #pragma unroll
    for (int k = 0; k < 8; k++)
        s += Wx[(size_t)t * Dd + lane + 32 * k] * qs[b * Dd + lane + 32 * k];
    #pragma unroll
    for (int o = 16; o; o >>= 1) s += __shfl_xor_sync(0xffffffffu, s, o);
    if (lane == 0) w[b * Dd + t] = s;
}

__global__ void k_possim(const float* __restrict__ x, const float* __restrict__ w,
                         float* __restrict__ possim_out, float* __restrict__ sel)
{
    int row = blockIdx.x * 8 + (threadIdx.x >> 5);
    int lane = threadIdx.x & 31;
    int b = row / Nn;
    const float4* xr = reinterpret_cast<const float4*>(x + (size_t)row * Dd);
    const float4* wr = reinterpret_cast<const float4*>(w + b * Dd);
    float s = 0.f;
    #pragma unroll
    for (int e = 0; e < 2; e++) {
        float4 xv = xr[lane + e * 32];
        float4 wv = wr[lane + e * 32];
        s += xv.x * wv.x + xv.y * wv.y + xv.z * wv.z + xv.w * wv.w;
    }
    #pragma unroll
    for (int o = 16; o; o >>= 1) s += __shfl_xor_sync(0xffffffffu, s, o);
    if (lane == 0) {
        float p = 1.f / (1.f + expf(-s * 0.0625f));
        possim_out[row] = p;
        sel[row] = (p > 0.97f) ? 1.f : 0.f;
    }
}

// dot of plane-pair rows with a1/a2
__global__ void k_dot2p(const __nv_bfloat16* __restrict__ rows, long plane,
                        const float* __restrict__ a1, const float* __restrict__ a2,
                        float* __restrict__ s1, float* __restrict__ s2, int nheads)
{
    int row = blockIdx.x * 8 + (threadIdx.x >> 5);
    int lane = threadIdx.x & 31;
    int head = (row / Nn) % nheads;
    const __nv_bfloat16* rp = rows + (size_t)row * Dd;
    const float* a1p = a1 + head * Dd;
    const float* a2p = a2 + head * Dd;
    float u = 0.f, v = 0.f;
    for (int e = lane; e < Dd; e += 32) {
        float rv = __bfloat162float(rp[e]) + __bfloat162float(rp[plane + e]);
        u += rv * a1p[e];
        v += rv * a2p[e];
    }
    #pragma unroll
    for (int o = 16; o; o >>= 1) {
        u += __shfl_xor_sync(0xffffffffu, u, o);
        v += __shfl_xor_sync(0xffffffffu, v, o);
    }
    if (lane == 0) { s1[row] = u; s2[row] = v; }
}

// GAT masked softmax, 4 rows per block, s2 staged in smem
__global__ void k_softmax_gat(const float* __restrict__ s1, const float* __restrict__ s2,
                              const uint8_t* __restrict__ connect, __nv_bfloat16* __restrict__ attn,
                              int nheads)
{
    __shared__ float s2row[Nn];
    __shared__ float r8[8];
    int z = blockIdx.y;
    int b = z / nheads;
    int t = threadIdx.x;
    int wid = t >> 5, lane = t & 31;
    #pragma unroll
    for (int k = 0; k < 4; k++) s2row[t + k * 256] = s2[(size_t)z * Nn + t + k * 256];
    __syncthreads();
    #pragma unroll
    for (int r = 0; r < 4; r++) {
        int i = blockIdx.x * 4 + r;
        const uint8_t* con = connect + (size_t)b * NNt + (size_t)i * Nn;
        float s1v = s1[(size_t)z * Nn + i];
        float v[4];
        float mx = -INFINITY;
        #pragma unroll
        for (int k = 0; k < 4; k++) {
            int j = t + k * 256;
            float e = s1v + s2row[j];
            e = (e >= 0.f) ? e : 0.2f * e;
            v[k] = con[j] ? e : -9.0e15f;
            mx = fmaxf(mx, v[k]);
        }
        mx = bred<true>(mx, r8, wid, lane);
        float sum = 0.f;
        #pragma unroll
        for (int k = 0; k < 4; k++) { v[k] = expf(v[k] - mx); sum += v[k]; }
        sum = bred<false>(sum, r8, wid, lane);
        float inv = 1.f / sum;
        __nv_bfloat16* out = attn + (size_t)z * NNt + (size_t)i * Nn;
        #pragma unroll
        for (int k = 0; k < 4; k++) out[t + k * 256] = __float2bfloat16(v[k] * inv);
        __syncthreads();
    }
}

__global__ void k_softmax_ca(const float* __restrict__ logits, const float* __restrict__ sel,
                             __nv_bfloat16* __restrict__ attn)
{
    __shared__ float r8[8];
    int i = blockIdx.x;
    int z = blockIdx.y;
    int b = z / HC;
    const float* row = logits + (size_t)z * NNt + (size_t)i * Nn;
    const float* sp = sel + b * Nn;
    int t = threadIdx.x;
    int wid = t >> 5, lane = t & 31;
    float v[4];
    float mx = -INFINITY;
    #pragma unroll
    for (int k = 0; k < 4; k++) {
        int j = t + k * 256;
        v[k] = (sp[j] > 0.5f) ? row[j] * 0.125f : -1.0e9f;
        mx = fmaxf(mx, v[k]);
    }
    mx = bred<true>(mx, r8, wid, lane);
    float sum = 0.f;
    #pragma unroll
    for (int k = 0; k < 4; k++) { v[k] = expf(v[k] - mx); sum += v[k]; }
    sum = bred<false>(sum, r8, wid, lane);
    float inv = 1.f / sum;
    __nv_bfloat16* out = attn + (size_t)z * NNt + (size_t)i * Nn;
    #pragma unroll
    for (int k = 0; k < 4; k++) out[t + k * 256] = __float2bfloat16(v[k] * inv);
}

// LayerNorm: fp32 in -> plane-pair out
__global__ void k_ln(const float* __restrict__ in, const float* __restrict__ g,
                     const float* __restrict__ bb, __nv_bfloat16* __restrict__ out, long oplane)
{
    int row = blockIdx.x * 8 + (threadIdx.x >> 5);
    int lane = threadIdx.x & 31;
    size_t base = (size_t)row * Dd;
    float vbuf[8];
    float s = 0.f, sq = 0.f;
    #pragma unroll
    for (int k = 0; k < 8; k++) {
        float x = in[base + lane + k * 32];
        vbuf[k] = x; s += x; sq += x * x;
    }
    #pragma unroll
    for (int o = 16; o; o >>= 1) {
        s += __shfl_xor_sync(0xffffffffu, s, o);
        sq += __shfl_xor_sync(0xffffffffu, sq, o);
    }
    float mean = s * (1.f / Dd);
    float var = sq * (1.f / Dd) - mean * mean;
    float rstd = rsqrtf(var + 1e-5f);
    #pragma unroll
    for (int k = 0; k < 8; k++) {
        int d = lane + k * 32;
        float y = (vbuf[k] - mean) * rstd * g[d] + bb[d];
        __nv_bfloat16 h, l; split1(y, h, l);
        out[base + d] = h; out[oplane + base + d] = l;
    }
}

// kv = LN4( sel ? gout + pos_emb : 0 ); gout is plane-pair
__global__ void k_qfull_ln(const __nv_bfloat16* __restrict__ gout, long gplane,
                           const float* __restrict__ pe,
                           const float* __restrict__ sel, const float* __restrict__ g,
                           const float* __restrict__ bb, __nv_bfloat16* __restrict__ out, long oplane)
{
    int row = blockIdx.x * 8 + (threadIdx.x >> 5);
    int lane = threadIdx.x & 31;
    int n = row % Nn;
    size_t base = (size_t)row * Dd;
    float selv = sel[row];
    float vbuf[8];
    float s = 0.f, sq = 0.f;
    #pragma unroll
    for (int k = 0; k < 8; k++) {
        int d = lane + k * 32;
        float gv = __bfloat162float(gout[base + d]) + __bfloat162float(gout[gplane + base + d]);
        float x = (selv > 0.5f) ? (gv + pe[(size_t)n * Dd + d]) : 0.f;
        vbuf[k] = x; s += x; sq += x * x;
    }
    #pragma unroll
    for (int o = 16; o; o >>= 1) {
        s += __shfl_xor_sync(0xffffffffu, s, o);
        sq += __shfl_xor_sync(0xffffffffu, sq, o);
    }
    float mean = s * (1.f / Dd);
    float var = sq * (1.f / Dd) - mean * mean;
    float rstd = rsqrtf(var + 1e-5f);
    #pragma unroll
    for (int k = 0; k < 8; k++) {
        int d = lane + k * 32;
        float y = (vbuf[k] - mean) * rstd * g[d] + bb[d];
        __nv_bfloat16 h, l; split1(y, h, l);
        out[base + d] = h; out[oplane + base + d] = l;
    }
}

// ---------------- launch ----------------
#define GETSYM(p, T, s) do { void* _t; cudaGetSymbolAddress(&_t, s); p = (T*)_t; } while (0)
#define SMEMSZ(BM, BN, NA) ((2 * (NA) * (BM) + 4 * (BN)) * ROWB)

extern "C" void kernel_launch(void* const* d_in, const int* in_sizes, int n_in,
                              void* d_out, int out_size)
{
    const float* x      = (const float*)d_in[0];
    const int*   mask   = (const int*)  d_in[1];
    const float* pe     = (const float*)d_in[2];
    const float* simWx  = (const float*)d_in[3];
    const float* simWq  = (const float*)d_in[4];
    const float* adjW   = (const float*)d_in[5];
    const float* gatW   = (const float*)d_in[6];
    const float* gatA1  = (const float*)d_in[7];
    const float* gatA2  = (const float*)d_in[8];
    const float* gatWo  = (const float*)d_in[9];
    const float* gatAo1 = (const float*)d_in[10];
    const float* gatAo2 = (const float*)d_in[11];
    const float* ln3g   = (const float*)d_in[12];
    const float* ln3b   = (const float*)d_in[13];
    const float* ln4g   = (const float*)d_in[14];
    const float* ln4b   = (const float*)d_in[15];
    const float* caWq   = (const float*)d_in[16];
    const float* caWk   = (const float*)d_in[17];
    const float* caWv   = (const float*)d_in[18];
    const float* caWp   = (const float*)d_in[19];
    const float* gamma  = (const float*)d_in[20];
    (void)in_sizes; (void)n_in; (void)out_size;

    float* out = (float*)d_out;
    float* possim_out = out + (size_t)Bz * Nn * Dd;

    float *posq, *pqpart, *pqcnt, *qsv, *w, *sel, *s1, *s2, *so1, *so2, *logits;
    uint8_t* connect;
    __nv_bfloat16 *attn_bf, *attno_bf;
    __nv_bfloat16 *x2, *fa2, *Wh2, *WhT2, *cat2, *Who2, *WhoT2, *gout2, *qx2, *kv2;
    __nv_bfloat16 *q2, *k2, *vT2, *o2;
    __nv_bfloat16 *adjWT2, *gatWT2, *WoT2, *caWqT2, *caWkT2, *caWvT2, *caWpT2;
    GETSYM(posq, float, g_posq);   GETSYM(pqpart, float, g_pqpart); GETSYM(pqcnt, float, g_pqcnt);
    GETSYM(qsv, float, g_qs);      GETSYM(w, float, g_w);       GETSYM(sel, float, g_sel);
    GETSYM(connect, uint8_t, g_connect);
    GETSYM(s1, float, g_s1);       GETSYM(s2, float, g_s2);
    GETSYM(so1, float, g_so1);     GETSYM(so2, float, g_so2);
    GETSYM(logits, float, g_logits);
    GETSYM(attn_bf, __nv_bfloat16, g_attn_bf);
    GETSYM(attno_bf, __nv_bfloat16, g_attno_bf);
    GETSYM(x2, __nv_bfloat16, g_x2);     GETSYM(fa2, __nv_bfloat16, g_fa2);
    GETSYM(Wh2, __nv_bfloat16, g_Wh2);   GETSYM(WhT2, __nv_bfloat16, g_WhT2);
    GETSYM(cat2, __nv_bfloat16, g_cat2);
    GETSYM(Who2, __nv_bfloat16, g_Who2); GETSYM(WhoT2, __nv_bfloat16, g_WhoT2);
    GETSYM(gout2, __nv_bfloat16, g_gout2);
    GETSYM(qx2, __nv_bfloat16, g_qx2);   GETSYM(kv2, __nv_bfloat16, g_kv2);
    GETSYM(q2, __nv_bfloat16, g_q2);     GETSYM(k2, __nv_bfloat16, g_k2);
    GETSYM(vT2, __nv_bfloat16, g_vT2);   GETSYM(o2, __nv_bfloat16, g_o2);
    GETSYM(adjWT2, __nv_bfloat16, g_adjWT2); GETSYM(gatWT2, __nv_bfloat16, g_gatWT2);
    GETSYM(WoT2, __nv_bfloat16, g_WoT2);
    GETSYM(caWqT2, __nv_bfloat16, g_caWqT2); GETSYM(caWkT2, __nv_bfloat16, g_caWkT2);
    GETSYM(caWvT2, __nv_bfloat16, g_caWvT2); GETSYM(caWpT2, __nv_bfloat16, g_caWpT2);

    const long PL_BND  = (long)Bz * ND;
    const long PL_BHND = (long)Bz * Hh * ND;
    const long PL_CAT  = (long)Bz * Nn * HD;
    const long PL_DD   = (long)Dd * Dd;
    const long PL_GATW = (long)Hh * Dd * Dd;
    const long PL_WO   = (long)HD * Dd;

    const int SM_22 = SMEMSZ(128, 128, 2);
    const int SM_12 = SMEMSZ(128, 128, 1);
    const int SM_AV = SMEMSZ(256, 64, 1);
    cudaFuncSetAttribute(mma_gemm<128,128,2,4,EPI_NONE,   2,OUT_PLANES, false>, cudaFuncAttributeMaxDynamicSharedMemorySize, SM_22);
    cudaFuncSetAttribute(mma_gemm<128,128,2,4,EPI_NONE,   2,OUT_PLANES, true >, cudaFuncAttributeMaxDynamicSharedMemorySize, SM_22);
    cudaFuncSetAttribute(mma_gemm<128,128,2,4,EPI_CONNECT,2,OUT_CONNECT,false>, cudaFuncAttributeMaxDynamicSharedMemorySize, SM_22);
    cudaFuncSetAttribute(mma_gemm<128,128,2,4,EPI_NONE,   2,OUT_NONE,   true >, cudaFuncAttributeMaxDynamicSharedMemorySize, SM_22);
    cudaFuncSetAttribute(mma_gemm<128,128,2,4,EPI_NONE,   2,OUT_F32,    false>, cudaFuncAttributeMaxDynamicSharedMemorySize, SM_22);
    cudaFuncSetAttribute(mma_gemm<128,128,2,4,EPI_RESID,  2,OUT_F32,    false>, cudaFuncAttributeMaxDynamicSharedMemorySize, SM_22);
    cudaFuncSetAttribute(mma_gemm<128,128,2,4,EPI_ELU,    1,OUT_PLANES, false>, cudaFuncAttributeMaxDynamicSharedMemorySize, SM_12);
    cudaFuncSetAttribute(mma_gemm<256,64, 4,2,EPI_NONE,   1,OUT_PLANES, false>, cudaFuncAttributeMaxDynamicSharedMemorySize, SM_AV);

    const long zero = 0;

    // prep
    k_transpose_all<<<1344, dim3(32, 8)>>>(adjW, adjWT2, caWq, caWqT2, caWk, caWkT2,
                                           caWv, caWvT2, caWp, caWpT2, gatW, gatWT2, gatWo, WoT2);
    k_split<<<Bz * ND / 1024, 256>>>(x, x2, PL_BND);

    // selection path (parallelized)
    k_posquery1<<<dim3(16, Bz), 256>>>(x, mask, pqpart, pqcnt);
    k_posquery2<<<Bz, 256>>>(pqpart, pqcnt, posq);
    k_mv1<<<dim3(8, Bz), 256>>>(simWq, posq, qsv);
    k_mv2<<<dim3(32, Bz), 256>>>(simWx, qsv, w);
    k_possim<<<Bz * Nn / 8, 256>>>(x, w, possim_out, sel);

    // fa = x @ adjW -> planes
    mma_gemm<128,128,2,4,EPI_NONE,2,OUT_PLANES,false><<<dim3(2, 64, 1), 256, SM_22>>>(
        x2, PL_BND, adjWT2, PL_DD, fa2, PL_BND,
        Dd, Dd, Dd, Dd, 1, zero, zero, zero, zero, zero, zero,
        nullptr, zero, nullptr, nullptr, zero, zero, zero, 0);

    // connect (u8)
    mma_gemm<128,128,2,4,EPI_CONNECT,2,OUT_CONNECT,false><<<dim3(8, 8, Bz), 256, SM_22>>>(
        fa2, PL_BND, fa2, PL_BND, connect, zero,
        Dd, Dd, Dd, Nn, 1, (long)ND, zero, (long)ND, zero, (long)NNt, zero,
        sel, (long)Nn, nullptr, nullptr, zero, zero, zero, 0);

    // Wh = x @ gatW[h]
    mma_gemm<128,128,2,4,EPI_NONE,2,OUT_PLANES,true><<<dim3(2, 8, Bz * Hh), 256, SM_22>>>(
        x2, PL_BND, gatWT2, PL_GATW, Wh2, PL_BHND,
        Dd, Dd, Dd, Dd, Hh, (long)ND, zero, zero, (long)Dd * Dd,
        (long)Hh * ND, (long)ND,
        nullptr, zero, nullptr, WhT2, PL_BHND, (long)Hh * ND, (long)ND, Nn);

    // s1/s2
    k_dot2p<<<Bz * Hh * Nn / 8, 256>>>(Wh2, PL_BHND, gatA1, gatA2, s1, s2, Hh);

    // GAT softmax -> bf16 (4 rows/block)
    k_softmax_gat<<<dim3(Nn / 4, Bz * Hh), 256>>>(s1, s2, connect, attn_bf, Hh);

    // cat = elu( attn @ Wh )
    mma_gemm<128,128,2,4,EPI_ELU,1,OUT_PLANES,false><<<dim3(2, 8, Bz * Hh), 256, SM_12>>>(
        attn_bf, zero, WhT2, PL_BHND, cat2, PL_CAT,
        Nn, Nn, Nn, HD, Hh, (long)Hh * NNt, (long)NNt, (long)Hh * ND, (long)ND,
        (long)Nn * HD, (long)Dd,
        nullptr, zero, nullptr, nullptr, zero, zero, zero, 0);

    // Who = cat @ gatWo
    mma_gemm<128,128,2,4,EPI_NONE,2,OUT_PLANES,true><<<dim3(2, 8, Bz), 256, SM_22>>>(
        cat2, PL_CAT, WoT2, PL_WO, Who2, PL_BND,
        HD, HD, HD, Dd, 1, (long)Nn * HD, zero, zero, zero, (long)ND, zero,
        nullptr, zero, nullptr, WhoT2, PL_BND, (long)ND, zero, Nn);

    // so1/so2
    k_dot2p<<<Bz * Nn / 8, 256>>>(Who2, PL_BND, gatAo1, gatAo2, so1, so2, 1);

    // out-layer softmax
    k_softmax_gat<<<dim3(Nn / 4, Bz), 256>>>(so1, so2, connect, attno_bf, 1);

    // gout = elu( attn_o @ Who )
    mma_gemm<128,128,2,4,EPI_ELU,1,OUT_PLANES,false><<<dim3(2, 8, Bz), 256, SM_12>>>(
        attno_bf, zero, WhoT2, PL_BND, gout2, PL_BND,
        Nn, Nn, Nn, Dd, 1, (long)NNt, zero, (long)ND, zero, (long)ND, zero,
        nullptr, zero, nullptr, nullptr, zero, zero, zero, 0);

    // LayerNorms -> planes
    k_ln<<<Bz * Nn / 8, 256>>>(x, ln3g, ln3b, qx2, PL_BND);
    k_qfull_ln<<<Bz * Nn / 8, 256>>>(gout2, PL_BND, pe, sel, ln4g, ln4b, kv2, PL_BND);

    // q/k projections; v -> transposed planes only
    mma_gemm<128,128,2,4,EPI_NONE,2,OUT_PLANES,false><<<dim3(2, 64, 1), 256, SM_22>>>(
        qx2, PL_BND, caWqT2, PL_DD, q2, PL_BND,
        Dd, Dd, Dd, Dd, 1, zero, zero, zero, zero, zero, zero,
        nullptr, zero, nullptr, nullptr, zero, zero, zero, 0);
    mma_gemm<128,128,2,4,EPI_NONE,2,OUT_PLANES,false><<<dim3(2, 64, 1), 256, SM_22>>>(
        kv2, PL_BND, caWkT2, PL_DD, k2, PL_BND,
        Dd, Dd, Dd, Dd, 1, zero, zero, zero, zero, zero, zero,
        nullptr, zero, nullptr, nullptr, zero, zero, zero, 0);
    mma_gemm<128,128,2,4,EPI_NONE,2,OUT_NONE,true><<<dim3(2, 8, Bz), 256, SM_22>>>(
        kv2, PL_BND, caWvT2, PL_DD, nullptr, zero,
        Dd, Dd, Dd, Dd, 1, (long)ND, zero, zero, zero, (long)ND, zero,
        nullptr, zero, nullptr, vT2, PL_BND, (long)ND, zero, Nn);

    // CA logits (fp32)
    mma_gemm<128,128,2,4,EPI_NONE,2,OUT_F32,false><<<dim3(8, 8, Bz * HC), 256, SM_22>>>(
        q2, PL_BND, k2, PL_BND, logits, zero,
        DH, Dd, Dd, Nn, HC, (long)ND, (long)DH, (long)ND, (long)DH,
        (long)HC * NNt, (long)NNt,
        nullptr, zero, nullptr, nullptr, zero, zero, zero, 0);

    // CA softmax -> bf16
    k_softmax_ca<<<dim3(Nn, Bz * HC), 256>>>(logits, sel, attn_bf);

    // o = a @ v -> planes
    mma_gemm<256,64,4,2,EPI_NONE,1,OUT_PLANES,false><<<dim3(1, 4, Bz * HC), 256, SM_AV>>>(
        attn_bf, zero, vT2, PL_BND, o2, PL_BND,
        Nn, Nn, Nn, Dd, HC, (long)HC * NNt, (long)NNt, (long)ND, (long)DH * Nn,
        (long)ND, (long)DH,
        nullptr, zero, nullptr, nullptr, zero, zero, zero, 0);

    // out = x + gamma * (o @ caWp)
    mma_gemm<128,128,2,4,EPI_RESID,2,OUT_F32,false><<<dim3(2, 64, 1), 256, SM_22>>>(
        o2, PL_BND, caWpT2, PL_DD, out, zero,
        Dd, Dd, Dd, Dd, 1, zero, zero, zero, zero, zero, zero,
        x, zero, gamma, nullptr, zero, zero, zero, 0);
}

// round 8
// speedup vs baseline: 1.3333x; 1.0060x over previous
#include <cuda_runtime.h>
#include <cuda_bf16.h>
#include <math.h>
#include <stdint.h>

// Problem constants
#define Bz 8
#define Nn 1024
#define Dd 256
#define Hh 8
#define HC 4
#define DH 64
#define HD 2048                 // Hh*Dd
#define ND (Nn*Dd)              // 262144
#define NNt ((size_t)Nn*Nn)     // 1048576

// ---------------- scratch (device globals) ----------------
__device__ float g_posq[Bz*Dd];
__device__ float g_pqpart[Bz*16*Dd];
__device__ float g_pqcnt[Bz*16];
__device__ float g_qs[Bz*Dd];
__device__ float g_w[Bz*Dd];
__device__ float g_sel[Bz*Nn];
__device__ uint8_t g_connect[(size_t)Bz*Nn*Nn];
__device__ float g_s1[Bz*Hh*Nn];
__device__ float g_s2[Bz*Hh*Nn];
__device__ float g_so1[Bz*Nn];
__device__ float g_so2[Bz*Nn];
__device__ float g_logits[(size_t)Bz*HC*Nn*Nn];            // 128 MB
__device__ __nv_bfloat16 g_attn_bf[(size_t)Bz*Hh*Nn*Nn];   // GAT / CA probs
__device__ __nv_bfloat16 g_attno_bf[(size_t)Bz*Nn*Nn];

__device__ __nv_bfloat16 g_x2[2*(size_t)Bz*ND];
__device__ __nv_bfloat16 g_fa2[2*(size_t)Bz*ND];
__device__ __nv_bfloat16 g_Wh2[2*(size_t)Bz*Hh*ND];
__device__ __nv_bfloat16 g_WhT2[2*(size_t)Bz*Hh*ND];
__device__ __nv_bfloat16 g_cat2[2*(size_t)Bz*Nn*HD];
__device__ __nv_bfloat16 g_Who2[2*(size_t)Bz*ND];
__device__ __nv_bfloat16 g_WhoT2[2*(size_t)Bz*ND];
__device__ __nv_bfloat16 g_gout2[2*(size_t)Bz*ND];
__device__ __nv_bfloat16 g_qx2[2*(size_t)Bz*ND];
__device__ __nv_bfloat16 g_kv2[2*(size_t)Bz*ND];
__device__ __nv_bfloat16 g_q2[2*(size_t)Bz*ND];
__device__ __nv_bfloat16 g_k2[2*(size_t)Bz*ND];
__device__ __nv_bfloat16 g_vT2[2*(size_t)Bz*ND];
__device__ __nv_bfloat16 g_o2[2*(size_t)Bz*ND];
// transposed weights (planes)
__device__ __nv_bfloat16 g_adjWT2[2*Dd*Dd];
__device__ __nv_bfloat16 g_gatWT2[2*Hh*Dd*Dd];
__device__ __nv_bfloat16 g_WoT2[2*HD*Dd];
__device__ __nv_bfloat16 g_caWqT2[2*Dd*Dd];
__device__ __nv_bfloat16 g_caWkT2[2*Dd*Dd];
__device__ __nv_bfloat16 g_caWvT2[2*Dd*Dd];
__device__ __nv_bfloat16 g_caWpT2[2*Dd*Dd];

// ---------------- streams/events (created once at process init; graph fork/join) ----------------
struct HXStreams {
    cudaStream_t s1, s2;
    cudaEvent_t e0, eT, eX, eConn, eQ;
    HXStreams() {
        cudaStreamCreateWithFlags(&s1, cudaStreamNonBlocking);
        cudaStreamCreateWithFlags(&s2, cudaStreamNonBlocking);
        cudaEventCreateWithFlags(&e0, cudaEventDisableTiming);
        cudaEventCreateWithFlags(&eT, cudaEventDisableTiming);
        cudaEventCreateWithFlags(&eX, cudaEventDisableTiming);
        cudaEventCreateWithFlags(&eConn, cudaEventDisableTiming);
        cudaEventCreateWithFlags(&eQ, cudaEventDisableTiming);
    }
};
static HXStreams hx;

// ---------------- low-level helpers ----------------
__device__ __forceinline__ uint32_t smem_u32(const void* p) {
    uint32_t a;
    asm("{ .reg .u64 t; cvta.to.shared.u64 t, %1; cvt.u32.u64 %0, t; }" : "=r"(a) : "l"(p));
    return a;
}
__device__ __forceinline__ void ldsm4(uint32_t* r, uint32_t addr) {
    asm volatile("ldmatrix.sync.aligned.m8n8.x4.shared.b16 {%0,%1,%2,%3}, [%4];"
        : "=r"(r[0]), "=r"(r[1]), "=r"(r[2]), "=r"(r[3]) : "r"(addr));
}
__device__ __forceinline__ void mma16816(float* c, const uint32_t* a, const uint32_t* b) {
    asm volatile("mma.sync.aligned.m16n8k16.row.col.f32.bf16.bf16.f32 "
        "{%0,%1,%2,%3}, {%4,%5,%6,%7}, {%8,%9}, {%0,%1,%2,%3};"
        : "+f"(c[0]), "+f"(c[1]), "+f"(c[2]), "+f"(c[3])
        : "r"(a[0]), "r"(a[1]), "r"(a[2]), "r"(a[3]), "r"(b[0]), "r"(b[1]));
}
__device__ __forceinline__ void split1(float v, __nv_bfloat16& h, __nv_bfloat16& l) {
    h = __float2bfloat16(v);
    l = __float2bfloat16(v - __bfloat162float(h));
}
__device__ __forceinline__ uint32_t pack2(__nv_bfloat16 a, __nv_bfloat16 b) {
    return (uint32_t)__bfloat16_as_ushort(a) | ((uint32_t)__bfloat16_as_ushort(b) << 16);
}
#define CP16(dst, src) \
    asm volatile("cp.async.cg.shared.global [%0], [%1], 16;" :: "r"(dst), "l"(src))
#define CP_COMMIT() asm volatile("cp.async.commit_group;" ::: "memory")

// block reduce (8 warps) via shfl + tiny smem
template <bool MAX>
__device__ __forceinline__ float bred(float v, float* r8, int wid, int lane) {
    #pragma unroll
    for (int o = 16; o; o >>= 1) {
        float u = __shfl_xor_sync(0xffffffffu, v, o);
        v = MAX ? fmaxf(v, u) : (v + u);
    }
    if (lane == 0) r8[wid] = v;
    __syncthreads();
    if (wid == 0) {
        float u = r8[lane & 7];
        #pragma unroll
        for (int o = 4; o; o >>= 1) {
            float t = __shfl_xor_sync(0xffffffffu, u, o);
            u = MAX ? fmaxf(u, t) : (u + t);
        }
        if (lane == 0) r8[0] = u;
    }
    __syncthreads();
    return r8[0];
}

// ---------------- split x into planes ----------------
__global__ void k_split(const float* __restrict__ in, __nv_bfloat16* __restrict__ outp, long plane)
{
    int i = blockIdx.x * 256 + threadIdx.x;
    float4 v = reinterpret_cast<const float4*>(in)[i];
    __nv_bfloat16 h0, l0, h1, l1, h2, l2, h3, l3;
    split1(v.x, h0, l0); split1(v.y, h1, l1); split1(v.z, h2, l2); split1(v.w, h3, l3);
    reinterpret_cast<uint2*>(outp)[i] = make_uint2(pack2(h0, h1), pack2(h2, h3));
    reinterpret_cast<uint2*>(outp + plane)[i] = make_uint2(pack2(l0, l1), pack2(l2, l3));
}

// ---------------- merged transpose kernel (emit planes) ----------------
__global__ void k_transpose_all(const float* adjW, __nv_bfloat16* adjWT,
                                const float* caWq, __nv_bfloat16* caWqT,
                                const float* caWk, __nv_bfloat16* caWkT,
                                const float* caWv, __nv_bfloat16* caWvT,
                                const float* caWp, __nv_bfloat16* caWpT,
                                const float* gatW, __nv_bfloat16* gatWT,
                                const float* gatWo, __nv_bfloat16* WoT)
{
    __shared__ float t[32][33];
    int id = blockIdx.x;
    int tx = threadIdx.x, ty = threadIdx.y;
    const float* src; __nv_bfloat16* dh; long plane; int R, C, bx, by;
    if (id < 320) {
        const float* srcs[5] = {adjW, caWq, caWk, caWv, caWp};
        __nv_bfloat16* dsts[5] = {adjWT, caWqT, caWkT, caWvT, caWpT};
        int m = id >> 6, l = id & 63;
        src = srcs[m]; dh = dsts[m]; plane = Dd * Dd;
        R = Dd; C = Dd; bx = (l & 7) * 32; by = (l >> 3) * 32;
    } else if (id < 832) {
        int l = id - 320; int z = l >> 6; l &= 63;
        src = gatW + (size_t)z * Dd * Dd; dh = gatWT + (size_t)z * Dd * Dd;
        plane = (long)Hh * Dd * Dd;
        R = Dd; C = Dd; bx = (l & 7) * 32; by = (l >> 3) * 32;
    } else {
        int l = id - 832;
        src = gatWo; dh = WoT; plane = (long)HD * Dd;
        R = HD; C = Dd; bx = (l & 7) * 32; by = (l >> 3) * 32;
    }
    #pragma unroll
    for (int i = 0; i < 32; i += 8)
        t[ty + i][tx] = src[(size_t)(by + ty + i) * C + bx + tx];
    __syncthreads();
    #pragma unroll
    for (int i = 0; i < 32; i += 8) {
        float v = t[tx][ty + i];
        __nv_bfloat16 h, l2;
        split1(v, h, l2);
        size_t o = (size_t)(bx + ty + i) * R + by + tx;
        dh[o] = h; dh[plane + o] = l2;
    }
}

// ---------------- plane-pair bf16 mma.sync NT GEMM ----------------
enum { EPI_NONE = 0, EPI_ELU = 1, EPI_CONNECT = 2, EPI_RESID = 3 };
enum { OUT_F32 = 0, OUT_PLANES = 1, OUT_CONNECT = 2, OUT_NONE = 3 };
#define ROWB 80

template <int BM, int BN, int WM, int WN, int EPI, int NA, int OUT, bool DUAL>
__global__ void __launch_bounds__(256, 2)
mma_gemm(const __nv_bfloat16* __restrict__ A, long aPlane,
         const __nv_bfloat16* __restrict__ Bm, long bPlane,
         void* __restrict__ Cv, long cPlane,
         int K, int lda, int ldb, int ldc, int zInner,
         long sAb, long sAi, long sBb, long sBi, long sCb, long sCi,
         const float* __restrict__ e1, long sE1b, const float* __restrict__ e2,
         __nv_bfloat16* __restrict__ Ct, long ctPlane, long sCtb, long sCti, int ldct)
{
    constexpr int ABYTES = BM * ROWB;
    constexpr int BBYTES = BN * ROWB;
    constexpr int STR = BM + 8;          // staging row stride (elements); (BM+8)*2 = 16B multiple
    constexpr int STGPL = BN * STR;      // staging plane elements

    extern __shared__ char smem[];
    const uint32_t sb = smem_u32(smem);

    const int tid = threadIdx.x;
    const int wid = tid >> 5;
    const int lane = tid & 31;

    const int z = blockIdx.z;
    const int zb = z / zInner, zi = z % zInner;
    const __nv_bfloat16* Ap = A + (size_t)zb * sAb + (size_t)zi * sAi;
    const __nv_bfloat16* Bp = Bm + (size_t)zb * sBb + (size_t)zi * sBi;
    float* Cpf = (float*)Cv + (size_t)zb * sCb + (size_t)zi * sCi;
    __nv_bfloat16* Cpb = (__nv_bfloat16*)Cv + (size_t)zb * sCb + (size_t)zi * sCi;
    uint8_t* Cp8 = (uint8_t*)Cv + (size_t)zb * sCb + (size_t)zi * sCi;
    const float* e1p = e1 ? (e1 + (size_t)zb * sE1b) : nullptr;

    const int m0 = blockIdx.y * BM;
    const int n0 = blockIdx.x * BN;

    const int crow = tid >> 2;
    const int cch = tid & 3;

    const int wid_m = wid % WM;
    const int wid_n = wid / WM;
    const int g = lane >> 3, rl = lane & 7;
    const int aRowBase = wid_m * 64 + (g & 1) * 8 + rl;
    const int aKsel = (g >> 1) * 8;
    const int bRowBase = wid_n * 32 + (g >> 1) * 8 + rl;
    const int bKsel = (g & 1) * 8;

    float acc[4][4][4] = {};
    const int nkt = K >> 5;
    const uint32_t bbase = 2 * NA * ABYTES;

    auto copyTile = [&](int kk, int stage) {
        #pragma unroll
        for (int pl = 0; pl < NA; pl++) {
            const __nv_bfloat16* src = Ap + (size_t)pl * aPlane;
            uint32_t dst0 = sb + (stage * NA + pl) * ABYTES;
            #pragma unroll
            for (int i = 0; i < BM / 64; i++) {
                int row = crow + 64 * i;
                CP16(dst0 + row * ROWB + cch * 16,
                     src + (size_t)(m0 + row) * lda + kk + cch * 8);
            }
        }
        #pragma unroll
        for (int pl = 0; pl < 2; pl++) {
            const __nv_bfloat16* src = Bp + (size_t)pl * bPlane;
            uint32_t dst0 = sb + bbase + (stage * 2 + pl) * BBYTES;
            #pragma unroll
            for (int i = 0; i < BN / 64; i++) {
                int row = crow + 64 * i;
                CP16(dst0 + row * ROWB + cch * 16,
                     src + (size_t)(n0 + row) * ldb + kk + cch * 8);
            }
        }
    };

    copyTile(0, 0); CP_COMMIT();

    for (int kt = 0; kt < nkt; kt++) {
        const int stage = kt & 1;
        const bool more = (kt + 1 < nkt);
        if (more) { copyTile((kt + 1) << 5, stage ^ 1); CP_COMMIT(); }
        if (more) asm volatile("cp.async.wait_group 1;" ::: "memory");
        else      asm volatile("cp.async.wait_group 0;" ::: "memory");
        __syncthreads();

        const uint32_t sAhi = sb + stage * NA * ABYTES;
        const uint32_t sAlo = sAhi + ABYTES;
        const uint32_t sBhi = sb + bbase + stage * 2 * BBYTES;
        const uint32_t sBlo = sBhi + BBYTES;

        #pragma unroll
        for (int j = 0; j < 2; j++) {
            const int kb = j * 16;
            uint32_t a[4][4], bh[4][2], bl[4][2];
            #pragma unroll
            for (int im = 0; im < 4; im++)
                ldsm4(a[im], sAhi + (uint32_t)((aRowBase + im * 16) * ROWB + (kb + aKsel) * 2));
            #pragma unroll
            for (int i2 = 0; i2 < 2; i2++) {
                uint32_t t[4];
                ldsm4(t, sBhi + (uint32_t)((bRowBase + i2 * 16) * ROWB + (kb + bKsel) * 2));
                bh[2 * i2][0] = t[0]; bh[2 * i2][1] = t[1];
                bh[2 * i2 + 1][0] = t[2]; bh[2 * i2 + 1][1] = t[3];
            }
            #pragma unroll
            for (int im = 0; im < 4; im++)
                #pragma unroll
                for (int in = 0; in < 4; in++)
                    mma16816(acc[im][in], a[im], bh[in]);           // Ah*Bh
            #pragma unroll
            for (int i2 = 0; i2 < 2; i2++) {
                uint32_t t[4];
                ldsm4(t, sBlo + (uint32_t)((bRowBase + i2 * 16) * ROWB + (kb + bKsel) * 2));
                bl[2 * i2][0] = t[0]; bl[2 * i2][1] = t[1];
                bl[2 * i2 + 1][0] = t[2]; bl[2 * i2 + 1][1] = t[3];
            }
            #pragma unroll
            for (int im = 0; im < 4; im++)
                #pragma unroll
                for (int in = 0; in < 4; in++)
                    mma16816(acc[im][in], a[im], bl[in]);           // Ah*Bl
            if (NA == 2) {
                #pragma unroll
                for (int im = 0; im < 4; im++)
                    ldsm4(a[im], sAlo + (uint32_t)((aRowBase + im * 16) * ROWB + (kb + aKsel) * 2));
                #pragma unroll
                for (int im = 0; im < 4; im++)
                    #pragma unroll
                    for (int in = 0; in < 4; in++)
                        mma16816(acc[im][in], a[im], bh[in]);       // Al*Bh
            }
        }
        __syncthreads();
    }

    // epilogue
    __nv_bfloat16* stg = reinterpret_cast<__nv_bfloat16*>(smem);
    const int mw = m0 + wid_m * 64;
    const int nw = n0 + wid_n * 32;
    #pragma unroll
    for (int im = 0; im < 4; im++) {
        const int row = mw + im * 16 + (lane >> 2);
        const float sr0 = (EPI == EPI_CONNECT) ? e1p[row] : 0.f;
        const float sr1 = (EPI == EPI_CONNECT) ? e1p[row + 8] : 0.f;
        #pragma unroll
        for (int in = 0; in < 4; in++) {
            const int col = nw + in * 8 + (lane & 3) * 2;
            float v00 = acc[im][in][0], v01 = acc[im][in][1];
            float v10 = acc[im][in][2], v11 = acc[im][in][3];
            if (EPI == EPI_ELU) {
                v00 = v00 > 0.f ? v00 : expm1f(v00);
                v01 = v01 > 0.f ? v01 : expm1f(v01);
                v10 = v10 > 0.f ? v10 : expm1f(v10);
                v11 = v11 > 0.f ? v11 : expm1f(v11);
            } else if (EPI == EPI_RESID) {
                const float g0 = e2[col], g1 = e2[col + 1];
                const size_t r0 = (size_t)row * ldc + col;
                const size_t r1 = (size_t)(row + 8) * ldc + col;
                v00 = e1p[r0] + g0 * v00; v01 = e1p[r0 + 1] + g1 * v01;
                v10 = e1p[r1] + g0 * v10; v11 = e1p[r1 + 1] + g1 * v11;
            }
            const size_t o0 = (size_t)row * ldc + col;
            const size_t o1 = (size_t)(row + 8) * ldc + col;
            if (OUT == OUT_CONNECT) {
                const float sc0 = e1p[col], sc1 = e1p[col + 1];
                uchar2 c0, c1;
                c0.x = (v00 > 0.f && sr0 > 0.5f && sc0 > 0.5f) ? 1 : 0;
                c0.y = (v01 > 0.f && sr0 > 0.5f && sc1 > 0.5f) ? 1 : 0;
                c1.x = (v10 > 0.f && sr1 > 0.5f && sc0 > 0.5f) ? 1 : 0;
                c1.y = (v11 > 0.f && sr1 > 0.5f && sc1 > 0.5f) ? 1 : 0;
                *reinterpret_cast<uchar2*>(Cp8 + o0) = c0;
                *reinterpret_cast<uchar2*>(Cp8 + o1) = c1;
            } else if (OUT == OUT_F32) {
                *reinterpret_cast<float2*>(Cpf + o0) = make_float2(v00, v01);
                *reinterpret_cast<float2*>(Cpf + o1) = make_float2(v10, v11);
            }
            __nv_bfloat16 h00, l00, h01, l01, h10, l10, h11, l11;
            if (OUT == OUT_PLANES || DUAL) {
                split1(v00, h00, l00); split1(v01, h01, l01);
                split1(v10, h10, l10); split1(v11, h11, l11);
            }
            if (OUT == OUT_PLANES) {
                *reinterpret_cast<uint32_t*>(Cpb + o0) = pack2(h00, h01);
                *reinterpret_cast<uint32_t*>(Cpb + o1) = pack2(h10, h11);
                *reinterpret_cast<uint32_t*>(Cpb + cPlane + o0) = pack2(l00, l01);
                *reinterpret_cast<uint32_t*>(Cpb + cPlane + o1) = pack2(l10, l11);
            }
            if (DUAL) {
                // stage transposed tile in smem (coalesced write-out after)
                const int cl = col - n0, rlc = row - m0;
                stg[cl * STR + rlc] = h00;
                stg[(cl + 1) * STR + rlc] = h01;
                stg[cl * STR + rlc + 8] = h10;
                stg[(cl + 1) * STR + rlc + 8] = h11;
                stg[STGPL + cl * STR + rlc] = l00;
                stg[STGPL + (cl + 1) * STR + rlc] = l01;
                stg[STGPL + cl * STR + rlc + 8] = l10;
                stg[STGPL + (cl + 1) * STR + rlc + 8] = l11;
            }
        }
    }
    if (DUAL) {
        __syncthreads();
        __nv_bfloat16* Ctp = Ct + (size_t)zb * sCtb + (size_t)zi * sCti;
        const int r = tid >> 1;
        const int hh = (tid & 1) * (BM / 2);
        #pragma unroll
        for (int p = 0; p < 2; p++) {
            const uint4* srow = reinterpret_cast<const uint4*>(stg + p * STGPL + r * STR + hh);
            uint4* drow = reinterpret_cast<uint4*>(Ctp + (size_t)p * ctPlane + (size_t)(n0 + r) * ldct + m0 + hh);
            #pragma unroll
            for (int i = 0; i < BM / 16; i++)
                drow[i] = srow[i];
        }
    }
}

// ---------------- auxiliary kernels ----------------
__global__ void k_posquery1(const float* __restrict__ x, const int* __restrict__ mask,
                            float* __restrict__ part, float* __restrict__ cntp)
{
    int seg = blockIdx.x, b = blockIdx.y, d = threadIdx.x;
    int n0 = seg * 64;
    float s = 0.f, cnt = 0.f;
    for (int n = n0; n < n0 + 64; n++) {
        if (mask[b * Nn + n] == 1) { s += x[((size_t)b * Nn + n) * Dd + d]; cnt += 1.f; }
    }
    part[((size_t)b * 16 + seg) * Dd + d] = s;
    if (d == 0) cntp[b * 16 + seg] = cnt;
}
__global__ void k_posquery2(const float* __restrict__ part, const float* __restrict__ cntp,
                            float* __restrict__ pq)
{
    int b = blockIdx.x, d = threadIdx.x;
    float s = 0.f, cnt = 0.f;
    #pragma unroll
    for (int seg = 0; seg < 16; seg++) {
        s += part[((size_t)b * 16 + seg) * Dd + d];
        cnt += cntp[b * 16 + seg];
    }
    pq[b * Dd + d] = s / fmaxf(cnt, 1.f);
}

__global__ void k_mv1(const float* __restrict__ Wq, const float* __restrict__ pq,
                      float* __restrict__ qs)
{
    __shared__ float spq[Dd];
    __shared__ float red[8][32];
    int b = blockIdx.y, t0 = blockIdx.x * 32;
    int tid = threadIdx.x;
    spq[tid] = pq[b * Dd + tid];
    __syncthreads();
    int tseg = tid >> 5, tl = tid & 31;
    float s = 0.f;
    #pragma unroll
    for (int i = 0; i < 32; i++)
        s += spq[tseg * 32 + i] * Wq[(tseg * 32 + i) * Dd + t0 + tl];
    red[tseg][tl] = s;
    __syncthreads();
    if (tseg == 0) {
        float a = 0.f;
        #pragma unroll
        for (int k = 0; k < 8; k++) a += red[k][tl];
        qs[b * Dd + t0 + tl] = a;
    }
}
__global__ void k_mv2(const float* __restrict__ Wx, const float* __restrict__ qs,
                      float* __restrict__ w)
{
    int b = blockIdx.y;
    int wid = threadIdx.x >> 5, lane = threadIdx.x & 31;
    int t = blockIdx.x * 8 + wid;
    float s = 0.f;
    #pragma unroll
    for (int k = 0; k < 8; k++)
        s += Wx[(size_t)t * Dd + lane + 32 * k] * qs[b * Dd + lane + 32 * k];
    #pragma unroll
    for (int o = 16; o; o >>= 1) s += __shfl_xor_sync(0xffffffffu, s, o);
    if (lane == 0) w[b * Dd + t] = s;
}

__global__ void k_possim(const float* __restrict__ x, const float* __restrict__ w,
                         float* __restrict__ possim_out, float* __restrict__ sel)
{
    int row = blockIdx.x * 8 + (threadIdx.x >> 5);
    int lane = threadIdx.x & 31;
    int b = row / Nn;
    const float4* xr = reinterpret_cast<const float4*>(x + (size_t)row * Dd);
    const float4* wr = reinterpret_cast<const float4*>(w + b * Dd);
    float s = 0.f;
    #pragma unroll
    for (int e = 0; e < 2; e++) {
        float4 xv = xr[lane + e * 32];
        float4 wv = wr[lane + e * 32];
        s += xv.x * wv.x + xv.y * wv.y + xv.z * wv.z + xv.w * wv.w;
    }
    #pragma unroll
    for (int o = 16; o; o >>= 1) s += __shfl_xor_sync(0xffffffffu, s, o);
    if (lane == 0) {
        float p = 1.f / (1.f + expf(-s * 0.0625f));
        possim_out[row] = p;
        sel[row] = (p > 0.97f) ? 1.f : 0.f;
    }
}

__global__ void k_dot2p(const __nv_bfloat16* __restrict__ rows, long plane,
                        const float* __restrict__ a1, const float* __restrict__ a2,
                        float* __restrict__ s1, float* __restrict__ s2, int nheads)
{
    int row = blockIdx.x * 8 + (threadIdx.x >> 5);
    int lane = threadIdx.x & 31;
    int head = (row / Nn) % nheads;
    const __nv_bfloat16* rp = rows + (size_t)row * Dd;
    const float* a1p = a1 + head * Dd;
    const float* a2p = a2 + head * Dd;
    float u = 0.f, v = 0.f;
    for (int e = lane; e < Dd; e += 32) {
        float rv = __bfloat162float(rp[e]) + __bfloat162float(rp[plane + e]);
        u += rv * a1p[e];
        v += rv * a2p[e];
    }
    #pragma unroll
    for (int o = 16; o; o >>= 1) {
        u += __shfl_xor_sync(0xffffffffu, u, o);
        v += __shfl_xor_sync(0xffffffffu, v, o);
    }
    if (lane == 0) { s1[row] = u; s2[row] = v; }
}

__global__ void k_softmax_gat(const float* __restrict__ s1, const float* __restrict__ s2,
                              const uint8_t* __restrict__ connect, __nv_bfloat16* __restrict__ attn,
                              int nheads)
{
    __shared__ float s2row[Nn];
    __shared__ float r8[8];
    int z = blockIdx.y;
    int b = z / nheads;
    int t = threadIdx.x;
    int wid = t >> 5, lane = t & 31;
    #pragma unroll
    for (int k = 0; k < 4; k++) s2row[t + k * 256] = s2[(size_t)z * Nn + t + k * 256];
    __syncthreads();
    #pragma unroll
    for (int r = 0; r < 4; r++) {
        int i = blockIdx.x * 4 + r;
        const uint8_t* con = connect + (size_t)b * NNt + (size_t)i * Nn;
        float s1v = s1[(size_t)z * Nn + i];
        float v[4];
        float mx = -INFINITY;
        #pragma unroll
        for (int k = 0; k < 4; k++) {
            int j = t + k * 256;
            float e = s1v + s2row[j];
            e = (e >= 0.f) ? e : 0.2f * e;
            v[k] = con[j] ? e : -9.0e15f;
            mx = fmaxf(mx, v[k]);
        }
        mx = bred<true>(mx, r8, wid, lane);
        float sum = 0.f;
        #pragma unroll
        for (int k = 0; k < 4; k++) { v[k] = expf(v[k] - mx); sum += v[k]; }
        sum = bred<false>(sum, r8, wid, lane);
        float inv = 1.f / sum;
        __nv_bfloat16* out = attn + (size_t)z * NNt + (size_t)i * Nn;
        #pragma unroll
        for (int k = 0; k < 4; k++) out[t + k * 256] = __float2bfloat16(v[k] * inv);
        __syncthreads();
    }
}

__global__ void k_softmax_ca(const float* __restrict__ logits, const float* __restrict__ sel,
                             __nv_bfloat16* __restrict__ attn)
{
    __shared__ float r8[8];
    int i = blockIdx.x;
    int z = blockIdx.y;
    int b = z / HC;
    const float* row = logits + (size_t)z * NNt + (size_t)i * Nn;
    const float* sp = sel + b * Nn;
    int t = threadIdx.x;
    int wid = t >> 5, lane = t & 31;
    float v[4];
    float mx = -INFINITY;
    #pragma unroll
    for (int k = 0; k < 4; k++) {
        int j = t + k * 256;
        v[k] = (sp[j] > 0.5f) ? row[j] * 0.125f : -1.0e9f;
        mx = fmaxf(mx, v[k]);
    }
    mx = bred<true>(mx, r8, wid, lane);
    float sum = 0.f;
    #pragma unroll
    for (int k = 0; k < 4; k++) { v[k] = expf(v[k] - mx); sum += v[k]; }
    sum = bred<false>(sum, r8, wid, lane);
    float inv = 1.f / sum;
    __nv_bfloat16* out = attn + (size_t)z * NNt + (size_t)i * Nn;
    #pragma unroll
    for (int k = 0; k < 4; k++) out[t + k * 256] = __float2bfloat16(v[k] * inv);
}

__global__ void k_ln(const float* __restrict__ in, const float* __restrict__ g,
                     const float* __restrict__ bb, __nv_bfloat16* __restrict__ out, long oplane)
{
    int row = blockIdx.x * 8 + (threadIdx.x >> 5);
    int lane = threadIdx.x & 31;
    size_t base = (size_t)row * Dd;
    float vbuf[8];
    float s = 0.f, sq = 0.f;
    #pragma unroll
    for (int k = 0; k < 8; k++) {
        float x = in[base + lane + k * 32];
        vbuf[k] = x; s += x; sq += x * x;
    }
    #pragma unroll
    for (int o = 16; o; o >>= 1) {
        s += __shfl_xor_sync(0xffffffffu, s, o);
        sq += __shfl_xor_sync(0xffffffffu, sq, o);
    }
    float mean = s * (1.f / Dd);
    float var = sq * (1.f / Dd) - mean * mean;
    float rstd = rsqrtf(var + 1e-5f);
    #pragma unroll
    for (int k = 0; k < 8; k++) {
        int d = lane + k * 32;
        float y = (vbuf[k] - mean) * rstd * g[d] + bb[d];
        __nv_bfloat16 h, l; split1(y, h, l);
        out[base + d] = h; out[oplane + base + d] = l;
    }
}

__global__ void k_qfull_ln(const __nv_bfloat16* __restrict__ gout, long gplane,
                           const float* __restrict__ pe,
                           const float* __restrict__ sel, const float* __restrict__ g,
                           const float* __restrict__ bb, __nv_bfloat16* __restrict__ out, long oplane)
{
    int row = blockIdx.x * 8 + (threadIdx.x >> 5);
    int lane = threadIdx.x & 31;
    int n = row % Nn;
    size_t base = (size_t)row * Dd;
    float selv = sel[row];
    float vbuf[8];
    float s = 0.f, sq = 0.f;
    #pragma unroll
    for (int k = 0; k < 8; k++) {
        int d = lane + k * 32;
        float gv = __bfloat162float(gout[base + d]) + __bfloat162float(gout[gplane + base + d]);
        float x = (selv > 0.5f) ? (gv + pe[(size_t)n * Dd + d]) : 0.f;
        vbuf[k] = x; s += x; sq += x * x;
    }
    #pragma unroll
    for (int o = 16; o; o >>= 1) {
        s += __shfl_xor_sync(0xffffffffu, s, o);
        sq += __shfl_xor_sync(0xffffffffu, sq, o);
    }
    float mean = s * (1.f / Dd);
    float var = sq * (1.f / Dd) - mean * mean;
    float rstd = rsqrtf(var + 1e-5f);
    #pragma unroll
    for (int k = 0; k < 8; k++) {
        int d = lane + k * 32;
        float y = (vbuf[k] - mean) * rstd * g[d] + bb[d];
        __nv_bfloat16 h, l; split1(y, h, l);
        out[base + d] = h; out[oplane + base + d] = l;
    }
}

// ---------------- launch ----------------
#define GETSYM(p, T, s) do { void* _t; cudaGetSymbolAddress(&_t, s); p = (T*)_t; } while (0)
#define SMEMSZ(BM, BN, NA) ((2 * (NA) * (BM) + 4 * (BN)) * ROWB)

extern "C" void kernel_launch(void* const* d_in, const int* in_sizes, int n_in,
                              void* d_out, int out_size)
{
    const float* x      = (const float*)d_in[0];
    const int*   mask   = (const int*)  d_in[1];
    const float* pe     = (const float*)d_in[2];
    const float* simWx  = (const float*)d_in[3];
    const float* simWq  = (const float*)d_in[4];
    const float* adjW   = (const float*)d_in[5];
    const float* gatW   = (const float*)d_in[6];
    const float* gatA1  = (const float*)d_in[7];
    const float* gatA2  = (const float*)d_in[8];
    const float* gatWo  = (const float*)d_in[9];
    const float* gatAo1 = (const float*)d_in[10];
    const float* gatAo2 = (const float*)d_in[11];
    const float* ln3g   = (const float*)d_in[12];
    const float* ln3b   = (const float*)d_in[13];
    const float* ln4g   = (const float*)d_in[14];
    const float* ln4b   = (const float*)d_in[15];
    const float* caWq   = (const float*)d_in[16];
    const float* caWk   = (const float*)d_in[17];
    const float* caWv   = (const float*)d_in[18];
    const float* caWp   = (const float*)d_in[19];
    const float* gamma  = (const float*)d_in[20];
    (void)in_sizes; (void)n_in; (void)out_size;

    float* out = (float*)d_out;
    float* possim_out = out + (size_t)Bz * Nn * Dd;

    float *posq, *pqpart, *pqcnt, *qsv, *w, *sel, *s1, *s2, *so1, *so2, *logits;
    uint8_t* connect;
    __nv_bfloat16 *attn_bf, *attno_bf;
    __nv_bfloat16 *x2, *fa2, *Wh2, *WhT2, *cat2, *Who2, *WhoT2, *gout2, *qx2, *kv2;
    __nv_bfloat16 *q2, *k2, *vT2, *o2;
    __nv_bfloat16 *adjWT2, *gatWT2, *WoT2, *caWqT2, *caWkT2, *caWvT2, *caWpT2;
    GETSYM(posq, float, g_posq);   GETSYM(pqpart, float, g_pqpart); GETSYM(pqcnt, float, g_pqcnt);
    GETSYM(qsv, float, g_qs);      GETSYM(w, float, g_w);       GETSYM(sel, float, g_sel);
    GETSYM(connect, uint8_t, g_connect);
    GETSYM(s1, float, g_s1);       GETSYM(s2, float, g_s2);
    GETSYM(so1, float, g_so1);     GETSYM(so2, float, g_so2);
    GETSYM(logits, float, g_logits);
    GETSYM(attn_bf, __nv_bfloat16, g_attn_bf);
    GETSYM(attno_bf, __nv_bfloat16, g_attno_bf);
    GETSYM(x2, __nv_bfloat16, g_x2);     GETSYM(fa2, __nv_bfloat16, g_fa2);
    GETSYM(Wh2, __nv_bfloat16, g_Wh2);   GETSYM(WhT2, __nv_bfloat16, g_WhT2);
    GETSYM(cat2, __nv_bfloat16, g_cat2);
    GETSYM(Who2, __nv_bfloat16, g_Who2); GETSYM(WhoT2, __nv_bfloat16, g_WhoT2);
    GETSYM(gout2, __nv_bfloat16, g_gout2);
    GETSYM(qx2, __nv_bfloat16, g_qx2);   GETSYM(kv2, __nv_bfloat16, g_kv2);
    GETSYM(q2, __nv_bfloat16, g_q2);     GETSYM(k2, __nv_bfloat16, g_k2);
    GETSYM(vT2, __nv_bfloat16, g_vT2);   GETSYM(o2, __nv_bfloat16, g_o2);
    GETSYM(adjWT2, __nv_bfloat16, g_adjWT2); GETSYM(gatWT2, __nv_bfloat16, g_gatWT2);
    GETSYM(WoT2, __nv_bfloat16, g_WoT2);
    GETSYM(caWqT2, __nv_bfloat16, g_caWqT2); GETSYM(caWkT2, __nv_bfloat16, g_caWkT2);
    GETSYM(caWvT2, __nv_bfloat16, g_caWvT2); GETSYM(caWpT2, __nv_bfloat16, g_caWpT2);

    const long PL_BND  = (long)Bz * ND;
    const long PL_BHND = (long)Bz * Hh * ND;
    const long PL_CAT  = (long)Bz * Nn * HD;
    const long PL_DD   = (long)Dd * Dd;
    const long PL_GATW = (long)Hh * Dd * Dd;
    const long PL_WO   = (long)HD * Dd;

    const int SM_22 = SMEMSZ(128, 128, 2);
    const int SM_12 = SMEMSZ(128, 128, 1);
    const int SM_AV = SMEMSZ(256, 64, 1);
    cudaFuncSetAttribute(mma_gemm<128,128,2,4,EPI_NONE,   2,OUT_PLANES, false>, cudaFuncAttributeMaxDynamicSharedMemorySize, SM_22);
    cudaFuncSetAttribute(mma_gemm<128,128,2,4,EPI_NONE,   2,OUT_PLANES, true >, cudaFuncAttributeMaxDynamicSharedMemorySize, SM_22);
    cudaFuncSetAttribute(mma_gemm<128,128,2,4,EPI_CONNECT,2,OUT_CONNECT,false>, cudaFuncAttributeMaxDynamicSharedMemorySize, SM_22);
    cudaFuncSetAttribute(mma_gemm<128,128,2,4,EPI_NONE,   2,OUT_NONE,   true >, cudaFuncAttributeMaxDynamicSharedMemorySize, SM_22);
    cudaFuncSetAttribute(mma_gemm<128,128,2,4,EPI_NONE,   2,OUT_F32,    false>, cudaFuncAttributeMaxDynamicSharedMemorySize, SM_22);
    cudaFuncSetAttribute(mma_gemm<128,128,2,4,EPI_RESID,  2,OUT_F32,    false>, cudaFuncAttributeMaxDynamicSharedMemorySize, SM_22);
    cudaFuncSetAttribute(mma_gemm<128,128,2,4,EPI_ELU,    1,OUT_PLANES, false>, cudaFuncAttributeMaxDynamicSharedMemorySize, SM_12);
    cudaFuncSetAttribute(mma_gemm<256,64, 4,2,EPI_NONE,   1,OUT_PLANES, false>, cudaFuncAttributeMaxDynamicSharedMemorySize, SM_AV);

    const long zero = 0;
    cudaStream_t s0 = 0;
    cudaStream_t sA = hx.s1;
    cudaStream_t sB = hx.s2;

    // fork
    cudaEventRecord(hx.e0, s0);
    cudaStreamWaitEvent(sA, hx.e0, 0);
    cudaStreamWaitEvent(sB, hx.e0, 0);

    // stream B: weight transposes -> LN3 -> q projection
    k_transpose_all<<<1344, dim3(32, 8), 0, sB>>>(adjW, adjWT2, caWq, caWqT2, caWk, caWkT2,
                                                  caWv, caWvT2, caWp, caWpT2, gatW, gatWT2, gatWo, WoT2);
    cudaEventRecord(hx.eT, sB);
    k_ln<<<Bz * Nn / 8, 256, 0, sB>>>(x, ln3g, ln3b, qx2, PL_BND);

    // stream 0: split x
    k_split<<<Bz * ND / 1024, 256, 0, s0>>>(x, x2, PL_BND);
    cudaEventRecord(hx.eX, s0);

    // stream B: q = qx @ caWq (needs qx2 + caWqT2, both sB-local)
    mma_gemm<128,128,2,4,EPI_NONE,2,OUT_PLANES,false><<<dim3(2, 64, 1), 256, SM_22, sB>>>(
        qx2, PL_BND, caWqT2, PL_DD, q2, PL_BND,
        Dd, Dd, Dd, Dd, 1, zero, zero, zero, zero, zero, zero,
        nullptr, zero, nullptr, nullptr, zero, zero, zero, 0);
    cudaEventRecord(hx.eQ, sB);

    // stream A: selection path, then fa -> connect
    k_posquery1<<<dim3(16, Bz), 256, 0, sA>>>(x, mask, pqpart, pqcnt);
    k_posquery2<<<Bz, 256, 0, sA>>>(pqpart, pqcnt, posq);
    k_mv1<<<dim3(8, Bz), 256, 0, sA>>>(simWq, posq, qsv);
    k_mv2<<<dim3(32, Bz), 256, 0, sA>>>(simWx, qsv, w);
    k_possim<<<Bz * Nn / 8, 256, 0, sA>>>(x, w, possim_out, sel);
    cudaStreamWaitEvent(sA, hx.eX, 0);
    cudaStreamWaitEvent(sA, hx.eT, 0);
    mma_gemm<128,128,2,4,EPI_NONE,2,OUT_PLANES,false><<<dim3(2, 64, 1), 256, SM_22, sA>>>(
        x2, PL_BND, adjWT2, PL_DD, fa2, PL_BND,
        Dd, Dd, Dd, Dd, 1, zero, zero, zero, zero, zero, zero,
        nullptr, zero, nullptr, nullptr, zero, zero, zero, 0);
    mma_gemm<128,128,2,4,EPI_CONNECT,2,OUT_CONNECT,false><<<dim3(8, 8, Bz), 256, SM_22, sA>>>(
        fa2, PL_BND, fa2, PL_BND, connect, zero,
        Dd, Dd, Dd, Nn, 1, (long)ND, zero, (long)ND, zero, (long)NNt, zero,
        sel, (long)Nn, nullptr, nullptr, zero, zero, zero, 0);
    cudaEventRecord(hx.eConn, sA);

    // stream 0: main chain
    cudaStreamWaitEvent(s0, hx.eT, 0);

    // Wh = x @ gatW[h] (dual-transpose via staged epilogue)
    mma_gemm<128,128,2,4,EPI_NONE,2,OUT_PLANES,true><<<dim3(2, 8, Bz * Hh), 256, SM_22, s0>>>(
        x2, PL_BND, gatWT2, PL_GATW, Wh2, PL_BHND,
        Dd, Dd, Dd, Dd, Hh, (long)ND, zero, zero, (long)Dd * Dd,
        (long)Hh * ND, (long)ND,
        nullptr, zero, nullptr, WhT2, PL_BHND, (long)Hh * ND, (long)ND, Nn);

    k_dot2p<<<Bz * Hh * Nn / 8, 256, 0, s0>>>(Wh2, PL_BHND, gatA1, gatA2, s1, s2, Hh);

    cudaStreamWaitEvent(s0, hx.eConn, 0);
    k_softmax_gat<<<dim3(Nn / 4, Bz * Hh), 256, 0, s0>>>(s1, s2, connect, attn_bf, Hh);

    mma_gemm<128,128,2,4,EPI_ELU,1,OUT_PLANES,false><<<dim3(2, 8, Bz * Hh), 256, SM_12, s0>>>(
        attn_bf, zero, WhT2, PL_BHND, cat2, PL_CAT,
        Nn, Nn, Nn, HD, Hh, (long)Hh * NNt, (long)NNt, (long)Hh * ND, (long)ND,
        (long)Nn * HD, (long)Dd,
        nullptr, zero, nullptr, nullptr, zero, zero, zero, 0);

    mma_gemm<128,128,2,4,EPI_NONE,2,OUT_PLANES,true><<<dim3(2, 8, Bz), 256, SM_22, s0>>>(
        cat2, PL_CAT, WoT2, PL_WO, Who2, PL_BND,
        HD, HD, HD, Dd, 1, (long)Nn * HD, zero, zero, zero, (long)ND, zero,
        nullptr, zero, nullptr, WhoT2, PL_BND, (long)ND, zero, Nn);

    k_dot2p<<<Bz * Nn / 8, 256, 0, s0>>>(Who2, PL_BND, gatAo1, gatAo2, so1, so2, 1);
    k_softmax_gat<<<dim3(Nn / 4, Bz), 256, 0, s0>>>(so1, so2, connect, attno_bf, 1);

    mma_gemm<128,128,2,4,EPI_ELU,1,OUT_PLANES,false><<<dim3(2, 8, Bz), 256, SM_12, s0>>>(
        attno_bf, zero, WhoT2, PL_BND, gout2, PL_BND,
        Nn, Nn, Nn, Dd, 1, (long)NNt, zero, (long)ND, zero, (long)ND, zero,
        nullptr, zero, nullptr, nullptr, zero, zero, zero, 0);

    k_qfull_ln<<<Bz * Nn / 8, 256, 0, s0>>>(gout2, PL_BND, pe, sel, ln4g, ln4b, kv2, PL_BND);

    mma_gemm<128,128,2,4,EPI_NONE,2,OUT_PLANES,false><<<dim3(2, 64, 1), 256, SM_22, s0>>>(
        kv2, PL_BND, caWkT2, PL_DD, k2, PL_BND,
        Dd, Dd, Dd, Dd, 1, zero, zero, zero, zero, zero, zero,
        nullptr, zero, nullptr, nullptr, zero, zero, zero, 0);
    mma_gemm<128,128,2,4,EPI_NONE,2,OUT_NONE,true><<<dim3(2, 8, Bz), 256, SM_22, s0>>>(
        kv2, PL_BND, caWvT2, PL_DD, nullptr, zero,
        Dd, Dd, Dd, Dd, 1, (long)ND, zero, zero, zero, (long)ND, zero,
        nullptr, zero, nullptr, vT2, PL_BND, (long)ND, zero, Nn);

    cudaStreamWaitEvent(s0, hx.eQ, 0);
    mma_gemm<128,128,2,4,EPI_NONE,2,OUT_F32,false><<<dim3(8, 8, Bz * HC), 256, SM_22, s0>>>(
        q2, PL_BND, k2, PL_BND, logits, zero,
        DH, Dd, Dd, Nn, HC, (long)ND, (long)DH, (long)ND, (long)DH,
        (long)HC * NNt, (long)NNt,
        nullptr, zero, nullptr, nullptr, zero, zero, zero, 0);

    k_softmax_ca<<<dim3(Nn, Bz * HC), 256, 0, s0>>>(logits, sel, attn_bf);

    mma_gemm<256,64,4,2,EPI_NONE,1,OUT_PLANES,false><<<dim3(1, 4, Bz * HC), 256, SM_AV, s0>>>(
        attn_bf, zero, vT2, PL_BND, o2, PL_BND,
        Nn, Nn, Nn, Dd, HC, (long)HC * NNt, (long)NNt, (long)ND, (long)DH * Nn,
        (long)ND, (long)DH,
        nullptr, zero, nullptr, nullptr, zero, zero, zero, 0);

    mma_gemm<128,128,2,4,EPI_RESID,2,OUT_F32,false><<<dim3(2, 64, 1), 256, SM_22, s0>>>(
        o2, PL_BND, caWpT2, PL_DD, out, zero,
        Dd, Dd, Dd, Dd, 1, zero, zero, zero, zero, zero, zero,
        x, zero, gamma, nullptr, zero, zero, zero, 0);
}

// round 10
// speedup vs baseline: 1.4144x; 1.0608x over previous
#include <cuda_runtime.h>
#include <cuda_bf16.h>
#include <math.h>
#include <stdint.h>

// Problem constants
#define Bz 8
#define Nn 1024
#define Dd 256
#define Hh 8
#define HC 4
#define DH 64
#define HD 2048                 // Hh*Dd
#define ND (Nn*Dd)              // 262144
#define NNt ((size_t)Nn*Nn)     // 1048576

// ---------------- scratch (device globals) ----------------
__device__ float g_posq[Bz*Dd];
__device__ float g_pqpart[Bz*16*Dd];
__device__ float g_pqcnt[Bz*16];
__device__ float g_qs[Bz*Dd];
__device__ float g_w[Bz*Dd];
__device__ float g_sel[Bz*Nn];
__device__ uint8_t g_connect[(size_t)Bz*Nn*Nn];
__device__ float g_s1[Bz*Hh*Nn];
__device__ float g_s2[Bz*Hh*Nn];
__device__ float g_so1[Bz*Nn];
__device__ float g_so2[Bz*Nn];
__device__ __nv_bfloat16 g_attn_bf[(size_t)Bz*Hh*Nn*Nn];   // GAT probs
__device__ __nv_bfloat16 g_attno_bf[(size_t)Bz*Nn*Nn];

__device__ __nv_bfloat16 g_x2[2*(size_t)Bz*ND];
__device__ __nv_bfloat16 g_fa2[2*(size_t)Bz*ND];
__device__ __nv_bfloat16 g_Wh2[2*(size_t)Bz*Hh*ND];
__device__ __nv_bfloat16 g_WhT2[2*(size_t)Bz*Hh*ND];
__device__ __nv_bfloat16 g_cat2[2*(size_t)Bz*Nn*HD];
__device__ __nv_bfloat16 g_Who2[2*(size_t)Bz*ND];
__device__ __nv_bfloat16 g_WhoT2[2*(size_t)Bz*ND];
__device__ __nv_bfloat16 g_gout2[2*(size_t)Bz*ND];
__device__ __nv_bfloat16 g_qx2[2*(size_t)Bz*ND];
__device__ __nv_bfloat16 g_kv2[2*(size_t)Bz*ND];
__device__ __nv_bfloat16 g_q2[2*(size_t)Bz*ND];
__device__ __nv_bfloat16 g_k2[2*(size_t)Bz*ND];
__device__ __nv_bfloat16 g_vT2[2*(size_t)Bz*ND];
__device__ __nv_bfloat16 g_o2[2*(size_t)Bz*ND];
// transposed weights (planes)
__device__ __nv_bfloat16 g_adjWT2[2*Dd*Dd];
__device__ __nv_bfloat16 g_gatWT2[2*Hh*Dd*Dd];
__device__ __nv_bfloat16 g_WoT2[2*HD*Dd];
__device__ __nv_bfloat16 g_caWqT2[2*Dd*Dd];
__device__ __nv_bfloat16 g_caWkT2[2*Dd*Dd];
__device__ __nv_bfloat16 g_caWvT2[2*Dd*Dd];
__device__ __nv_bfloat16 g_caWpT2[2*Dd*Dd];

// ---------------- streams/events ----------------
struct HXStreams {
    cudaStream_t s1, s2;
    cudaEvent_t e0, eT, eX, eConn, eQ, eKV, eK;
    HXStreams() {
        cudaStreamCreateWithFlags(&s1, cudaStreamNonBlocking);
        cudaStreamCreateWithFlags(&s2, cudaStreamNonBlocking);
        cudaEventCreateWithFlags(&e0, cudaEventDisableTiming);
        cudaEventCreateWithFlags(&eT, cudaEventDisableTiming);
        cudaEventCreateWithFlags(&eX, cudaEventDisableTiming);
        cudaEventCreateWithFlags(&eConn, cudaEventDisableTiming);
        cudaEventCreateWithFlags(&eQ, cudaEventDisableTiming);
        cudaEventCreateWithFlags(&eKV, cudaEventDisableTiming);
        cudaEventCreateWithFlags(&eK, cudaEventDisableTiming);
    }
};
static HXStreams hx;

// ---------------- low-level helpers ----------------
__device__ __forceinline__ uint32_t smem_u32(const void* p) {
    uint32_t a;
    asm("{ .reg .u64 t; cvta.to.shared.u64 t, %1; cvt.u32.u64 %0, t; }" : "=r"(a) : "l"(p));
    return a;
}
__device__ __forceinline__ void ldsm4(uint32_t* r, uint32_t addr) {
    asm volatile("ldmatrix.sync.aligned.m8n8.x4.shared.b16 {%0,%1,%2,%3}, [%4];"
        : "=r"(r[0]), "=r"(r[1]), "=r"(r[2]), "=r"(r[3]) : "r"(addr));
}
__device__ __forceinline__ void mma16816(float* c, const uint32_t* a, const uint32_t* b) {
    asm volatile("mma.sync.aligned.m16n8k16.row.col.f32.bf16.bf16.f32 "
        "{%0,%1,%2,%3}, {%4,%5,%6,%7}, {%8,%9}, {%0,%1,%2,%3};"
        : "+f"(c[0]), "+f"(c[1]), "+f"(c[2]), "+f"(c[3])
        : "r"(a[0]), "r"(a[1]), "r"(a[2]), "r"(a[3]), "r"(b[0]), "r"(b[1]));
}
__device__ __forceinline__ void split1(float v, __nv_bfloat16& h, __nv_bfloat16& l) {
    h = __float2bfloat16(v);
    l = __float2bfloat16(v - __bfloat162float(h));
}
__device__ __forceinline__ uint32_t pack2(__nv_bfloat16 a, __nv_bfloat16 b) {
    return (uint32_t)__bfloat16_as_ushort(a) | ((uint32_t)__bfloat16_as_ushort(b) << 16);
}
__device__ __forceinline__ uint32_t packf2(float a, float b) {
    uint32_t r;
    asm("cvt.rn.bf16x2.f32 %0, %1, %2;" : "=r"(r) : "f"(b), "f"(a));
    return r;
}
#define CP16(dst, src) \
    asm volatile("cp.async.cg.shared.global [%0], [%1], 16;" :: "r"(dst), "l"(src))
#define CP_COMMIT() asm volatile("cp.async.commit_group;" ::: "memory")

template <bool MAX>
__device__ __forceinline__ float bred(float v, float* r8, int wid, int lane) {
    #pragma unroll
    for (int o = 16; o; o >>= 1) {
        float u = __shfl_xor_sync(0xffffffffu, v, o);
        v = MAX ? fmaxf(v, u) : (v + u);
    }
    if (lane == 0) r8[wid] = v;
    __syncthreads();
    if (wid == 0) {
        float u = r8[lane & 7];
        #pragma unroll
        for (int o = 4; o; o >>= 1) {
            float t = __shfl_xor_sync(0xffffffffu, u, o);
            u = MAX ? fmaxf(u, t) : (u + t);
        }
        if (lane == 0) r8[0] = u;
    }
    __syncthreads();
    return r8[0];
}

// ---------------- split x into planes ----------------
__global__ void k_split(const float* __restrict__ in, __nv_bfloat16* __restrict__ outp, long plane)
{
    int i = blockIdx.x * 256 + threadIdx.x;
    float4 v = reinterpret_cast<const float4*>(in)[i];
    __nv_bfloat16 h0, l0, h1, l1, h2, l2, h3, l3;
    split1(v.x, h0, l0); split1(v.y, h1, l1); split1(v.z, h2, l2); split1(v.w, h3, l3);
    reinterpret_cast<uint2*>(outp)[i] = make_uint2(pack2(h0, h1), pack2(h2, h3));
    reinterpret_cast<uint2*>(outp + plane)[i] = make_uint2(pack2(l0, l1), pack2(l2, l3));
}

// ---------------- merged transpose kernel ----------------
__global__ void k_transpose_all(const float* adjW, __nv_bfloat16* adjWT,
                                const float* caWq, __nv_bfloat16* caWqT,
                                const float* caWk, __nv_bfloat16* caWkT,
                                const float* caWv, __nv_bfloat16* caWvT,
                                const float* caWp, __nv_bfloat16* caWpT,
                                const float* gatW, __nv_bfloat16* gatWT,
                                const float* gatWo, __nv_bfloat16* WoT)
{
    __shared__ float t[32][33];
    int id = blockIdx.x;
    int tx = threadIdx.x, ty = threadIdx.y;
    const float* src; __nv_bfloat16* dh; long plane; int R, C, bx, by;
    if (id < 320) {
        const float* srcs[5] = {adjW, caWq, caWk, caWv, caWp};
        __nv_bfloat16* dsts[5] = {adjWT, caWqT, caWkT, caWvT, caWpT};
        int m = id >> 6, l = id & 63;
        src = srcs[m]; dh = dsts[m]; plane = Dd * Dd;
        R = Dd; C = Dd; bx = (l & 7) * 32; by = (l >> 3) * 32;
    } else if (id < 832) {
        int l = id - 320; int z = l >> 6; l &= 63;
        src = gatW + (size_t)z * Dd * Dd; dh = gatWT + (size_t)z * Dd * Dd;
        plane = (long)Hh * Dd * Dd;
        R = Dd; C = Dd; bx = (l & 7) * 32; by = (l >> 3) * 32;
    } else {
        int l = id - 832;
        src = gatWo; dh = WoT; plane = (long)HD * Dd;
        R = HD; C = Dd; bx = (l & 7) * 32; by = (l >> 3) * 32;
    }
    #pragma unroll
    for (int i = 0; i < 32; i += 8)
        t[ty + i][tx] = src[(size_t)(by + ty + i) * C + bx + tx];
    __syncthreads();
    #pragma unroll
    for (int i = 0; i < 32; i += 8) {
        float v = t[tx][ty + i];
        __nv_bfloat16 h, l2;
        split1(v, h, l2);
        size_t o = (size_t)(bx + ty + i) * R + by + tx;
        dh[o] = h; dh[plane + o] = l2;
    }
}

// ---------------- plane-pair bf16 mma.sync NT GEMM ----------------
enum { EPI_NONE = 0, EPI_ELU = 1, EPI_CONNECT = 2, EPI_RESID = 3 };
enum { OUT_F32 = 0, OUT_PLANES = 1, OUT_CONNECT = 2, OUT_NONE = 3 };
#define ROWB 80

template <int BM, int BN, int WM, int WN, int EPI, int NA, int OUT, bool DUAL>
__global__ void __launch_bounds__(256, 2)
mma_gemm(const __nv_bfloat16* __restrict__ A, long aPlane,
         const __nv_bfloat16* __restrict__ Bm, long bPlane,
         void* __restrict__ Cv, long cPlane,
         int K, int lda, int ldb, int ldc, int zInner,
         long sAb, long sAi, long sBb, long sBi, long sCb, long sCi,
         const float* __restrict__ e1, long sE1b, const float* __restrict__ e2,
         __nv_bfloat16* __restrict__ Ct, long ctPlane, long sCtb, long sCti, int ldct)
{
    constexpr int ABYTES = BM * ROWB;
    constexpr int BBYTES = BN * ROWB;
    constexpr int STR = BM + 8;
    constexpr int STGPL = BN * STR;

    extern __shared__ char smem[];
    const uint32_t sb = smem_u32(smem);

    const int tid = threadIdx.x;
    const int wid = tid >> 5;
    const int lane = tid & 31;

    const int z = blockIdx.z;
    const int zb = z / zInner, zi = z % zInner;
    const __nv_bfloat16* Ap = A + (size_t)zb * sAb + (size_t)zi * sAi;
    const __nv_bfloat16* Bp = Bm + (size_t)zb * sBb + (size_t)zi * sBi;
    float* Cpf = (float*)Cv + (size_t)zb * sCb + (size_t)zi * sCi;
    __nv_bfloat16* Cpb = (__nv_bfloat16*)Cv + (size_t)zb * sCb + (size_t)zi * sCi;
    uint8_t* Cp8 = (uint8_t*)Cv + (size_t)zb * sCb + (size_t)zi * sCi;
    const float* e1p = e1 ? (e1 + (size_t)zb * sE1b) : nullptr;

    const int m0 = blockIdx.y * BM;
    const int n0 = blockIdx.x * BN;

    const int crow = tid >> 2;
    const int cch = tid & 3;

    const int wid_m = wid % WM;
    const int wid_n = wid / WM;
    const int g = lane >> 3, rl = lane & 7;
    const int aRowBase = wid_m * 64 + (g & 1) * 8 + rl;
    const int aKsel = (g >> 1) * 8;
    const int bRowBase = wid_n * 32 + (g >> 1) * 8 + rl;
    const int bKsel = (g & 1) * 8;

    float acc[4][4][4] = {};
    const int nkt = K >> 5;
    const uint32_t bbase = 2 * NA * ABYTES;

    auto copyTile = [&](int kk, int stage) {
        #pragma unroll
        for (int pl = 0; pl < NA; pl++) {
            const __nv_bfloat16* src = Ap + (size_t)pl * aPlane;
            uint32_t dst0 = sb + (stage * NA + pl) * ABYTES;
            #pragma unroll
            for (int i = 0; i < BM / 64; i++) {
                int row = crow + 64 * i;
                CP16(dst0 + row * ROWB + cch * 16,
                     src + (size_t)(m0 + row) * lda + kk + cch * 8);
            }
        }
        #pragma unroll
        for (int pl = 0; pl < 2; pl++) {
            const __nv_bfloat16* src = Bp + (size_t)pl * bPlane;
            uint32_t dst0 = sb + bbase + (stage * 2 + pl) * BBYTES;
            #pragma unroll
            for (int i = 0; i < BN / 64; i++) {
                int row = crow + 64 * i;
                CP16(dst0 + row * ROWB + cch * 16,
                     src + (size_t)(n0 + row) * ldb + kk + cch * 8);
            }
        }
    };

    copyTile(0, 0); CP_COMMIT();

    for (int kt = 0; kt < nkt; kt++) {
        const int stage = kt & 1;
        const bool more = (kt + 1 < nkt);
        if (more) { copyTile((kt + 1) << 5, stage ^ 1); CP_COMMIT(); }
        if (more) asm volatile("cp.async.wait_group 1;" ::: "memory");
        else      asm volatile("cp.async.wait_group 0;" ::: "memory");
        __syncthreads();

        const uint32_t sAhi = sb + stage * NA * ABYTES;
        const uint32_t sAlo = sAhi + ABYTES;
        const uint32_t sBhi = sb + bbase + stage * 2 * BBYTES;
        const uint32_t sBlo = sBhi + BBYTES;

        #pragma unroll
        for (int j = 0; j < 2; j++) {
            const int kb = j * 16;
            uint32_t a[4][4], bh[4][2], bl[4][2];
            #pragma unroll
            for (int im = 0; im < 4; im++)
                ldsm4(a[im], sAhi + (uint32_t)((aRowBase + im * 16) * ROWB + (kb + aKsel) * 2));
            #pragma unroll
            for (int i2 = 0; i2 < 2; i2++) {
                uint32_t t[4];
                ldsm4(t, sBhi + (uint32_t)((bRowBase + i2 * 16) * ROWB + (kb + bKsel) * 2));
                bh[2 * i2][0] = t[0]; bh[2 * i2][1] = t[1];
                bh[2 * i2 + 1][0] = t[2]; bh[2 * i2 + 1][1] = t[3];
            }
            #pragma unroll
            for (int im = 0; im < 4; im++)
                #pragma unroll
                for (int in = 0; in < 4; in++)
                    mma16816(acc[im][in], a[im], bh[in]);
            #pragma unroll
            for (int i2 = 0; i2 < 2; i2++) {
                uint32_t t[4];
                ldsm4(t, sBlo + (uint32_t)((bRowBase + i2 * 16) * ROWB + (kb + bKsel) * 2));
                bl[2 * i2][0] = t[0]; bl[2 * i2][1] = t[1];
                bl[2 * i2 + 1][0] = t[2]; bl[2 * i2 + 1][1] = t[3];
            }
            #pragma unroll
            for (int im = 0; im < 4; im++)
                #pragma unroll
                for (int in = 0; in < 4; in++)
                    mma16816(acc[im][in], a[im], bl[in]);
            if (NA == 2) {
                #pragma unroll
                for (int im = 0; im < 4; im++)
                    ldsm4(a[im], sAlo + (uint32_t)((aRowBase + im * 16) * ROWB + (kb + aKsel) * 2));
                #pragma unroll
                for (int im = 0; im < 4; im++)
                    #pragma unroll
                    for (int in = 0; in < 4; in++)
                        mma16816(acc[im][in], a[im], bh[in]);
            }
        }
        __syncthreads();
    }

    // epilogue
    __nv_bfloat16* stg = reinterpret_cast<__nv_bfloat16*>(smem);
    const int mw = m0 + wid_m * 64;
    const int nw = n0 + wid_n * 32;
    #pragma unroll
    for (int im = 0; im < 4; im++) {
        const int row = mw + im * 16 + (lane >> 2);
        const float sr0 = (EPI == EPI_CONNECT) ? e1p[row] : 0.f;
        const float sr1 = (EPI == EPI_CONNECT) ? e1p[row + 8] : 0.f;
        #pragma unroll
        for (int in = 0; in < 4; in++) {
            const int col = nw + in * 8 + (lane & 3) * 2;
            float v00 = acc[im][in][0], v01 = acc[im][in][1];
            float v10 = acc[im][in][2], v11 = acc[im][in][3];
            if (EPI == EPI_ELU) {
                v00 = v00 > 0.f ? v00 : expm1f(v00);
                v01 = v01 > 0.f ? v01 : expm1f(v01);
                v10 = v10 > 0.f ? v10 : expm1f(v10);
                v11 = v11 > 0.f ? v11 : expm1f(v11);
            } else if (EPI == EPI_RESID) {
                const float g0 = e2[col], g1 = e2[col + 1];
                const size_t r0 = (size_t)row * ldc + col;
                const size_t r1 = (size_t)(row + 8) * ldc + col;
                v00 = e1p[r0] + g0 * v00; v01 = e1p[r0 + 1] + g1 * v01;
                v10 = e1p[r1] + g0 * v10; v11 = e1p[r1 + 1] + g1 * v11;
            }
            const size_t o0 = (size_t)row * ldc + col;
            const size_t o1 = (size_t)(row + 8) * ldc + col;
            if (OUT == OUT_CONNECT) {
                const float sc0 = e1p[col], sc1 = e1p[col + 1];
                uchar2 c0, c1;
                c0.x = (v00 > 0.f && sr0 > 0.5f && sc0 > 0.5f) ? 1 : 0;
                c0.y = (v01 > 0.f && sr0 > 0.5f && sc1 > 0.5f) ? 1 : 0;
                c1.x = (v10 > 0.f && sr1 > 0.5f && sc0 > 0.5f) ? 1 : 0;
                c1.y = (v11 > 0.f && sr1 > 0.5f && sc1 > 0.5f) ? 1 : 0;
                *reinterpret_cast<uchar2*>(Cp8 + o0) = c0;
                *reinterpret_cast<uchar2*>(Cp8 + o1) = c1;
            } else if (OUT == OUT_F32) {
                *reinterpret_cast<float2*>(Cpf + o0) = make_float2(v00, v01);
                *reinterpret_cast<float2*>(Cpf + o1) = make_float2(v10, v11);
            }
            __nv_bfloat16 h00, l00, h01, l01, h10, l10, h11, l11;
            if (OUT == OUT_PLANES || DUAL) {
                split1(v00, h00, l00); split1(v01, h01, l01);
                split1(v10, h10, l10); split1(v11, h11, l11);
            }
            if (OUT == OUT_PLANES) {
                *reinterpret_cast<uint32_t*>(Cpb + o0) = pack2(h00, h01);
                *reinterpret_cast<uint32_t*>(Cpb + o1) = pack2(h10, h11);
                *reinterpret_cast<uint32_t*>(Cpb + cPlane + o0) = pack2(l00, l01);
                *reinterpret_cast<uint32_t*>(Cpb + cPlane + o1) = pack2(l10, l11);
            }
            if (DUAL) {
                const int cl = col - n0, rlc = row - m0;
                stg[cl * STR + rlc] = h00;
                stg[(cl + 1) * STR + rlc] = h01;
                stg[cl * STR + rlc + 8] = h10;
                stg[(cl + 1) * STR + rlc + 8] = h11;
                stg[STGPL + cl * STR + rlc] = l00;
                stg[STGPL + (cl + 1) * STR + rlc] = l01;
                stg[STGPL + cl * STR + rlc + 8] = l10;
                stg[STGPL + (cl + 1) * STR + rlc + 8] = l11;
            }
        }
    }
    if (DUAL) {
        __syncthreads();
        __nv_bfloat16* Ctp = Ct + (size_t)zb * sCtb + (size_t)zi * sCti;
        const int r = tid >> 1;
        const int hh = (tid & 1) * (BM / 2);
        #pragma unroll
        for (int p = 0; p < 2; p++) {
            const uint4* srow = reinterpret_cast<const uint4*>(stg + p * STGPL + r * STR + hh);
            uint4* drow = reinterpret_cast<uint4*>(Ctp + (size_t)p * ctPlane + (size_t)(n0 + r) * ldct + m0 + hh);
            #pragma unroll
            for (int i = 0; i < BM / 16; i++)
                drow[i] = srow[i];
        }
    }
}

// ---------------- fused flash cross-attention ----------------
// grid (Nn/128, Bz*HC); 256 threads. O = softmax(mask(QK^T*0.125)) @ V, written as planes.
#define QROWB 144
#define VROWB 272
#define QPLB (128*QROWB)         // 18432
#define VPLB (64*VROWB)          // 17408
#define FCA_SMEM (4*QPLB + 2*VPLB + 512)

__global__ void __launch_bounds__(256, 1)
k_flash_ca(const __nv_bfloat16* __restrict__ q2, const __nv_bfloat16* __restrict__ k2,
           const __nv_bfloat16* __restrict__ vT2, const float* __restrict__ sel,
           __nv_bfloat16* __restrict__ o2, long plane)
{
    extern __shared__ char smem[];
    const uint32_t sb = smem_u32(smem);
    const uint32_t Q0 = 0, K0 = 2 * QPLB, V0 = 4 * QPLB, SEL0 = 4 * QPLB + 2 * VPLB;
    const float* sel_s = reinterpret_cast<const float*>(smem + SEL0);

    const int tid = threadIdx.x, wid = tid >> 5, lane = tid & 31;
    const int b = blockIdx.y / HC, hc = blockIdx.y % HC;
    const int m0 = blockIdx.x * 128;

    const __nv_bfloat16* Qp = q2 + (size_t)b * ND + hc * DH;
    const __nv_bfloat16* Kp = k2 + (size_t)b * ND + hc * DH;
    const __nv_bfloat16* Vp = vT2 + (size_t)b * ND + (size_t)hc * DH * Nn;
    const float* selb = sel + b * Nn;

    // load Q once
    {
        int row = tid >> 1, cb = (tid & 1) * 4;
        #pragma unroll
        for (int pl = 0; pl < 2; pl++)
            #pragma unroll
            for (int c = 0; c < 4; c++)
                CP16(sb + Q0 + pl * QPLB + row * QROWB + (cb + c) * 16,
                     Qp + (size_t)pl * plane + (size_t)(m0 + row) * Dd + (cb + c) * 8);
    }

    const int g = lane >> 3, rl = lane & 7;
    const int aRow = wid * 16 + (g & 1) * 8 + rl;
    const int aKs = (g >> 1) * 8;
    const int bRow = (g >> 1) * 8 + rl;
    const int bKs = (g & 1) * 8;
    const int q2c = (lane & 3) * 2;

    float O[8][4] = {};
    float mrow0 = -INFINITY, mrow1 = -INFINITY;
    float lrow0 = 0.f, lrow1 = 0.f;

    for (int kt = 0; kt < 8; kt++) {
        const int t0 = kt * 128;
        {
            int row = tid >> 1, cb = (tid & 1) * 4;
            #pragma unroll
            for (int pl = 0; pl < 2; pl++)
                #pragma unroll
                for (int c = 0; c < 4; c++)
                    CP16(sb + K0 + pl * QPLB + row * QROWB + (cb + c) * 16,
                         Kp + (size_t)pl * plane + (size_t)(t0 + row) * Dd + (cb + c) * 8);
            int vrow = tid >> 2, vcb = (tid & 3) * 4;
            #pragma unroll
            for (int pl = 0; pl < 2; pl++)
                #pragma unroll
                for (int c = 0; c < 4; c++)
                    CP16(sb + V0 + pl * VPLB + vrow * VROWB + (vcb + c) * 16,
                         Vp + (size_t)pl * plane + (size_t)vrow * Nn + t0 + (vcb + c) * 8);
            if (tid < 32)
                CP16(sb + SEL0 + tid * 16, selb + t0 + tid * 4);
        }
        CP_COMMIT();
        asm volatile("cp.async.wait_group 0;" ::: "memory");
        __syncthreads();

        // S = Q K^T (3 products)
        float S[16][4];
        #pragma unroll
        for (int f = 0; f < 16; f++) { S[f][0] = S[f][1] = S[f][2] = S[f][3] = 0.f; }
        #pragma unroll
        for (int ks = 0; ks < 4; ks++) {
            uint32_t ah[4], al[4];
            ldsm4(ah, sb + Q0 + (uint32_t)(aRow * QROWB + (ks * 16 + aKs) * 2));
            ldsm4(al, sb + Q0 + QPLB + (uint32_t)(aRow * QROWB + (ks * 16 + aKs) * 2));
            #pragma unroll
            for (int nf2 = 0; nf2 < 8; nf2++) {
                uint32_t th[4], tl[4];
                ldsm4(th, sb + K0 + (uint32_t)((bRow + nf2 * 16) * QROWB + (ks * 16 + bKs) * 2));
                ldsm4(tl, sb + K0 + QPLB + (uint32_t)((bRow + nf2 * 16) * QROWB + (ks * 16 + bKs) * 2));
                uint32_t bh0[2] = {th[0], th[1]}, bh1[2] = {th[2], th[3]};
                uint32_t bl0[2] = {tl[0], tl[1]}, bl1[2] = {tl[2], tl[3]};
                mma16816(S[2 * nf2], ah, bh0);     mma16816(S[2 * nf2 + 1], ah, bh1);
                mma16816(S[2 * nf2], ah, bl0);     mma16816(S[2 * nf2 + 1], ah, bl1);
                mma16816(S[2 * nf2], al, bh0);     mma16816(S[2 * nf2 + 1], al, bh1);
            }
        }

        // scale + mask + row max
        float mx0 = mrow0, mx1 = mrow1;
        #pragma unroll
        for (int f = 0; f < 16; f++) {
            int col = f * 8 + q2c;
            bool k0 = sel_s[col] > 0.5f, k1 = sel_s[col + 1] > 0.5f;
            S[f][0] = k0 ? S[f][0] * 0.125f : -1.0e9f;
            S[f][1] = k1 ? S[f][1] * 0.125f : -1.0e9f;
            S[f][2] = k0 ? S[f][2] * 0.125f : -1.0e9f;
            S[f][3] = k1 ? S[f][3] * 0.125f : -1.0e9f;
            mx0 = fmaxf(mx0, fmaxf(S[f][0], S[f][1]));
            mx1 = fmaxf(mx1, fmaxf(S[f][2], S[f][3]));
        }
        #pragma unroll
        for (int o = 1; o < 4; o <<= 1) {
            mx0 = fmaxf(mx0, __shfl_xor_sync(0xffffffffu, mx0, o));
            mx1 = fmaxf(mx1, __shfl_xor_sync(0xffffffffu, mx1, o));
        }
        const float sc0 = expf(mrow0 - mx0);
        const float sc1 = expf(mrow1 - mx1);
        mrow0 = mx0; mrow1 = mx1;
        lrow0 *= sc0; lrow1 *= sc1;
        #pragma unroll
        for (int f = 0; f < 8; f++) {
            O[f][0] *= sc0; O[f][1] *= sc0; O[f][2] *= sc1; O[f][3] *= sc1;
        }
        // P = exp(S - m), pack as A fragments
        uint32_t P[8][4];
        float rs0 = 0.f, rs1 = 0.f;
        #pragma unroll
        for (int nf2 = 0; nf2 < 8; nf2++) {
            float p00 = expf(S[2 * nf2][0] - mx0),     p01 = expf(S[2 * nf2][1] - mx0);
            float p10 = expf(S[2 * nf2][2] - mx1),     p11 = expf(S[2 * nf2][3] - mx1);
            float p20 = expf(S[2 * nf2 + 1][0] - mx0), p21 = expf(S[2 * nf2 + 1][1] - mx0);
            float p30 = expf(S[2 * nf2 + 1][2] - mx1), p31 = expf(S[2 * nf2 + 1][3] - mx1);
            rs0 += p00 + p01 + p20 + p21;
            rs1 += p10 + p11 + p30 + p31;
            P[nf2][0] = packf2(p00, p01);
            P[nf2][1] = packf2(p10, p11);
            P[nf2][2] = packf2(p20, p21);
            P[nf2][3] = packf2(p30, p31);
        }
        #pragma unroll
        for (int o = 1; o < 4; o <<= 1) {
            rs0 += __shfl_xor_sync(0xffffffffu, rs0, o);
            rs1 += __shfl_xor_sync(0xffffffffu, rs1, o);
        }
        lrow0 += rs0; lrow1 += rs1;

        // O += P @ V (2 products); dn indexes 4 blocks of 16 dh rows
        #pragma unroll
        for (int ks2 = 0; ks2 < 8; ks2++) {
            #pragma unroll
            for (int dn = 0; dn < 4; dn++) {
                uint32_t th[4], tl[4];
                ldsm4(th, sb + V0 + (uint32_t)((bRow + dn * 16) * VROWB + (ks2 * 16 + bKs) * 2));
                ldsm4(tl, sb + V0 + VPLB + (uint32_t)((bRow + dn * 16) * VROWB + (ks2 * 16 + bKs) * 2));
                uint32_t bh0[2] = {th[0], th[1]}, bh1[2] = {th[2], th[3]};
                uint32_t bl0[2] = {tl[0], tl[1]}, bl1[2] = {tl[2], tl[3]};
                mma16816(O[2 * dn],     P[ks2], bh0);
                mma16816(O[2 * dn + 1], P[ks2], bh1);
                mma16816(O[2 * dn],     P[ks2], bl0);
                mma16816(O[2 * dn + 1], P[ks2], bl1);
            }
        }
        __syncthreads();
    }

    const float li0 = 1.f / lrow0, li1 = 1.f / lrow1;
    const int row0 = m0 + wid * 16 + (lane >> 2);
    __nv_bfloat16* ob = o2 + (size_t)b * ND;
    #pragma unroll
    for (int f = 0; f < 8; f++) {
        int d = hc * DH + f * 8 + q2c;
        float v00 = O[f][0] * li0, v01 = O[f][1] * li0;
        float v10 = O[f][2] * li1, v11 = O[f][3] * li1;
        __nv_bfloat16 h00, l00, h01, l01, h10, l10, h11, l11;
        split1(v00, h00, l00); split1(v01, h01, l01);
        split1(v10, h10, l10); split1(v11, h11, l11);
        size_t o0 = (size_t)row0 * Dd + d;
        size_t o1 = (size_t)(row0 + 8) * Dd + d;
        *reinterpret_cast<uint32_t*>(ob + o0) = pack2(h00, h01);
        *reinterpret_cast<uint32_t*>(ob + o1) = pack2(h10, h11);
        *reinterpret_cast<uint32_t*>(ob + plane + o0) = pack2(l00, l01);
        *reinterpret_cast<uint32_t*>(ob + plane + o1) = pack2(l10, l11);
    }
}

// ---------------- auxiliary kernels ----------------
__global__ void k_posquery1(const float* __restrict__ x, const int* __restrict__ mask,
                            float* __restrict__ part, float* __restrict__ cntp)
{
    int seg = blockIdx.x, b = blockIdx.y, d = threadIdx.x;
    int n0 = seg * 64;
    float s = 0.f, cnt = 0.f;
    for (int n = n0; n < n0 + 64; n++) {
        if (mask[b * Nn + n] == 1) { s += x[((size_t)b * Nn + n) * Dd + d]; cnt += 1.f; }
    }
    part[((size_t)b * 16 + seg) * Dd + d] = s;
    if (d == 0) cntp[b * 16 + seg] = cnt;
}
__global__ void k_posquery2(const float* __restrict__ part, const float* __restrict__ cntp,
                            float* __restrict__ pq)
{
    int b = blockIdx.x, d = threadIdx.x;
    float s = 0.f, cnt = 0.f;
    #pragma unroll
    for (int seg = 0; seg < 16; seg++) {
        s += part[((size_t)b * 16 + seg) * Dd + d];
        cnt += cntp[b * 16 + seg];
    }
    pq[b * Dd + d] = s / fmaxf(cnt, 1.f);
}

__global__ void k_mv1(const float* __restrict__ Wq, const float* __restrict__ pq,
                      float* __restrict__ qs)
{
    __shared__ float spq[Dd];
    __shared__ float red[8][32];
    int b = blockIdx.y, t0 = blockIdx.x * 32;
    int tid = threadIdx.x;
    spq[tid] = pq[b * Dd + tid];
    __syncthreads();
    int tseg = tid >> 5, tl = tid & 31;
    float s = 0.f;
    #pragma unroll
    for (int i = 0; i < 32; i++)
        s += spq[tseg * 32 + i] * Wq[(tseg * 32 + i) * Dd + t0 + tl];
    red[tseg][tl] = s;
    __syncthreads();
    if (tseg == 0) {
        float a = 0.f;
        #pragma unroll
        for (int k = 0; k < 8; k++) a += red[k][tl];
        qs[b * Dd + t0 + tl] = a;
    }
}
__global__ void k_mv2(const float* __restrict__ Wx, const float* __restrict__ qs,
                      float* __restrict__ w)
{
    int b = blockIdx.y;
    int wid = threadIdx.x >> 5, lane = threadIdx.x & 31;
    int t = blockIdx.x * 8 + wid;
    float s = 0.f;
    #pragma unroll
    for (int k = 0; k < 8; k++)
        s += Wx[(size_t)t * Dd + lane + 32 * k] * qs[b * Dd + lane + 32 * k];
    #pragma unroll
    for (int o = 16; o; o >>= 1) s += __shfl_xor_sync(0xffffffffu, s, o);
    if (lane == 0) w[b * Dd + t] = s;
}

__global__ void k_possim(const float* __restrict__ x, const float* __restrict__ w,
                         float* __restrict__ possim_out, float* __restrict__ sel)
{
    int row = blockIdx.x * 8 + (threadIdx.x >> 5);
    int lane = threadIdx.x & 31;
    int b = row / Nn;
    const float4* xr = reinterpret_cast<const float4*>(x + (size_t)row * Dd);
    const float4* wr = reinterpret_cast<const float4*>(w + b * Dd);
    float s = 0.f;
    #pragma unroll
    for (int e = 0; e < 2; e++) {
        float4 xv = xr[lane + e * 32];
        float4 wv = wr[lane + e * 32];
        s += xv.x * wv.x + xv.y * wv.y + xv.z * wv.z + xv.w * wv.w;
    }
    #pragma unroll
    for (int o = 16; o; o >>= 1) s += __shfl_xor_sync(0xffffffffu, s, o);
    if (lane == 0) {
        float p = 1.f / (1.f + expf(-s * 0.0625f));
        possim_out[row] = p;
        sel[row] = (p > 0.97f) ? 1.f : 0.f;
    }
}

__global__ void k_dot2p(const __nv_bfloat16* __restrict__ rows, long plane,
                        const float* __restrict__ a1, const float* __restrict__ a2,
                        float* __restrict__ s1, float* __restrict__ s2, int nheads)
{
    int row = blockIdx.x * 8 + (threadIdx.x >> 5);
    int lane = threadIdx.x & 31;
    int head = (row / Nn) % nheads;
    const __nv_bfloat16* rp = rows + (size_t)row * Dd;
    const float* a1p = a1 + head * Dd;
    const float* a2p = a2 + head * Dd;
    float u = 0.f, v = 0.f;
    for (int e = lane; e < Dd; e += 32) {
        float rv = __bfloat162float(rp[e]) + __bfloat162float(rp[plane + e]);
        u += rv * a1p[e];
        v += rv * a2p[e];
    }
    #pragma unroll
    for (int o = 16; o; o >>= 1) {
        u += __shfl_xor_sync(0xffffffffu, u, o);
        v += __shfl_xor_sync(0xffffffffu, v, o);
    }
    if (lane == 0) { s1[row] = u; s2[row] = v; }
}

__global__ void k_softmax_gat(const float* __restrict__ s1, const float* __restrict__ s2,
                              const uint8_t* __restrict__ connect, __nv_bfloat16* __restrict__ attn,
                              int nheads)
{
    __shared__ float s2row[Nn];
    __shared__ float r8[8];
    int z = blockIdx.y;
    int b = z / nheads;
    int t = threadIdx.x;
    int wid = t >> 5, lane = t & 31;
    #pragma unroll
    for (int k = 0; k < 4; k++) s2row[t + k * 256] = s2[(size_t)z * Nn + t + k * 256];
    __syncthreads();
    #pragma unroll
    for (int r = 0; r < 4; r++) {
        int i = blockIdx.x * 4 + r;
        const uint8_t* con = connect + (size_t)b * NNt + (size_t)i * Nn;
        float s1v = s1[(size_t)z * Nn + i];
        float v[4];
        float mx = -INFINITY;
        #pragma unroll
        for (int k = 0; k < 4; k++) {
            int j = t + k * 256;
            float e = s1v + s2row[j];
            e = (e >= 0.f) ? e : 0.2f * e;
            v[k] = con[j] ? e : -9.0e15f;
            mx = fmaxf(mx, v[k]);
        }
        mx = bred<true>(mx, r8, wid, lane);
        float sum = 0.f;
        #pragma unroll
        for (int k = 0; k < 4; k++) { v[k] = expf(v[k] - mx); sum += v[k]; }
        sum = bred<false>(sum, r8, wid, lane);
        float inv = 1.f / sum;
        __nv_bfloat16* out = attn + (size_t)z * NNt + (size_t)i * Nn;
        #pragma unroll
        for (int k = 0; k < 4; k++) out[t + k * 256] = __float2bfloat16(v[k] * inv);
        __syncthreads();
    }
}

__global__ void k_ln(const float* __restrict__ in, const float* __restrict__ g,
                     const float* __restrict__ bb, __nv_bfloat16* __restrict__ out, long oplane)
{
    int row = blockIdx.x * 8 + (threadIdx.x >> 5);
    int lane = threadIdx.x & 31;
    size_t base = (size_t)row * Dd;
    float vbuf[8];
    float s = 0.f, sq = 0.f;
    #pragma unroll
    for (int k = 0; k < 8; k++) {
        float x = in[base + lane + k * 32];
        vbuf[k] = x; s += x; sq += x * x;
    }
    #pragma unroll
    for (int o = 16; o; o >>= 1) {
        s += __shfl_xor_sync(0xffffffffu, s, o);
        sq += __shfl_xor_sync(0xffffffffu, sq, o);
    }
    float mean = s * (1.f / Dd);
    float var = sq * (1.f / Dd) - mean * mean;
    float rstd = rsqrtf(var + 1e-5f);
    #pragma unroll
    for (int k = 0; k < 8; k++) {
        int d = lane + k * 32;
        float y = (vbuf[k] - mean) * rstd * g[d] + bb[d];
        __nv_bfloat16 h, l; split1(y, h, l);
        out[base + d] = h; out[oplane + base + d] = l;
    }
}

__global__ void k_qfull_ln(const __nv_bfloat16* __restrict__ gout, long gplane,
                           const float* __restrict__ pe,
                           const float* __restrict__ sel, const float* __restrict__ g,
                           const float* __restrict__ bb, __nv_bfloat16* __restrict__ out, long oplane)
{
    int row = blockIdx.x * 8 + (threadIdx.x >> 5);
    int lane = threadIdx.x & 31;
    int n = row % Nn;
    size_t base = (size_t)row * Dd;
    float selv = sel[row];
    float vbuf[8];
    float s = 0.f, sq = 0.f;
    #pragma unroll
    for (int k = 0; k < 8; k++) {
        int d = lane + k * 32;
        float gv = __bfloat162float(gout[base + d]) + __bfloat162float(gout[gplane + base + d]);
        float x = (selv > 0.5f) ? (gv + pe[(size_t)n * Dd + d]) : 0.f;
        vbuf[k] = x; s += x; sq += x * x;
    }
    #pragma unroll
    for (int o = 16; o; o >>= 1) {
        s += __shfl_xor_sync(0xffffffffu, s, o);
        sq += __shfl_xor_sync(0xffffffffu, sq, o);
    }
    float mean = s * (1.f / Dd);
    float var = sq * (1.f / Dd) - mean * mean;
    float rstd = rsqrtf(var + 1e-5f);
    #pragma unroll
    for (int k = 0; k < 8; k++) {
        int d = lane + k * 32;
        float y = (vbuf[k] - mean) * rstd * g[d] + bb[d];
        __nv_bfloat16 h, l; split1(y, h, l);
        out[base + d] = h; out[oplane + base + d] = l;
    }
}

// ---------------- launch ----------------
#define GETSYM(p, T, s) do { void* _t; cudaGetSymbolAddress(&_t, s); p = (T*)_t; } while (0)
#define SMEMSZ(BM, BN, NA) ((2 * (NA) * (BM) + 4 * (BN)) * ROWB)

extern "C" void kernel_launch(void* const* d_in, const int* in_sizes, int n_in,
                              void* d_out, int out_size)
{
    const float* x      = (const float*)d_in[0];
    const int*   mask   = (const int*)  d_in[1];
    const float* pe     = (const float*)d_in[2];
    const float* simWx  = (const float*)d_in[3];
    const float* simWq  = (const float*)d_in[4];
    const float* adjW   = (const float*)d_in[5];
    const float* gatW   = (const float*)d_in[6];
    const float* gatA1  = (const float*)d_in[7];
    const float* gatA2  = (const float*)d_in[8];
    const float* gatWo  = (const float*)d_in[9];
    const float* gatAo1 = (const float*)d_in[10];
    const float* gatAo2 = (const float*)d_in[11];
    const float* ln3g   = (const float*)d_in[12];
    const float* ln3b   = (const float*)d_in[13];
    const float* ln4g   = (const float*)d_in[14];
    const float* ln4b   = (const float*)d_in[15];
    const float* caWq   = (const float*)d_in[16];
    const float* caWk   = (const float*)d_in[17];
    const float* caWv   = (const float*)d_in[18];
    const float* caWp   = (const float*)d_in[19];
    const float* gamma  = (const float*)d_in[20];
    (void)in_sizes; (void)n_in; (void)out_size;

    float* out = (float*)d_out;
    float* possim_out = out + (size_t)Bz * Nn * Dd;

    float *posq, *pqpart, *pqcnt, *qsv, *w, *sel, *s1, *s2, *so1, *so2;
    uint8_t* connect;
    __nv_bfloat16 *attn_bf, *attno_bf;
    __nv_bfloat16 *x2, *fa2, *Wh2, *WhT2, *cat2, *Who2, *WhoT2, *gout2, *qx2, *kv2;
    __nv_bfloat16 *q2, *k2, *vT2, *o2;
    __nv_bfloat16 *adjWT2, *gatWT2, *WoT2, *caWqT2, *caWkT2, *caWvT2, *caWpT2;
    GETSYM(posq, float, g_posq);   GETSYM(pqpart, float, g_pqpart); GETSYM(pqcnt, float, g_pqcnt);
    GETSYM(qsv, float, g_qs);      GETSYM(w, float, g_w);       GETSYM(sel, float, g_sel);
    GETSYM(connect, uint8_t, g_connect);
    GETSYM(s1, float, g_s1);       GETSYM(s2, float, g_s2);
    GETSYM(so1, float, g_so1);     GETSYM(so2, float, g_so2);
    GETSYM(attn_bf, __nv_bfloat16, g_attn_bf);
    GETSYM(attno_bf, __nv_bfloat16, g_attno_bf);
    GETSYM(x2, __nv_bfloat16, g_x2);     GETSYM(fa2, __nv_bfloat16, g_fa2);
    GETSYM(Wh2, __nv_bfloat16, g_Wh2);   GETSYM(WhT2, __nv_bfloat16, g_WhT2);
    GETSYM(cat2, __nv_bfloat16, g_cat2);
    GETSYM(Who2, __nv_bfloat16, g_Who2); GETSYM(WhoT2, __nv_bfloat16, g_WhoT2);
    GETSYM(gout2, __nv_bfloat16, g_gout2);
    GETSYM(qx2, __nv_bfloat16, g_qx2);   GETSYM(kv2, __nv_bfloat16, g_kv2);
    GETSYM(q2, __nv_bfloat16, g_q2);     GETSYM(k2, __nv_bfloat16, g_k2);
    GETSYM(vT2, __nv_bfloat16, g_vT2);   GETSYM(o2, __nv_bfloat16, g_o2);
    GETSYM(adjWT2, __nv_bfloat16, g_adjWT2); GETSYM(gatWT2, __nv_bfloat16, g_gatWT2);
    GETSYM(WoT2, __nv_bfloat16, g_WoT2);
    GETSYM(caWqT2, __nv_bfloat16, g_caWqT2); GETSYM(caWkT2, __nv_bfloat16, g_caWkT2);
    GETSYM(caWvT2, __nv_bfloat16, g_caWvT2); GETSYM(caWpT2, __nv_bfloat16, g_caWpT2);

    const long PL_BND  = (long)Bz * ND;
    const long PL_BHND = (long)Bz * Hh * ND;
    const long PL_CAT  = (long)Bz * Nn * HD;
    const long PL_DD   = (long)Dd * Dd;
    const long PL_GATW = (long)Hh * Dd * Dd;
    const long PL_WO   = (long)HD * Dd;

    const int SM_22 = SMEMSZ(128, 128, 2);
    const int SM_12 = SMEMSZ(128, 128, 1);
    cudaFuncSetAttribute(mma_gemm<128,128,2,4,EPI_NONE,   2,OUT_PLANES, false>, cudaFuncAttributeMaxDynamicSharedMemorySize, SM_22);
    cudaFuncSetAttribute(mma_gemm<128,128,2,4,EPI_NONE,   2,OUT_PLANES, true >, cudaFuncAttributeMaxDynamicSharedMemorySize, SM_22);
    cudaFuncSetAttribute(mma_gemm<128,128,2,4,EPI_CONNECT,2,OUT_CONNECT,false>, cudaFuncAttributeMaxDynamicSharedMemorySize, SM_22);
    cudaFuncSetAttribute(mma_gemm<128,128,2,4,EPI_NONE,   2,OUT_NONE,   true >, cudaFuncAttributeMaxDynamicSharedMemorySize, SM_22);
    cudaFuncSetAttribute(mma_gemm<128,128,2,4,EPI_RESID,  2,OUT_F32,    false>, cudaFuncAttributeMaxDynamicSharedMemorySize, SM_22);
    cudaFuncSetAttribute(mma_gemm<128,128,2,4,EPI_ELU,    1,OUT_PLANES, false>, cudaFuncAttributeMaxDynamicSharedMemorySize, SM_12);
    cudaFuncSetAttribute(k_flash_ca, cudaFuncAttributeMaxDynamicSharedMemorySize, FCA_SMEM);

    const long zero = 0;
    cudaStream_t s0 = 0;
    cudaStream_t sA = hx.s1;
    cudaStream_t sB = hx.s2;

    // fork
    cudaEventRecord(hx.e0, s0);
    cudaStreamWaitEvent(sA, hx.e0, 0);
    cudaStreamWaitEvent(sB, hx.e0, 0);

    // stream B: weight transposes -> LN3 -> q projection
    k_transpose_all<<<1344, dim3(32, 8), 0, sB>>>(adjW, adjWT2, caWq, caWqT2, caWk, caWkT2,
                                                  caWv, caWvT2, caWp, caWpT2, gatW, gatWT2, gatWo, WoT2);
    cudaEventRecord(hx.eT, sB);
    k_ln<<<Bz * Nn / 8, 256, 0, sB>>>(x, ln3g, ln3b, qx2, PL_BND);

    // stream 0: split x
    k_split<<<Bz * ND / 1024, 256, 0, s0>>>(x, x2, PL_BND);
    cudaEventRecord(hx.eX, s0);

    // stream B: q = qx @ caWq
    mma_gemm<128,128,2,4,EPI_NONE,2,OUT_PLANES,false><<<dim3(2, 64, 1), 256, SM_22, sB>>>(
        qx2, PL_BND, caWqT2, PL_DD, q2, PL_BND,
        Dd, Dd, Dd, Dd, 1, zero, zero, zero, zero, zero, zero,
        nullptr, zero, nullptr, nullptr, zero, zero, zero, 0);
    cudaEventRecord(hx.eQ, sB);

    // stream A: selection path, then fa -> connect
    k_posquery1<<<dim3(16, Bz), 256, 0, sA>>>(x, mask, pqpart, pqcnt);
    k_posquery2<<<Bz, 256, 0, sA>>>(pqpart, pqcnt, posq);
    k_mv1<<<dim3(8, Bz), 256, 0, sA>>>(simWq, posq, qsv);
    k_mv2<<<dim3(32, Bz), 256, 0, sA>>>(simWx, qsv, w);
    k_possim<<<Bz * Nn / 8, 256, 0, sA>>>(x, w, possim_out, sel);
    cudaStreamWaitEvent(sA, hx.eX, 0);
    cudaStreamWaitEvent(sA, hx.eT, 0);
    mma_gemm<128,128,2,4,EPI_NONE,2,OUT_PLANES,false><<<dim3(2, 64, 1), 256, SM_22, sA>>>(
        x2, PL_BND, adjWT2, PL_DD, fa2, PL_BND,
        Dd, Dd, Dd, Dd, 1, zero, zero, zero, zero, zero, zero,
        nullptr, zero, nullptr, nullptr, zero, zero, zero, 0);
    mma_gemm<128,128,2,4,EPI_CONNECT,2,OUT_CONNECT,false><<<dim3(8, 8, Bz), 256, SM_22, sA>>>(
        fa2, PL_BND, fa2, PL_BND, connect, zero,
        Dd, Dd, Dd, Nn, 1, (long)ND, zero, (long)ND, zero, (long)NNt, zero,
        sel, (long)Nn, nullptr, nullptr, zero, zero, zero, 0);
    cudaEventRecord(hx.eConn, sA);

    // stream 0: main chain
    cudaStreamWaitEvent(s0, hx.eT, 0);

    mma_gemm<128,128,2,4,EPI_NONE,2,OUT_PLANES,true><<<dim3(2, 8, Bz * Hh), 256, SM_22, s0>>>(
        x2, PL_BND, gatWT2, PL_GATW, Wh2, PL_BHND,
        Dd, Dd, Dd, Dd, Hh, (long)ND, zero, zero, (long)Dd * Dd,
        (long)Hh * ND, (long)ND,
        nullptr, zero, nullptr, WhT2, PL_BHND, (long)Hh * ND, (long)ND, Nn);

    k_dot2p<<<Bz * Hh * Nn / 8, 256, 0, s0>>>(Wh2, PL_BHND, gatA1, gatA2, s1, s2, Hh);

    cudaStreamWaitEvent(s0, hx.eConn, 0);
    k_softmax_gat<<<dim3(Nn / 4, Bz * Hh), 256, 0, s0>>>(s1, s2, connect, attn_bf, Hh);

    mma_gemm<128,128,2,4,EPI_ELU,1,OUT_PLANES,false><<<dim3(2, 8, Bz * Hh), 256, SM_12, s0>>>(
        attn_bf, zero, WhT2, PL_BHND, cat2, PL_CAT,
        Nn, Nn, Nn, HD, Hh, (long)Hh * NNt, (long)NNt, (long)Hh * ND, (long)ND,
        (long)Nn * HD, (long)Dd,
        nullptr, zero, nullptr, nullptr, zero, zero, zero, 0);

    mma_gemm<128,128,2,4,EPI_NONE,2,OUT_PLANES,true><<<dim3(2, 8, Bz), 256, SM_22, s0>>>(
        cat2, PL_CAT, WoT2, PL_WO, Who2, PL_BND,
        HD, HD, HD, Dd, 1, (long)Nn * HD, zero, zero, zero, (long)ND, zero,
        nullptr, zero, nullptr, WhoT2, PL_BND, (long)ND, zero, Nn);

    k_dot2p<<<Bz * Nn / 8, 256, 0, s0>>>(Who2, PL_BND, gatAo1, gatAo2, so1, so2, 1);
    k_softmax_gat<<<dim3(Nn / 4, Bz), 256, 0, s0>>>(so1, so2, connect, attno_bf, 1);

    mma_gemm<128,128,2,4,EPI_ELU,1,OUT_PLANES,false><<<dim3(2, 8, Bz), 256, SM_12, s0>>>(
        attno_bf, zero, WhoT2, PL_BND, gout2, PL_BND,
        Nn, Nn, Nn, Dd, 1, (long)NNt, zero, (long)ND, zero, (long)ND, zero,
        nullptr, zero, nullptr, nullptr, zero, zero, zero, 0);

    k_qfull_ln<<<Bz * Nn / 8, 256, 0, s0>>>(gout2, PL_BND, pe, sel, ln4g, ln4b, kv2, PL_BND);
    cudaEventRecord(hx.eKV, s0);

    // stream B: k projection (parallel with vT on s0)
    cudaStreamWaitEvent(sB, hx.eKV, 0);
    mma_gemm<128,128,2,4,EPI_NONE,2,OUT_PLANES,false><<<dim3(2, 64, 1), 256, SM_22, sB>>>(
        kv2, PL_BND, caWkT2, PL_DD, k2, PL_BND,
        Dd, Dd, Dd, Dd, 1, zero, zero, zero, zero, zero, zero,
        nullptr, zero, nullptr, nullptr, zero, zero, zero, 0);
    cudaEventRecord(hx.eK, sB);

    // stream 0: v projection (transposed planes only)
    mma_gemm<128,128,2,4,EPI_NONE,2,OUT_NONE,true><<<dim3(2, 8, Bz), 256, SM_22, s0>>>(
        kv2, PL_BND, caWvT2, PL_DD, nullptr, zero,
        Dd, Dd, Dd, Dd, 1, (long)ND, zero, zero, zero, (long)ND, zero,
        nullptr, zero, nullptr, vT2, PL_BND, (long)ND, zero, Nn);

    // fused flash CA: needs q2 (eQ), k2 (eK), vT2 (s0)
    cudaStreamWaitEvent(s0, hx.eQ, 0);
    cudaStreamWaitEvent(s0, hx.eK, 0);
    k_flash_ca<<<dim3(Nn / 128, Bz * HC), 256, FCA_SMEM, s0>>>(
        q2, k2, vT2, sel, o2, PL_BND);

    // out = x + gamma * (o @ caWp)
    mma_gemm<128,128,2,4,EPI_RESID,2,OUT_F32,false><<<dim3(2, 64, 1), 256, SM_22, s0>>>(
        o2, PL_BND, caWpT2, PL_DD, out, zero,
        Dd, Dd, Dd, Dd, 1, zero, zero, zero, zero, zero, zero,
        x, zero, gamma, nullptr, zero, zero, zero, 0);
}

// round 11
// speedup vs baseline: 1.4178x; 1.0024x over previous
#include <cuda_runtime.h>
#include <cuda_bf16.h>
#include <math.h>
#include <stdint.h>

// Problem constants
#define Bz 8
#define Nn 1024
#define Dd 256
#define Hh 8
#define HC 4
#define DH 64
#define HD 2048                 // Hh*Dd
#define ND (Nn*Dd)              // 262144
#define NNt ((size_t)Nn*Nn)     // 1048576

// ---------------- scratch (device globals) ----------------
__device__ float g_posq[Bz*Dd];
__device__ float g_pqpart[Bz*16*Dd];
__device__ float g_pqcnt[Bz*16];
__device__ float g_qs[Bz*Dd];
__device__ float g_w[Bz*Dd];
__device__ float g_sel[Bz*Nn];
__device__ uint8_t g_connect[(size_t)Bz*Nn*Nn];
__device__ float g_s1[Bz*Hh*Nn];
__device__ float g_s2[Bz*Hh*Nn];
__device__ float g_so1[Bz*Nn];
__device__ float g_so2[Bz*Nn];
__device__ __nv_bfloat16 g_attn_bf[(size_t)Bz*Hh*Nn*Nn];   // GAT probs
__device__ __nv_bfloat16 g_attno_bf[(size_t)Bz*Nn*Nn];

__device__ __nv_bfloat16 g_x2[2*(size_t)Bz*ND];
__device__ __nv_bfloat16 g_fa2[2*(size_t)Bz*ND];
__device__ __nv_bfloat16 g_Wh2[2*(size_t)Bz*Hh*ND];
__device__ __nv_bfloat16 g_WhT2[2*(size_t)Bz*Hh*ND];
__device__ __nv_bfloat16 g_cat2[2*(size_t)Bz*Nn*HD];
__device__ __nv_bfloat16 g_Who2[2*(size_t)Bz*ND];
__device__ __nv_bfloat16 g_WhoT2[2*(size_t)Bz*ND];
__device__ __nv_bfloat16 g_gout2[2*(size_t)Bz*ND];
__device__ __nv_bfloat16 g_qx2[2*(size_t)Bz*ND];
__device__ __nv_bfloat16 g_kv2[2*(size_t)Bz*ND];
__device__ __nv_bfloat16 g_q2[2*(size_t)Bz*ND];
__device__ __nv_bfloat16 g_k2[2*(size_t)Bz*ND];
__device__ __nv_bfloat16 g_vT2[2*(size_t)Bz*ND];
__device__ __nv_bfloat16 g_o2[2*(size_t)Bz*ND];
// transposed weights (planes)
__device__ __nv_bfloat16 g_adjWT2[2*Dd*Dd];
__device__ __nv_bfloat16 g_gatWT2[2*Hh*Dd*Dd];
__device__ __nv_bfloat16 g_WoT2[2*HD*Dd];
__device__ __nv_bfloat16 g_caWqT2[2*Dd*Dd];
__device__ __nv_bfloat16 g_caWkT2[2*Dd*Dd];
__device__ __nv_bfloat16 g_caWvT2[2*Dd*Dd];
__device__ __nv_bfloat16 g_caWpT2[2*Dd*Dd];

// ---------------- streams/events ----------------
struct HXStreams {
    cudaStream_t s1, s2;
    cudaEvent_t e0, eT, eX, eConn, eQ, eKV, eK;
    HXStreams() {
        cudaStreamCreateWithFlags(&s1, cudaStreamNonBlocking);
        cudaStreamCreateWithFlags(&s2, cudaStreamNonBlocking);
        cudaEventCreateWithFlags(&e0, cudaEventDisableTiming);
        cudaEventCreateWithFlags(&eT, cudaEventDisableTiming);
        cudaEventCreateWithFlags(&eX, cudaEventDisableTiming);
        cudaEventCreateWithFlags(&eConn, cudaEventDisableTiming);
        cudaEventCreateWithFlags(&eQ, cudaEventDisableTiming);
        cudaEventCreateWithFlags(&eKV, cudaEventDisableTiming);
        cudaEventCreateWithFlags(&eK, cudaEventDisableTiming);
    }
};
static HXStreams hx;

// ---------------- low-level helpers ----------------
__device__ __forceinline__ uint32_t smem_u32(const void* p) {
    uint32_t a;
    asm("{ .reg .u64 t; cvta.to.shared.u64 t, %1; cvt.u32.u64 %0, t; }" : "=r"(a) : "l"(p));
    return a;
}
__device__ __forceinline__ void ldsm4(uint32_t* r, uint32_t addr) {
    asm volatile("ldmatrix.sync.aligned.m8n8.x4.shared.b16 {%0,%1,%2,%3}, [%4];"
        : "=r"(r[0]), "=r"(r[1]), "=r"(r[2]), "=r"(r[3]) : "r"(addr));
}
__device__ __forceinline__ void mma16816(float* c, const uint32_t* a, const uint32_t* b) {
    asm volatile("mma.sync.aligned.m16n8k16.row.col.f32.bf16.bf16.f32 "
        "{%0,%1,%2,%3}, {%4,%5,%6,%7}, {%8,%9}, {%0,%1,%2,%3};"
        : "+f"(c[0]), "+f"(c[1]), "+f"(c[2]), "+f"(c[3])
        : "r"(a[0]), "r"(a[1]), "r"(a[2]), "r"(a[3]), "r"(b[0]), "r"(b[1]));
}
__device__ __forceinline__ void split1(float v, __nv_bfloat16& h, __nv_bfloat16& l) {
    h = __float2bfloat16(v);
    l = __float2bfloat16(v - __bfloat162float(h));
}
__device__ __forceinline__ uint32_t pack2(__nv_bfloat16 a, __nv_bfloat16 b) {
    return (uint32_t)__bfloat16_as_ushort(a) | ((uint32_t)__bfloat16_as_ushort(b) << 16);
}
__device__ __forceinline__ uint32_t packf2(float a, float b) {
    uint32_t r;
    asm("cvt.rn.bf16x2.f32 %0, %1, %2;" : "=r"(r) : "f"(b), "f"(a));
    return r;
}
#define CP16(dst, src) \
    asm volatile("cp.async.cg.shared.global [%0], [%1], 16;" :: "r"(dst), "l"(src))
#define CP_COMMIT() asm volatile("cp.async.commit_group;" ::: "memory")

template <bool MAX>
__device__ __forceinline__ float bred(float v, float* r8, int wid, int lane) {
    #pragma unroll
    for (int o = 16; o; o >>= 1) {
        float u = __shfl_xor_sync(0xffffffffu, v, o);
        v = MAX ? fmaxf(v, u) : (v + u);
    }
    if (lane == 0) r8[wid] = v;
    __syncthreads();
    if (wid == 0) {
        float u = r8[lane & 7];
        #pragma unroll
        for (int o = 4; o; o >>= 1) {
            float t = __shfl_xor_sync(0xffffffffu, u, o);
            u = MAX ? fmaxf(u, t) : (u + t);
        }
        if (lane == 0) r8[0] = u;
    }
    __syncthreads();
    return r8[0];
}

// ---------------- split x into planes ----------------
__global__ void k_split(const float* __restrict__ in, __nv_bfloat16* __restrict__ outp, long plane)
{
    int i = blockIdx.x * 256 + threadIdx.x;
    float4 v = reinterpret_cast<const float4*>(in)[i];
    __nv_bfloat16 h0, l0, h1, l1, h2, l2, h3, l3;
    split1(v.x, h0, l0); split1(v.y, h1, l1); split1(v.z, h2, l2); split1(v.w, h3, l3);
    reinterpret_cast<uint2*>(outp)[i] = make_uint2(pack2(h0, h1), pack2(h2, h3));
    reinterpret_cast<uint2*>(outp + plane)[i] = make_uint2(pack2(l0, l1), pack2(l2, l3));
}

// ---------------- merged transpose kernel ----------------
__global__ void k_transpose_all(const float* adjW, __nv_bfloat16* adjWT,
                                const float* caWq, __nv_bfloat16* caWqT,
                                const float* caWk, __nv_bfloat16* caWkT,
                                const float* caWv, __nv_bfloat16* caWvT,
                                const float* caWp, __nv_bfloat16* caWpT,
                                const float* gatW, __nv_bfloat16* gatWT,
                                const float* gatWo, __nv_bfloat16* WoT)
{
    __shared__ float t[32][33];
    int id = blockIdx.x;
    int tx = threadIdx.x, ty = threadIdx.y;
    const float* src; __nv_bfloat16* dh; long plane; int R, C, bx, by;
    if (id < 320) {
        const float* srcs[5] = {adjW, caWq, caWk, caWv, caWp};
        __nv_bfloat16* dsts[5] = {adjWT, caWqT, caWkT, caWvT, caWpT};
        int m = id >> 6, l = id & 63;
        src = srcs[m]; dh = dsts[m]; plane = Dd * Dd;
        R = Dd; C = Dd; bx = (l & 7) * 32; by = (l >> 3) * 32;
    } else if (id < 832) {
        int l = id - 320; int z = l >> 6; l &= 63;
        src = gatW + (size_t)z * Dd * Dd; dh = gatWT + (size_t)z * Dd * Dd;
        plane = (long)Hh * Dd * Dd;
        R = Dd; C = Dd; bx = (l & 7) * 32; by = (l >> 3) * 32;
    } else {
        int l = id - 832;
        src = gatWo; dh = WoT; plane = (long)HD * Dd;
        R = HD; C = Dd; bx = (l & 7) * 32; by = (l >> 3) * 32;
    }
    #pragma unroll
    for (int i = 0; i < 32; i += 8)
        t[ty + i][tx] = src[(size_t)(by + ty + i) * C + bx + tx];
    __syncthreads();
    #pragma unroll
    for (int i = 0; i < 32; i += 8) {
        float v = t[tx][ty + i];
        __nv_bfloat16 h, l2;
        split1(v, h, l2);
        size_t o = (size_t)(bx + ty + i) * R + by + tx;
        dh[o] = h; dh[plane + o] = l2;
    }
}

// ---------------- plane-pair bf16 mma.sync NT GEMM ----------------
enum { EPI_NONE = 0, EPI_ELU = 1, EPI_CONNECT = 2, EPI_RESID = 3 };
enum { OUT_F32 = 0, OUT_PLANES = 1, OUT_CONNECT = 2, OUT_NONE = 3 };
#define ROWB 80

template <int BM, int BN, int WM, int WN, int EPI, int NA, int OUT, bool DUAL, int ST>
__global__ void __launch_bounds__(256, 2)
mma_gemm(const __nv_bfloat16* __restrict__ A, long aPlane,
         const __nv_bfloat16* __restrict__ Bm, long bPlane,
         void* __restrict__ Cv, long cPlane,
         int K, int lda, int ldb, int ldc, int zInner,
         long sAb, long sAi, long sBb, long sBi, long sCb, long sCi,
         const float* __restrict__ e1, long sE1b, const float* __restrict__ e2,
         __nv_bfloat16* __restrict__ Ct, long ctPlane, long sCtb, long sCti, int ldct)
{
    constexpr int ABYTES = BM * ROWB;
    constexpr int BBYTES = BN * ROWB;
    constexpr int STR = BM + 8;
    constexpr int STGPL = BN * STR;

    extern __shared__ char smem[];
    const uint32_t sb = smem_u32(smem);

    const int tid = threadIdx.x;
    const int wid = tid >> 5;
    const int lane = tid & 31;

    const int z = blockIdx.z;
    const int zb = z / zInner, zi = z % zInner;
    const __nv_bfloat16* Ap = A + (size_t)zb * sAb + (size_t)zi * sAi;
    const __nv_bfloat16* Bp = Bm + (size_t)zb * sBb + (size_t)zi * sBi;
    float* Cpf = (float*)Cv + (size_t)zb * sCb + (size_t)zi * sCi;
    __nv_bfloat16* Cpb = (__nv_bfloat16*)Cv + (size_t)zb * sCb + (size_t)zi * sCi;
    uint8_t* Cp8 = (uint8_t*)Cv + (size_t)zb * sCb + (size_t)zi * sCi;
    const float* e1p = e1 ? (e1 + (size_t)zb * sE1b) : nullptr;

    const int m0 = blockIdx.y * BM;
    const int n0 = blockIdx.x * BN;

    const int crow = tid >> 2;
    const int cch = tid & 3;

    const int wid_m = wid % WM;
    const int wid_n = wid / WM;
    const int g = lane >> 3, rl = lane & 7;
    const int aRowBase = wid_m * 64 + (g & 1) * 8 + rl;
    const int aKsel = (g >> 1) * 8;
    const int bRowBase = wid_n * 32 + (g >> 1) * 8 + rl;
    const int bKsel = (g & 1) * 8;

    float acc[4][4][4] = {};
    const int nkt = K >> 5;
    const uint32_t bbase = ST * NA * ABYTES;

    auto copyTile = [&](int kk, int stage) {
        #pragma unroll
        for (int pl = 0; pl < NA; pl++) {
            const __nv_bfloat16* src = Ap + (size_t)pl * aPlane;
            uint32_t dst0 = sb + (stage * NA + pl) * ABYTES;
            #pragma unroll
            for (int i = 0; i < BM / 64; i++) {
                int row = crow + 64 * i;
                CP16(dst0 + row * ROWB + cch * 16,
                     src + (size_t)(m0 + row) * lda + kk + cch * 8);
            }
        }
        #pragma unroll
        for (int pl = 0; pl < 2; pl++) {
            const __nv_bfloat16* src = Bp + (size_t)pl * bPlane;
            uint32_t dst0 = sb + bbase + (stage * 2 + pl) * BBYTES;
            #pragma unroll
            for (int i = 0; i < BN / 64; i++) {
                int row = crow + 64 * i;
                CP16(dst0 + row * ROWB + cch * 16,
                     src + (size_t)(n0 + row) * ldb + kk + cch * 8);
            }
        }
    };

    copyTile(0, 0); CP_COMMIT();
    if (ST == 3 && nkt > 1) { copyTile(32, 1); CP_COMMIT(); }

    for (int kt = 0; kt < nkt; kt++) {
        const int stage = (ST == 2) ? (kt & 1) : (kt % 3);
        if (ST == 2) {
            const bool more = (kt + 1 < nkt);
            if (more) { copyTile((kt + 1) << 5, (kt + 1) & 1); CP_COMMIT(); }
            if (more) asm volatile("cp.async.wait_group 1;" ::: "memory");
            else      asm volatile("cp.async.wait_group 0;" ::: "memory");
        } else {
            if (kt + 2 < nkt) { copyTile((kt + 2) << 5, (kt + 2) % 3); CP_COMMIT(); }
            if (kt + 2 < nkt)      asm volatile("cp.async.wait_group 2;" ::: "memory");
            else if (kt + 1 < nkt) asm volatile("cp.async.wait_group 1;" ::: "memory");
            else                   asm volatile("cp.async.wait_group 0;" ::: "memory");
        }
        __syncthreads();

        const uint32_t sAhi = sb + stage * NA * ABYTES;
        const uint32_t sAlo = sAhi + ABYTES;
        const uint32_t sBhi = sb + bbase + stage * 2 * BBYTES;
        const uint32_t sBlo = sBhi + BBYTES;

        #pragma unroll
        for (int j = 0; j < 2; j++) {
            const int kb = j * 16;
            uint32_t a[4][4], bh[4][2], bl[4][2];
            #pragma unroll
            for (int im = 0; im < 4; im++)
                ldsm4(a[im], sAhi + (uint32_t)((aRowBase + im * 16) * ROWB + (kb + aKsel) * 2));
            #pragma unroll
            for (int i2 = 0; i2 < 2; i2++) {
                uint32_t t[4];
                ldsm4(t, sBhi + (uint32_t)((bRowBase + i2 * 16) * ROWB + (kb + bKsel) * 2));
                bh[2 * i2][0] = t[0]; bh[2 * i2][1] = t[1];
                bh[2 * i2 + 1][0] = t[2]; bh[2 * i2 + 1][1] = t[3];
            }
            #pragma unroll
            for (int im = 0; im < 4; im++)
                #pragma unroll
                for (int in = 0; in < 4; in++)
                    mma16816(acc[im][in], a[im], bh[in]);
            #pragma unroll
            for (int i2 = 0; i2 < 2; i2++) {
                uint32_t t[4];
                ldsm4(t, sBlo + (uint32_t)((bRowBase + i2 * 16) * ROWB + (kb + bKsel) * 2));
                bl[2 * i2][0] = t[0]; bl[2 * i2][1] = t[1];
                bl[2 * i2 + 1][0] = t[2]; bl[2 * i2 + 1][1] = t[3];
            }
            #pragma unroll
            for (int im = 0; im < 4; im++)
                #pragma unroll
                for (int in = 0; in < 4; in++)
                    mma16816(acc[im][in], a[im], bl[in]);
            if (NA == 2) {
                #pragma unroll
                for (int im = 0; im < 4; im++)
                    ldsm4(a[im], sAlo + (uint32_t)((aRowBase + im * 16) * ROWB + (kb + aKsel) * 2));
                #pragma unroll
                for (int im = 0; im < 4; im++)
                    #pragma unroll
                    for (int in = 0; in < 4; in++)
                        mma16816(acc[im][in], a[im], bh[in]);
            }
        }
        __syncthreads();
    }

    // epilogue
    __nv_bfloat16* stg = reinterpret_cast<__nv_bfloat16*>(smem);
    const int mw = m0 + wid_m * 64;
    const int nw = n0 + wid_n * 32;
    #pragma unroll
    for (int im = 0; im < 4; im++) {
        const int row = mw + im * 16 + (lane >> 2);
        const float sr0 = (EPI == EPI_CONNECT) ? e1p[row] : 0.f;
        const float sr1 = (EPI == EPI_CONNECT) ? e1p[row + 8] : 0.f;
        #pragma unroll
        for (int in = 0; in < 4; in++) {
            const int col = nw + in * 8 + (lane & 3) * 2;
            float v00 = acc[im][in][0], v01 = acc[im][in][1];
            float v10 = acc[im][in][2], v11 = acc[im][in][3];
            if (EPI == EPI_ELU) {
                v00 = v00 > 0.f ? v00 : expm1f(v00);
                v01 = v01 > 0.f ? v01 : expm1f(v01);
                v10 = v10 > 0.f ? v10 : expm1f(v10);
                v11 = v11 > 0.f ? v11 : expm1f(v11);
            } else if (EPI == EPI_RESID) {
                const float g0 = e2[col], g1 = e2[col + 1];
                const size_t r0 = (size_t)row * ldc + col;
                const size_t r1 = (size_t)(row + 8) * ldc + col;
                v00 = e1p[r0] + g0 * v00; v01 = e1p[r0 + 1] + g1 * v01;
                v10 = e1p[r1] + g0 * v10; v11 = e1p[r1 + 1] + g1 * v11;
            }
            const size_t o0 = (size_t)row * ldc + col;
            const size_t o1 = (size_t)(row + 8) * ldc + col;
            if (OUT == OUT_CONNECT) {
                const float sc0 = e1p[col], sc1 = e1p[col + 1];
                uchar2 c0, c1;
                c0.x = (v00 > 0.f && sr0 > 0.5f && sc0 > 0.5f) ? 1 : 0;
                c0.y = (v01 > 0.f && sr0 > 0.5f && sc1 > 0.5f) ? 1 : 0;
                c1.x = (v10 > 0.f && sr1 > 0.5f && sc0 > 0.5f) ? 1 : 0;
                c1.y = (v11 > 0.f && sr1 > 0.5f && sc1 > 0.5f) ? 1 : 0;
                *reinterpret_cast<uchar2*>(Cp8 + o0) = c0;
                *reinterpret_cast<uchar2*>(Cp8 + o1) = c1;
            } else if (OUT == OUT_F32) {
                *reinterpret_cast<float2*>(Cpf + o0) = make_float2(v00, v01);
                *reinterpret_cast<float2*>(Cpf + o1) = make_float2(v10, v11);
            }
            __nv_bfloat16 h00, l00, h01, l01, h10, l10, h11, l11;
            if (OUT == OUT_PLANES || DUAL) {
                split1(v00, h00, l00); split1(v01, h01, l01);
                split1(v10, h10, l10); split1(v11, h11, l11);
            }
            if (OUT == OUT_PLANES) {
                *reinterpret_cast<uint32_t*>(Cpb + o0) = pack2(h00, h01);
                *reinterpret_cast<uint32_t*>(Cpb + o1) = pack2(h10, h11);
                *reinterpret_cast<uint32_t*>(Cpb + cPlane + o0) = pack2(l00, l01);
                *reinterpret_cast<uint32_t*>(Cpb + cPlane + o1) = pack2(l10, l11);
            }
            if (DUAL) {
                const int cl = col - n0, rlc = row - m0;
                stg[cl * STR + rlc] = h00;
                stg[(cl + 1) * STR + rlc] = h01;
                stg[cl * STR + rlc + 8] = h10;
                stg[(cl + 1) * STR + rlc + 8] = h11;
                stg[STGPL + cl * STR + rlc] = l00;
                stg[STGPL + (cl + 1) * STR + rlc] = l01;
                stg[STGPL + cl * STR + rlc + 8] = l10;
                stg[STGPL + (cl + 1) * STR + rlc + 8] = l11;
            }
        }
    }
    if (DUAL) {
        __syncthreads();
        __nv_bfloat16* Ctp = Ct + (size_t)zb * sCtb + (size_t)zi * sCti;
        const int r = tid >> 1;
        const int hh = (tid & 1) * (BM / 2);
        #pragma unroll
        for (int p = 0; p < 2; p++) {
            const uint4* srow = reinterpret_cast<const uint4*>(stg + p * STGPL + r * STR + hh);
            uint4* drow = reinterpret_cast<uint4*>(Ctp + (size_t)p * ctPlane + (size_t)(n0 + r) * ldct + m0 + hh);
            #pragma unroll
            for (int i = 0; i < BM / 16; i++)
                drow[i] = srow[i];
        }
    }
}

// ---------------- fused flash cross-attention ----------------
#define QROWB 144
#define VROWB 272
#define QPLB (128*QROWB)
#define VPLB (64*VROWB)
#define FCA_SMEM (4*QPLB + 2*VPLB + 512)

__global__ void __launch_bounds__(256, 1)
k_flash_ca(const __nv_bfloat16* __restrict__ q2, const __nv_bfloat16* __restrict__ k2,
           const __nv_bfloat16* __restrict__ vT2, const float* __restrict__ sel,
           __nv_bfloat16* __restrict__ o2, long plane)
{
    extern __shared__ char smem[];
    const uint32_t sb = smem_u32(smem);
    const uint32_t Q0 = 0, K0 = 2 * QPLB, V0 = 4 * QPLB, SEL0 = 4 * QPLB + 2 * VPLB;
    const float* sel_s = reinterpret_cast<const float*>(smem + SEL0);

    const int tid = threadIdx.x, wid = tid >> 5, lane = tid & 31;
    const int b = blockIdx.y / HC, hc = blockIdx.y % HC;
    const int m0 = blockIdx.x * 128;

    const __nv_bfloat16* Qp = q2 + (size_t)b * ND + hc * DH;
    const __nv_bfloat16* Kp = k2 + (size_t)b * ND + hc * DH;
    const __nv_bfloat16* Vp = vT2 + (size_t)b * ND + (size_t)hc * DH * Nn;
    const float* selb = sel + b * Nn;

    {
        int row = tid >> 1, cb = (tid & 1) * 4;
        #pragma unroll
        for (int pl = 0; pl < 2; pl++)
            #pragma unroll
            for (int c = 0; c < 4; c++)
                CP16(sb + Q0 + pl * QPLB + row * QROWB + (cb + c) * 16,
                     Qp + (size_t)pl * plane + (size_t)(m0 + row) * Dd + (cb + c) * 8);
    }

    const int g = lane >> 3, rl = lane & 7;
    const int aRow = wid * 16 + (g & 1) * 8 + rl;
    const int aKs = (g >> 1) * 8;
    const int bRow = (g >> 1) * 8 + rl;
    const int bKs = (g & 1) * 8;
    const int q2c = (lane & 3) * 2;

    float O[8][4] = {};
    float mrow0 = -INFINITY, mrow1 = -INFINITY;
    float lrow0 = 0.f, lrow1 = 0.f;

    for (int kt = 0; kt < 8; kt++) {
        const int t0 = kt * 128;
        {
            int row = tid >> 1, cb = (tid & 1) * 4;
            #pragma unroll
            for (int pl = 0; pl < 2; pl++)
                #pragma unroll
                for (int c = 0; c < 4; c++)
                    CP16(sb + K0 + pl * QPLB + row * QROWB + (cb + c) * 16,
                         Kp + (size_t)pl * plane + (size_t)(t0 + row) * Dd + (cb + c) * 8);
            int vrow = tid >> 2, vcb = (tid & 3) * 4;
            #pragma unroll
            for (int pl = 0; pl < 2; pl++)
                #pragma unroll
                for (int c = 0; c < 4; c++)
                    CP16(sb + V0 + pl * VPLB + vrow * VROWB + (vcb + c) * 16,
                         Vp + (size_t)pl * plane + (size_t)vrow * Nn + t0 + (vcb + c) * 8);
            if (tid < 32)
                CP16(sb + SEL0 + tid * 16, selb + t0 + tid * 4);
        }
        CP_COMMIT();
        asm volatile("cp.async.wait_group 0;" ::: "memory");
        __syncthreads();

        float S[16][4];
        #pragma unroll
        for (int f = 0; f < 16; f++) { S[f][0] = S[f][1] = S[f][2] = S[f][3] = 0.f; }
        #pragma unroll
        for (int ks = 0; ks < 4; ks++) {
            uint32_t ah[4], al[4];
            ldsm4(ah, sb + Q0 + (uint32_t)(aRow * QROWB + (ks * 16 + aKs) * 2));
            ldsm4(al, sb + Q0 + QPLB + (uint32_t)(aRow * QROWB + (ks * 16 + aKs) * 2));
            #pragma unroll
            for (int nf2 = 0; nf2 < 8; nf2++) {
                uint32_t th[4], tl[4];
                ldsm4(th, sb + K0 + (uint32_t)((bRow + nf2 * 16) * QROWB + (ks * 16 + bKs) * 2));
                ldsm4(tl, sb + K0 + QPLB + (uint32_t)((bRow + nf2 * 16) * QROWB + (ks * 16 + bKs) * 2));
                uint32_t bh0[2] = {th[0], th[1]}, bh1[2] = {th[2], th[3]};
                uint32_t bl0[2] = {tl[0], tl[1]}, bl1[2] = {tl[2], tl[3]};
                mma16816(S[2 * nf2], ah, bh0);     mma16816(S[2 * nf2 + 1], ah, bh1);
                mma16816(S[2 * nf2], ah, bl0);     mma16816(S[2 * nf2 + 1], ah, bl1);
                mma16816(S[2 * nf2], al, bh0);     mma16816(S[2 * nf2 + 1], al, bh1);
            }
        }

        float mx0 = mrow0, mx1 = mrow1;
        #pragma unroll
        for (int f = 0; f < 16; f++) {
            int col = f * 8 + q2c;
            bool k0 = sel_s[col] > 0.5f, k1 = sel_s[col + 1] > 0.5f;
            S[f][0] = k0 ? S[f][0] * 0.125f : -1.0e9f;
            S[f][1] = k1 ? S[f][1] * 0.125f : -1.0e9f;
            S[f][2] = k0 ? S[f][2] * 0.125f : -1.0e9f;
            S[f][3] = k1 ? S[f][3] * 0.125f : -1.0e9f;
            mx0 = fmaxf(mx0, fmaxf(S[f][0], S[f][1]));
            mx1 = fmaxf(mx1, fmaxf(S[f][2], S[f][3]));
        }
        #pragma unroll
        for (int o = 1; o < 4; o <<= 1) {
            mx0 = fmaxf(mx0, __shfl_xor_sync(0xffffffffu, mx0, o));
            mx1 = fmaxf(mx1, __shfl_xor_sync(0xffffffffu, mx1, o));
        }
        const float sc0 = expf(mrow0 - mx0);
        const float sc1 = expf(mrow1 - mx1);
        mrow0 = mx0; mrow1 = mx1;
        lrow0 *= sc0; lrow1 *= sc1;
        #pragma unroll
        for (int f = 0; f < 8; f++) {
            O[f][0] *= sc0; O[f][1] *= sc0; O[f][2] *= sc1; O[f][3] *= sc1;
        }
        uint32_t P[8][4];
        float rs0 = 0.f, rs1 = 0.f;
        #pragma unroll
        for (int nf2 = 0; nf2 < 8; nf2++) {
            float p00 = expf(S[2 * nf2][0] - mx0),     p01 = expf(S[2 * nf2][1] - mx0);
            float p10 = expf(S[2 * nf2][2] - mx1),     p11 = expf(S[2 * nf2][3] - mx1);
            float p20 = expf(S[2 * nf2 + 1][0] - mx0), p21 = expf(S[2 * nf2 + 1][1] - mx0);
            float p30 = expf(S[2 * nf2 + 1][2] - mx1), p31 = expf(S[2 * nf2 + 1][3] - mx1);
            rs0 += p00 + p01 + p20 + p21;
            rs1 += p10 + p11 + p30 + p31;
            P[nf2][0] = packf2(p00, p01);
            P[nf2][1] = packf2(p10, p11);
            P[nf2][2] = packf2(p20, p21);
            P[nf2][3] = packf2(p30, p31);
        }
        #pragma unroll
        for (int o = 1; o < 4; o <<= 1) {
            rs0 += __shfl_xor_sync(0xffffffffu, rs0, o);
            rs1 += __shfl_xor_sync(0xffffffffu, rs1, o);
        }
        lrow0 += rs0; lrow1 += rs1;

        #pragma unroll
        for (int ks2 = 0; ks2 < 8; ks2++) {
            #pragma unroll
            for (int dn = 0; dn < 4; dn++) {
                uint32_t th[4], tl[4];
                ldsm4(th, sb + V0 + (uint32_t)((bRow + dn * 16) * VROWB + (ks2 * 16 + bKs) * 2));
                ldsm4(tl, sb + V0 + VPLB + (uint32_t)((bRow + dn * 16) * VROWB + (ks2 * 16 + bKs) * 2));
                uint32_t bh0[2] = {th[0], th[1]}, bh1[2] = {th[2], th[3]};
                uint32_t bl0[2] = {tl[0], tl[1]}, bl1[2] = {tl[2], tl[3]};
                mma16816(O[2 * dn],     P[ks2], bh0);
                mma16816(O[2 * dn + 1], P[ks2], bh1);
                mma16816(O[2 * dn],     P[ks2], bl0);
                mma16816(O[2 * dn + 1], P[ks2], bl1);
            }
        }
        __syncthreads();
    }

    const float li0 = 1.f / lrow0, li1 = 1.f / lrow1;
    const int row0 = m0 + wid * 16 + (lane >> 2);
    __nv_bfloat16* ob = o2 + (size_t)b * ND;
    #pragma unroll
    for (int f = 0; f < 8; f++) {
        int d = hc * DH + f * 8 + q2c;
        float v00 = O[f][0] * li0, v01 = O[f][1] * li0;
        float v10 = O[f][2] * li1, v11 = O[f][3] * li1;
        __nv_bfloat16 h00, l00, h01, l01, h10, l10, h11, l11;
        split1(v00, h00, l00); split1(v01, h01, l01);
        split1(v10, h10, l10); split1(v11, h11, l11);
        size_t o0 = (size_t)row0 * Dd + d;
        size_t o1 = (size_t)(row0 + 8) * Dd + d;
        *reinterpret_cast<uint32_t*>(ob + o0) = pack2(h00, h01);
        *reinterpret_cast<uint32_t*>(ob + o1) = pack2(h10, h11);
        *reinterpret_cast<uint32_t*>(ob + plane + o0) = pack2(l00, l01);
        *reinterpret_cast<uint32_t*>(ob + plane + o1) = pack2(l10, l11);
    }
}

// ---------------- auxiliary kernels ----------------
__global__ void k_posquery1(const float* __restrict__ x, const int* __restrict__ mask,
                            float* __restrict__ part, float* __restrict__ cntp)
{
    int seg = blockIdx.x, b = blockIdx.y, d = threadIdx.x;
    int n0 = seg * 64;
    float s = 0.f, cnt = 0.f;
    for (int n = n0; n < n0 + 64; n++) {
        if (mask[b * Nn + n] == 1) { s += x[((size_t)b * Nn + n) * Dd + d]; cnt += 1.f; }
    }
    part[((size_t)b * 16 + seg) * Dd + d] = s;
    if (d == 0) cntp[b * 16 + seg] = cnt;
}
__global__ void k_posquery2(const float* __restrict__ part, const float* __restrict__ cntp,
                            float* __restrict__ pq)
{
    int b = blockIdx.x, d = threadIdx.x;
    float s = 0.f, cnt = 0.f;
    #pragma unroll
    for (int seg = 0; seg < 16; seg++) {
        s += part[((size_t)b * 16 + seg) * Dd + d];
        cnt += cntp[b * 16 + seg];
    }
    pq[b * Dd + d] = s / fmaxf(cnt, 1.f);
}

__global__ void k_mv1(const float* __restrict__ Wq, const float* __restrict__ pq,
                      float* __restrict__ qs)
{
    __shared__ float spq[Dd];
    __shared__ float red[8][32];
    int b = blockIdx.y, t0 = blockIdx.x * 32;
    int tid = threadIdx.x;
    spq[tid] = pq[b * Dd + tid];
    __syncthreads();
    int tseg = tid >> 5, tl = tid & 31;
    float s = 0.f;
    #pragma unroll
    for (int i = 0; i < 32; i++)
        s += spq[tseg * 32 + i] * Wq[(tseg * 32 + i) * Dd + t0 + tl];
    red[tseg][tl] = s;
    __syncthreads();
    if (tseg == 0) {
        float a = 0.f;
        #pragma unroll
        for (int k = 0; k < 8; k++) a += red[k][tl];
        qs[b * Dd + t0 + tl] = a;
    }
}
__global__ void k_mv2(const float* __restrict__ Wx, const float* __restrict__ qs,
                      float* __restrict__ w)
{
    int b = blockIdx.y;
    int wid = threadIdx.x >> 5, lane = threadIdx.x & 31;
    int t = blockIdx.x * 8 + wid;
    float s = 0.f;
    #pragma unroll
    for (int k = 0; k < 8; k++)
        s += Wx[(size_t)t * Dd + lane + 32 * k] * qs[b * Dd + lane + 32 * k];
    #pragma unroll
    for (int o = 16; o; o >>= 1) s += __shfl_xor_sync(0xffffffffu, s, o);
    if (lane == 0) w[b * Dd + t] = s;
}

__global__ void k_possim(const float* __restrict__ x, const float* __restrict__ w,
                         float* __restrict__ possim_out, float* __restrict__ sel)
{
    int row = blockIdx.x * 8 + (threadIdx.x >> 5);
    int lane = threadIdx.x & 31;
    int b = row / Nn;
    const float4* xr = reinterpret_cast<const float4*>(x + (size_t)row * Dd);
    const float4* wr = reinterpret_cast<const float4*>(w + b * Dd);
    float s = 0.f;
    #pragma unroll
    for (int e = 0; e < 2; e++) {
        float4 xv = xr[lane + e * 32];
        float4 wv = wr[lane + e * 32];
        s += xv.x * wv.x + xv.y * wv.y + xv.z * wv.z + xv.w * wv.w;
    }
    #pragma unroll
    for (int o = 16; o; o >>= 1) s += __shfl_xor_sync(0xffffffffu, s, o);
    if (lane == 0) {
        float p = 1.f / (1.f + expf(-s * 0.0625f));
        possim_out[row] = p;
        sel[row] = (p > 0.97f) ? 1.f : 0.f;
    }
}

__global__ void k_dot2p(const __nv_bfloat16* __restrict__ rows, long plane,
                        const float* __restrict__ a1, const float* __restrict__ a2,
                        float* __restrict__ s1, float* __restrict__ s2, int nheads)
{
    int row = blockIdx.x * 8 + (threadIdx.x >> 5);
    int lane = threadIdx.x & 31;
    int head = (row / Nn) % nheads;
    const __nv_bfloat16* rp = rows + (size_t)row * Dd;
    const float* a1p = a1 + head * Dd;
    const float* a2p = a2 + head * Dd;
    float u = 0.f, v = 0.f;
    for (int e = lane; e < Dd; e += 32) {
        float rv = __bfloat162float(rp[e]) + __bfloat162float(rp[plane + e]);
        u += rv * a1p[e];
        v += rv * a2p[e];
    }
    #pragma unroll
    for (int o = 16; o; o >>= 1) {
        u += __shfl_xor_sync(0xffffffffu, u, o);
        v += __shfl_xor_sync(0xffffffffu, v, o);
    }
    if (lane == 0) { s1[row] = u; s2[row] = v; }
}

__global__ void k_softmax_gat(const float* __restrict__ s1, const float* __restrict__ s2,
                              const uint8_t* __restrict__ connect, __nv_bfloat16* __restrict__ attn,
                              int nheads)
{
    __shared__ float s2row[Nn];
    __shared__ float r8[8];
    int z = blockIdx.y;
    int b = z / nheads;
    int t = threadIdx.x;
    int wid = t >> 5, lane = t & 31;
    #pragma unroll
    for (int k = 0; k < 4; k++) s2row[t + k * 256] = s2[(size_t)z * Nn + t + k * 256];
    __syncthreads();
    #pragma unroll
    for (int r = 0; r < 4; r++) {
        int i = blockIdx.x * 4 + r;
        const uint8_t* con = connect + (size_t)b * NNt + (size_t)i * Nn;
        float s1v = s1[(size_t)z * Nn + i];
        float v[4];
        float mx = -INFINITY;
        #pragma unroll
        for (int k = 0; k < 4; k++) {
            int j = t + k * 256;
            float e = s1v + s2row[j];
            e = (e >= 0.f) ? e : 0.2f * e;
            v[k] = con[j] ? e : -9.0e15f;
            mx = fmaxf(mx, v[k]);
        }
        mx = bred<true>(mx, r8, wid, lane);
        float sum = 0.f;
        #pragma unroll
        for (int k = 0; k < 4; k++) { v[k] = expf(v[k] - mx); sum += v[k]; }
        sum = bred<false>(sum, r8, wid, lane);
        float inv = 1.f / sum;
        __nv_bfloat16* out = attn + (size_t)z * NNt + (size_t)i * Nn;
        #pragma unroll
        for (int k = 0; k < 4; k++) out[t + k * 256] = __float2bfloat16(v[k] * inv);
        __syncthreads();
    }
}

__global__ void k_ln(const float* __restrict__ in, const float* __restrict__ g,
                     const float* __restrict__ bb, __nv_bfloat16* __restrict__ out, long oplane)
{
    int row = blockIdx.x * 8 + (threadIdx.x >> 5);
    int lane = threadIdx.x & 31;
    size_t base = (size_t)row * Dd;
    float vbuf[8];
    float s = 0.f, sq = 0.f;
    #pragma unroll
    for (int k = 0; k < 8; k++) {
        float x = in[base + lane + k * 32];
        vbuf[k] = x; s += x; sq += x * x;
    }
    #pragma unroll
    for (int o = 16; o; o >>= 1) {
        s += __shfl_xor_sync(0xffffffffu, s, o);
        sq += __shfl_xor_sync(0xffffffffu, sq, o);
    }
    float mean = s * (1.f / Dd);
    float var = sq * (1.f / Dd) - mean * mean;
    float rstd = rsqrtf(var + 1e-5f);
    #pragma unroll
    for (int k = 0; k < 8; k++) {
        int d = lane + k * 32;
        float y = (vbuf[k] - mean) * rstd * g[d] + bb[d];
        __nv_bfloat16 h, l; split1(y, h, l);
        out[base + d] = h; out[oplane + base + d] = l;
    }
}

__global__ void k_qfull_ln(const __nv_bfloat16* __restrict__ gout, long gplane,
                           const float* __restrict__ pe,
                           const float* __restrict__ sel, const float* __restrict__ g,
                           const float* __restrict__ bb, __nv_bfloat16* __restrict__ out, long oplane)
{
    int row = blockIdx.x * 8 + (threadIdx.x >> 5);
    int lane = threadIdx.x & 31;
    int n = row % Nn;
    size_t base = (size_t)row * Dd;
    float selv = sel[row];
    float vbuf[8];
    float s = 0.f, sq = 0.f;
    #pragma unroll
    for (int k = 0; k < 8; k++) {
        int d = lane + k * 32;
        float gv = __bfloat162float(gout[base + d]) + __bfloat162float(gout[gplane + base + d]);
        float x = (selv > 0.5f) ? (gv + pe[(size_t)n * Dd + d]) : 0.f;
        vbuf[k] = x; s += x; sq += x * x;
    }
    #pragma unroll
    for (int o = 16; o; o >>= 1) {
        s += __shfl_xor_sync(0xffffffffu, s, o);
        sq += __shfl_xor_sync(0xffffffffu, sq, o);
    }
    float mean = s * (1.f / Dd);
    float var = sq * (1.f / Dd) - mean * mean;
    float rstd = rsqrtf(var + 1e-5f);
    #pragma unroll
    for (int k = 0; k < 8; k++) {
        int d = lane + k * 32;
        float y = (vbuf[k] - mean) * rstd * g[d] + bb[d];
        __nv_bfloat16 h, l; split1(y, h, l);
        out[base + d] = h; out[oplane + base + d] = l;
    }
}

// ---------------- launch ----------------
#define GETSYM(p, T, s) do { void* _t; cudaGetSymbolAddress(&_t, s); p = (T*)_t; } while (0)
#define SMEMSZ(BM, BN, NA, ST) (((ST) * (NA) * (BM) + (ST) * 2 * (BN)) * ROWB)

extern "C" void kernel_launch(void* const* d_in, const int* in_sizes, int n_in,
                              void* d_out, int out_size)
{
    const float* x      = (const float*)d_in[0];
    const int*   mask   = (const int*)  d_in[1];
    const float* pe     = (const float*)d_in[2];
    const float* simWx  = (const float*)d_in[3];
    const float* simWq  = (const float*)d_in[4];
    const float* adjW   = (const float*)d_in[5];
    const float* gatW   = (const float*)d_in[6];
    const float* gatA1  = (const float*)d_in[7];
    const float* gatA2  = (const float*)d_in[8];
    const float* gatWo  = (const float*)d_in[9];
    const float* gatAo1 = (const float*)d_in[10];
    const float* gatAo2 = (const float*)d_in[11];
    const float* ln3g   = (const float*)d_in[12];
    const float* ln3b   = (const float*)d_in[13];
    const float* ln4g   = (const float*)d_in[14];
    const float* ln4b   = (const float*)d_in[15];
    const float* caWq   = (const float*)d_in[16];
    const float* caWk   = (const float*)d_in[17];
    const float* caWv   = (const float*)d_in[18];
    const float* caWp   = (const float*)d_in[19];
    const float* gamma  = (const float*)d_in[20];
    (void)in_sizes; (void)n_in; (void)out_size;

    float* out = (float*)d_out;
    float* possim_out = out + (size_t)Bz * Nn * Dd;

    float *posq, *pqpart, *pqcnt, *qsv, *w, *sel, *s1, *s2, *so1, *so2;
    uint8_t* connect;
    __nv_bfloat16 *attn_bf, *attno_bf;
    __nv_bfloat16 *x2, *fa2, *Wh2, *WhT2, *cat2, *Who2, *WhoT2, *gout2, *qx2, *kv2;
    __nv_bfloat16 *q2, *k2, *vT2, *o2;
    __nv_bfloat16 *adjWT2, *gatWT2, *WoT2, *caWqT2, *caWkT2, *caWvT2, *caWpT2;
    GETSYM(posq, float, g_posq);   GETSYM(pqpart, float, g_pqpart); GETSYM(pqcnt, float, g_pqcnt);
    GETSYM(qsv, float, g_qs);      GETSYM(w, float, g_w);       GETSYM(sel, float, g_sel);
    GETSYM(connect, uint8_t, g_connect);
    GETSYM(s1, float, g_s1);       GETSYM(s2, float, g_s2);
    GETSYM(so1, float, g_so1);     GETSYM(so2, float, g_so2);
    GETSYM(attn_bf, __nv_bfloat16, g_attn_bf);
    GETSYM(attno_bf, __nv_bfloat16, g_attno_bf);
    GETSYM(x2, __nv_bfloat16, g_x2);     GETSYM(fa2, __nv_bfloat16, g_fa2);
    GETSYM(Wh2, __nv_bfloat16, g_Wh2);   GETSYM(WhT2, __nv_bfloat16, g_WhT2);
    GETSYM(cat2, __nv_bfloat16, g_cat2);
    GETSYM(Who2, __nv_bfloat16, g_Who2); GETSYM(WhoT2, __nv_bfloat16, g_WhoT2);
    GETSYM(gout2, __nv_bfloat16, g_gout2);
    GETSYM(qx2, __nv_bfloat16, g_qx2);   GETSYM(kv2, __nv_bfloat16, g_kv2);
    GETSYM(q2, __nv_bfloat16, g_q2);     GETSYM(k2, __nv_bfloat16, g_k2);
    GETSYM(vT2, __nv_bfloat16, g_vT2);   GETSYM(o2, __nv_bfloat16, g_o2);
    GETSYM(adjWT2, __nv_bfloat16, g_adjWT2); GETSYM(gatWT2, __nv_bfloat16, g_gatWT2);
    GETSYM(WoT2, __nv_bfloat16, g_WoT2);
    GETSYM(caWqT2, __nv_bfloat16, g_caWqT2); GETSYM(caWkT2, __nv_bfloat16, g_caWkT2);
    GETSYM(caWvT2, __nv_bfloat16, g_caWvT2); GETSYM(caWpT2, __nv_bfloat16, g_caWpT2);

    const long PL_BND  = (long)Bz * ND;
    const long PL_BHND = (long)Bz * Hh * ND;
    const long PL_CAT  = (long)Bz * Nn * HD;
    const long PL_DD   = (long)Dd * Dd;
    const long PL_GATW = (long)Hh * Dd * Dd;
    const long PL_WO   = (long)HD * Dd;

    const int SM_22_2 = SMEMSZ(128, 128, 2, 2);   // 80 KB
    const int SM_22_3 = SMEMSZ(128, 128, 2, 3);   // 120 KB
    const int SM_12_2 = SMEMSZ(128, 128, 1, 2);   // 60 KB
    const int SM_12_3 = SMEMSZ(128, 128, 1, 3);   // 90 KB
    cudaFuncSetAttribute(mma_gemm<128,128,2,4,EPI_NONE,   2,OUT_PLANES, false,3>, cudaFuncAttributeMaxDynamicSharedMemorySize, SM_22_3);
    cudaFuncSetAttribute(mma_gemm<128,128,2,4,EPI_NONE,   2,OUT_PLANES, true ,2>, cudaFuncAttributeMaxDynamicSharedMemorySize, SM_22_2);
    cudaFuncSetAttribute(mma_gemm<128,128,2,4,EPI_NONE,   2,OUT_PLANES, true ,3>, cudaFuncAttributeMaxDynamicSharedMemorySize, SM_22_3);
    cudaFuncSetAttribute(mma_gemm<128,128,2,4,EPI_CONNECT,2,OUT_CONNECT,false,2>, cudaFuncAttributeMaxDynamicSharedMemorySize, SM_22_2);
    cudaFuncSetAttribute(mma_gemm<128,128,2,4,EPI_NONE,   2,OUT_NONE,   true ,3>, cudaFuncAttributeMaxDynamicSharedMemorySize, SM_22_3);
    cudaFuncSetAttribute(mma_gemm<128,128,2,4,EPI_RESID,  2,OUT_F32,    false,3>, cudaFuncAttributeMaxDynamicSharedMemorySize, SM_22_3);
    cudaFuncSetAttribute(mma_gemm<128,128,2,4,EPI_ELU,    1,OUT_PLANES, false,2>, cudaFuncAttributeMaxDynamicSharedMemorySize, SM_12_2);
    cudaFuncSetAttribute(mma_gemm<128,128,2,4,EPI_ELU,    1,OUT_PLANES, false,3>, cudaFuncAttributeMaxDynamicSharedMemorySize, SM_12_3);
    cudaFuncSetAttribute(k_flash_ca, cudaFuncAttributeMaxDynamicSharedMemorySize, FCA_SMEM);

    const long zero = 0;
    cudaStream_t s0 = 0;
    cudaStream_t sA = hx.s1;
    cudaStream_t sB = hx.s2;

    // fork
    cudaEventRecord(hx.e0, s0);
    cudaStreamWaitEvent(sA, hx.e0, 0);
    cudaStreamWaitEvent(sB, hx.e0, 0);

    // stream B: weight transposes -> LN3 -> q projection
    k_transpose_all<<<1344, dim3(32, 8), 0, sB>>>(adjW, adjWT2, caWq, caWqT2, caWk, caWkT2,
                                                  caWv, caWvT2, caWp, caWpT2, gatW, gatWT2, gatWo, WoT2);
    cudaEventRecord(hx.eT, sB);
    k_ln<<<Bz * Nn / 8, 256, 0, sB>>>(x, ln3g, ln3b, qx2, PL_BND);

    // stream 0: split x
    k_split<<<Bz * ND / 1024, 256, 0, s0>>>(x, x2, PL_BND);
    cudaEventRecord(hx.eX, s0);

    // stream B: q = qx @ caWq   (grid 128 -> 3-stage)
    mma_gemm<128,128,2,4,EPI_NONE,2,OUT_PLANES,false,3><<<dim3(2, 64, 1), 256, SM_22_3, sB>>>(
        qx2, PL_BND, caWqT2, PL_DD, q2, PL_BND,
        Dd, Dd, Dd, Dd, 1, zero, zero, zero, zero, zero, zero,
        nullptr, zero, nullptr, nullptr, zero, zero, zero, 0);
    cudaEventRecord(hx.eQ, sB);

    // stream A: selection path, then fa -> connect
    k_posquery1<<<dim3(16, Bz), 256, 0, sA>>>(x, mask, pqpart, pqcnt);
    k_posquery2<<<Bz, 256, 0, sA>>>(pqpart, pqcnt, posq);
    k_mv1<<<dim3(8, Bz), 256, 0, sA>>>(simWq, posq, qsv);
    k_mv2<<<dim3(32, Bz), 256, 0, sA>>>(simWx, qsv, w);
    k_possim<<<Bz * Nn / 8, 256, 0, sA>>>(x, w, possim_out, sel);
    cudaStreamWaitEvent(sA, hx.eX, 0);
    cudaStreamWaitEvent(sA, hx.eT, 0);
    mma_gemm<128,128,2,4,EPI_NONE,2,OUT_PLANES,false,3><<<dim3(2, 64, 1), 256, SM_22_3, sA>>>(
        x2, PL_BND, adjWT2, PL_DD, fa2, PL_BND,
        Dd, Dd, Dd, Dd, 1, zero, zero, zero, zero, zero, zero,
        nullptr, zero, nullptr, nullptr, zero, zero, zero, 0);
    mma_gemm<128,128,2,4,EPI_CONNECT,2,OUT_CONNECT,false,2><<<dim3(8, 8, Bz), 256, SM_22_2, sA>>>(
        fa2, PL_BND, fa2, PL_BND, connect, zero,
        Dd, Dd, Dd, Nn, 1, (long)ND, zero, (long)ND, zero, (long)NNt, zero,
        sel, (long)Nn, nullptr, nullptr, zero, zero, zero, 0);
    cudaEventRecord(hx.eConn, sA);

    // stream 0: main chain
    cudaStreamWaitEvent(s0, hx.eT, 0);

    mma_gemm<128,128,2,4,EPI_NONE,2,OUT_PLANES,true,2><<<dim3(2, 8, Bz * Hh), 256, SM_22_2, s0>>>(
        x2, PL_BND, gatWT2, PL_GATW, Wh2, PL_BHND,
        Dd, Dd, Dd, Dd, Hh, (long)ND, zero, zero, (long)Dd * Dd,
        (long)Hh * ND, (long)ND,
        nullptr, zero, nullptr, WhT2, PL_BHND, (long)Hh * ND, (long)ND, Nn);

    k_dot2p<<<Bz * Hh * Nn / 8, 256, 0, s0>>>(Wh2, PL_BHND, gatA1, gatA2, s1, s2, Hh);

    cudaStreamWaitEvent(s0, hx.eConn, 0);
    k_softmax_gat<<<dim3(Nn / 4, Bz * Hh), 256, 0, s0>>>(s1, s2, connect, attn_bf, Hh);

    mma_gemm<128,128,2,4,EPI_ELU,1,OUT_PLANES,false,2><<<dim3(2, 8, Bz * Hh), 256, SM_12_2, s0>>>(
        attn_bf, zero, WhT2, PL_BHND, cat2, PL_CAT,
        Nn, Nn, Nn, HD, Hh, (long)Hh * NNt, (long)NNt, (long)Hh * ND, (long)ND,
        (long)Nn * HD, (long)Dd,
        nullptr, zero, nullptr, nullptr, zero, zero, zero, 0);

    // Who: grid 128, K=2048 -> 3-stage
    mma_gemm<128,128,2,4,EPI_NONE,2,OUT_PLANES,true,3><<<dim3(2, 8, Bz), 256, SM_22_3, s0>>>(
        cat2, PL_CAT, WoT2, PL_WO, Who2, PL_BND,
        HD, HD, HD, Dd, 1, (long)Nn * HD, zero, zero, zero, (long)ND, zero,
        nullptr, zero, nullptr, WhoT2, PL_BND, (long)ND, zero, Nn);

    k_dot2p<<<Bz * Nn / 8, 256, 0, s0>>>(Who2, PL_BND, gatAo1, gatAo2, so1, so2, 1);
    k_softmax_gat<<<dim3(Nn / 4, Bz), 256, 0, s0>>>(so1, so2, connect, attno_bf, 1);

    // gout: grid 128, K=1024 -> 3-stage
    mma_gemm<128,128,2,4,EPI_ELU,1,OUT_PLANES,false,3><<<dim3(2, 8, Bz), 256, SM_12_3, s0>>>(
        attno_bf, zero, WhoT2, PL_BND, gout2, PL_BND,
        Nn, Nn, Nn, Dd, 1, (long)NNt, zero, (long)ND, zero, (long)ND, zero,
        nullptr, zero, nullptr, nullptr, zero, zero, zero, 0);

    k_qfull_ln<<<Bz * Nn / 8, 256, 0, s0>>>(gout2, PL_BND, pe, sel, ln4g, ln4b, kv2, PL_BND);
    cudaEventRecord(hx.eKV, s0);

    // stream B: k projection (parallel with vT on s0)
    cudaStreamWaitEvent(sB, hx.eKV, 0);
    mma_gemm<128,128,2,4,EPI_NONE,2,OUT_PLANES,false,3><<<dim3(2, 64, 1), 256, SM_22_3, sB>>>(
        kv2, PL_BND, caWkT2, PL_DD, k2, PL_BND,
        Dd, Dd, Dd, Dd, 1, zero, zero, zero, zero, zero, zero,
        nullptr, zero, nullptr, nullptr, zero, zero, zero, 0);
    cudaEventRecord(hx.eK, sB);

    // stream 0: v projection (transposed planes only)
    mma_gemm<128,128,2,4,EPI_NONE,2,OUT_NONE,true,3><<<dim3(2, 8, Bz), 256, SM_22_3, s0>>>(
        kv2, PL_BND, caWvT2, PL_DD, nullptr, zero,
        Dd, Dd, Dd, Dd, 1, (long)ND, zero, zero, zero, (long)ND, zero,
        nullptr, zero, nullptr, vT2, PL_BND, (long)ND, zero, Nn);

    // fused flash CA
    cudaStreamWaitEvent(s0, hx.eQ, 0);
    cudaStreamWaitEvent(s0, hx.eK, 0);
    k_flash_ca<<<dim3(Nn / 128, Bz * HC), 256, FCA_SMEM, s0>>>(
        q2, k2, vT2, sel, o2, PL_BND);

    // out = x + gamma * (o @ caWp)
    mma_gemm<128,128,2,4,EPI_RESID,2,OUT_F32,false,3><<<dim3(2, 64, 1), 256, SM_22_3, s0>>>(
        o2, PL_BND, caWpT2, PL_DD, out, zero,
        Dd, Dd, Dd, Dd, 1, zero, zero, zero, zero, zero, zero,
        x, zero, gamma, nullptr, zero, zero, zero, 0);
}